// round 9
// baseline (speedup 1.0000x reference)
#include <cuda_runtime.h>
#include <cuda_fp16.h>
#include <math.h>
#include <stdint.h>

// ---------------------------------------------------------------------------
// TargetAwareContextAttention — fused pair kernel, barrier-free k-loops:
// B fragments register-loaded from L2-resident weights; K/V tiles in smem.
// B=2, Nt=128, Nc=512, D=256, DPHI=16, HID=128, H=8, dk=32; NP=131072 pairs.
// ---------------------------------------------------------------------------

#define D_    256
#define DPHI_ 16
#define HID_  128
#define B_    2
#define NT_   128
#define NC_   512
#define NTT_  (B_*NT_)    // 256
#define NCC_  (B_*NC_)    // 1024
#define NP_   (NTT_*NC_)  // 131072

// ------------------------------- scratch -----------------------------------
__device__ __half s_Hh[(size_t)NP_*256]; // [hk(128)|hv(128)]
__device__ __half s_Kg[(size_t)NP_*256];
__device__ __half s_Vg[(size_t)NP_*256];
__device__ __half s_BGh [256*512];      // gate B rows: [gw3 | G1|G2]
__device__ __half s_kp2h[256*128];
__device__ __half s_vp2h[256*128];
__device__ float s_Tt [NTT_*1024];      // [kt|vt|Q|At] per target row
__device__ float s_Cc [NCC_*768];       // [kc|vc|Ac] per ctx row
__device__ float s_At [NTT_*256];       // ctx (attention output)
__device__ float s_Wt [1024*256];       // [kt_w; vt_w; Wq_w; Wat]
__device__ float s_bt [1024];
__device__ float s_Wc [768*256];        // [kc_w; vc_w; Wac]
__device__ float s_WB [768*512];        // weight-prep B
__device__ float s_cb [256];
__device__ float s_kpb[256];
__device__ float s_vpb[256];

// --------------------------- helpers ----------------------------------------
__device__ __forceinline__ void mma16(float* c, const uint32_t* a, const uint32_t* b) {
    asm volatile(
        "mma.sync.aligned.m16n8k16.row.col.f32.f16.f16.f32 "
        "{%0,%1,%2,%3}, {%4,%5,%6,%7}, {%8,%9}, {%0,%1,%2,%3};"
        : "+f"(c[0]), "+f"(c[1]), "+f"(c[2]), "+f"(c[3])
        : "r"(a[0]), "r"(a[1]), "r"(a[2]), "r"(a[3]), "r"(b[0]), "r"(b[1]));
}
__device__ __forceinline__ uint32_t habsdiff2(uint32_t a, uint32_t b) {
    __half2 ha = *reinterpret_cast<__half2*>(&a);
    __half2 hb = *reinterpret_cast<__half2*>(&b);
    __half2 r = __habs2(__hsub2(ha, hb));
    return *reinterpret_cast<uint32_t*>(&r);
}

// ---------------------- fused pair kernel -----------------------------------
#define TP 132                                  // tile pitch (u32), 256-half rows
#define FUSED_SMEM (3*128*TP*4)                 // 202752 B

struct FusedP {
    const __half *Hh, *kp2h, *vp2h, *BGh;
    __half *Kg, *Vg;
    const float *Tt, *Cc, *kpb, *vpb, *cb;
};

struct BFrag { uint32_t v[2][8][2]; };          // [kf][nf][b0/b1]

__global__ void __launch_bounds__(256) fused_pair(FusedP p) {
    extern __shared__ __align__(16) uint32_t sm[];
    uint32_t* Ht = sm;
    uint32_t* Kt = sm + 128*TP;
    uint32_t* Vt = sm + 2*128*TP;

    const int tid   = threadIdx.x;
    const int lane  = tid & 31;
    const int wid   = tid >> 5;
    const int warpM = wid & 3;
    const int warpN = wid >> 2;
    const int g     = lane >> 2;
    const int t4    = lane & 3;
    const int mBase = blockIdx.x * 128;

    // load H tile (128 rows x 256 halves)
    for (int i = tid; i < 128*32; i += 256) {
        const int row = i >> 5, c4 = i & 31;
        *(uint4*)(Ht + row*TP + c4*4) =
            *(const uint4*)(p.Hh + (size_t)(mBase + row)*256 + c4*8);
    }
    __syncthreads();

    float acc[2][8][4];

    auto zeroAcc = [&]() {
#pragma unroll
        for (int mf = 0; mf < 2; mf++)
#pragma unroll
            for (int nf = 0; nf < 8; nf++)
#pragma unroll
                for (int q = 0; q < 4; q++) acc[mf][nf][q] = 0.f;
    };
    // B fragments straight from global (L1/L2-resident weights)
    auto loadBF = [&](BFrag& f, const __half* Bp, int ldb, int nB, int kc) {
#pragma unroll
        for (int kf = 0; kf < 2; kf++)
#pragma unroll
            for (int nf = 0; nf < 8; nf++) {
                const __half* bp = Bp + (size_t)(nB + warpN*64 + nf*8 + g)*ldb
                                 + kc + (kf*8 + t4)*2;
                f.v[kf][nf][0] = __ldg((const uint32_t*)bp);
                f.v[kf][nf][1] = __ldg((const uint32_t*)(bp + 8));
            }
    };
    // one 32-half k-chunk; amode 0 -> A from Ht at u32 col aU; 1 -> |Kt-Vt|
    auto computeF = [&](const BFrag& f, int amode, int aU) {
#pragma unroll
        for (int kf = 0; kf < 2; kf++) {
            const int kb = kf*8 + t4;
            uint32_t af[2][4];
#pragma unroll
            for (int mf = 0; mf < 2; mf++) {
                const int ro = (warpM*32 + mf*16 + g)*TP + aU + kb;
                if (amode == 0) {
                    af[mf][0] = Ht[ro];          af[mf][1] = Ht[ro + 8*TP];
                    af[mf][2] = Ht[ro + 4];      af[mf][3] = Ht[ro + 8*TP + 4];
                } else {
                    af[mf][0] = habsdiff2(Kt[ro],          Vt[ro]);
                    af[mf][1] = habsdiff2(Kt[ro + 8*TP],   Vt[ro + 8*TP]);
                    af[mf][2] = habsdiff2(Kt[ro + 4],      Vt[ro + 4]);
                    af[mf][3] = habsdiff2(Kt[ro + 8*TP+4], Vt[ro + 8*TP+4]);
                }
            }
#pragma unroll
            for (int mf = 0; mf < 2; mf++)
#pragma unroll
                for (int nf = 0; nf < 8; nf++)
                    mma16(acc[mf][nf], af[mf], f.v[kf][nf]);
        }
    };

    BFrag fr[2];

    // ---- K and V phases: outputs to smem tiles (no barriers in loop) ----
    for (int sel = 0; sel < 2; sel++) {
        const __half* Bp = sel ? p.vp2h : p.kp2h;
        const int   aBase = sel ? 64 : 0;
        uint32_t*   Ot    = sel ? Vt : Kt;
        const float* bias = sel ? p.vpb : p.kpb;
        const int   poff  = sel ? 256 : 0;
        for (int nh = 0; nh < 2; nh++) {
            const int nB = nh * 128;
            zeroAcc();
            loadBF(fr[0], Bp, HID_, nB, 0);
#pragma unroll
            for (int c = 0; c < 4; c++) {
                if (c < 3) loadBF(fr[(c+1)&1], Bp, HID_, nB, (c+1)*32);
                computeF(fr[c&1], 0, aBase + c*16);
            }
#pragma unroll
            for (int mf = 0; mf < 2; mf++)
#pragma unroll
            for (int hf = 0; hf < 2; hf++) {
                const int row  = warpM*32 + mf*16 + g + hf*8;
                const int grow = mBase + row;
                const int tg = grow >> 9;
                const int cx = ((grow >> 16) << 9) + (grow & 511);
                const float* r1 = p.Tt + (size_t)tg*1024 + poff;
                const float* r2 = p.Cc + (size_t)cx*768  + poff;
#pragma unroll
                for (int nf = 0; nf < 8; nf++) {
                    const int col = nB + warpN*64 + nf*8 + t4*2;
                    float2 a = __ldg((const float2*)(r1 + col));
                    float2 b = __ldg((const float2*)(r2 + col));
                    float2 v = __ldg((const float2*)(bias + col));
                    __half2 h = __floats2half2_rn(
                        acc[mf][nf][hf*2+0] + a.x + b.x + v.x,
                        acc[mf][nf][hf*2+1] + a.y + b.y + v.y);
                    Ot[row*TP + (col >> 1)] = *reinterpret_cast<uint32_t*>(&h);
                }
            }
        }
    }

    __syncthreads();   // K/V tiles visible cross-warp for gate A operand

    // ---- gate phase: K=512 (|K-V| then H) -> Kg/Vg in HBM ----
    for (int nh = 0; nh < 2; nh++) {
        const int nB = nh * 128;
        zeroAcc();
        loadBF(fr[0], p.BGh, 512, nB, 0);
#pragma unroll
        for (int c = 0; c < 16; c++) {
            if (c < 15) loadBF(fr[(c+1)&1], p.BGh, 512, nB, (c+1)*32);
            if (c < 8) computeF(fr[c&1], 1, c*16);
            else       computeF(fr[c&1], 0, (c-8)*16);
        }
#pragma unroll
        for (int mf = 0; mf < 2; mf++)
#pragma unroll
        for (int hf = 0; hf < 2; hf++) {
            const int row  = warpM*32 + mf*16 + g + hf*8;
            const int grow = mBase + row;
            const size_t ro = (size_t)grow * 256;
            const int tg = grow >> 9;
            const int cx = ((grow >> 16) << 9) + (grow & 511);
            const float* r1 = p.Tt + (size_t)tg*1024 + 768;
            const float* r2 = p.Cc + (size_t)cx*768  + 512;
#pragma unroll
            for (int nf = 0; nf < 8; nf++) {
                const int col = nB + warpN*64 + nf*8 + t4*2;
                float2 at = __ldg((const float2*)(r1 + col));
                float2 ac = __ldg((const float2*)(r2 + col));
                float2 cb = __ldg((const float2*)(p.cb + col));
                uint32_t ku = Kt[row*TP + (col >> 1)];
                uint32_t vu = Vt[row*TP + (col >> 1)];
                float2 kk = __half22float2(*reinterpret_cast<__half2*>(&ku));
                float2 vv = __half22float2(*reinterpret_cast<__half2*>(&vu));
                float g0 = 1.f / (1.f + __expf(-(acc[mf][nf][hf*2+0] + at.x + ac.x + cb.x)));
                float g1 = 1.f / (1.f + __expf(-(acc[mf][nf][hf*2+1] + at.y + ac.y + cb.y)));
                *(__half2*)(p.Kg + ro + col) = __floats2half2_rn(kk.x*g0, kk.y*g1);
                *(__half2*)(p.Vg + ro + col) = __floats2half2_rn(vv.x*g0, vv.y*g1);
            }
        }
    }
}

// ------------------- fp32 FFMA2 GEMM (prologue-sized) -----------------------
__device__ __forceinline__ unsigned long long pk2(float lo, float hi) {
    unsigned long long r;
    asm("mov.b64 %0, {%1, %2};" : "=l"(r) : "f"(lo), "f"(hi));
    return r;
}
__device__ __forceinline__ void upk2(unsigned long long v, float& lo, float& hi) {
    asm("mov.b64 {%0, %1}, %2;" : "=f"(lo), "=f"(hi) : "l"(v));
}
__device__ __forceinline__ void ffma2(unsigned long long& d,
                                      unsigned long long a, unsigned long long b) {
    asm("fma.rn.f32x2 %0, %1, %2, %0;" : "+l"(d) : "l"(a), "l"(b));
}

struct GemmP {
    const float* A; int lda; int aoff;
    const float* B; int ldb; int boff;
    int K;
    float* C; int ldc; int coff;
    const float* vec;
    __half* hC; float* O2; float* O3;
};

enum { EP_NONE = 0, EP_BIAS = 1, EP_WPREP = 4 };

template<int BM, int BN, int TM, int TN, int EPI>
__global__ void __launch_bounds__(256, 1) gemm_nt(GemmP p) {
    constexpr int BK  = 16;
    constexpr int NTX = BN / TN;
    constexpr int PA  = BM / 64;
    constexpr int PB  = BN / 64;
    __shared__ __align__(16) float As[2][BK*BM];
    __shared__ __align__(16) float Bs[2][BK*BN];

    const int tid   = threadIdx.x;
    const int mBase = blockIdx.y * BM;
    const int nBase = blockIdx.x * BN;
    const int tx = tid % NTX;
    const int ty = tid / NTX;
    const int lrow = tid >> 2;
    const int lk   = (tid & 3) << 2;

    const float* Abase = p.A + (size_t)(mBase + lrow) * p.lda + p.aoff + lk;
    const float* Bbase = p.B + (size_t)(nBase + lrow) * p.ldb + p.boff + lk;

    unsigned long long acc2[TM/2][TN];
#pragma unroll
    for (int i = 0; i < TM/2; i++)
#pragma unroll
        for (int j = 0; j < TN; j++) acc2[i][j] = 0ull;

    const int nTiles = p.K / BK;
    float4 ra[PA], rb[PB];

#pragma unroll
    for (int q = 0; q < PA; q++) ra[q] = *(const float4*)(Abase + (size_t)q*64*p.lda);
#pragma unroll
    for (int q = 0; q < PB; q++) rb[q] = *(const float4*)(Bbase + (size_t)q*64*p.ldb);
#pragma unroll
    for (int q = 0; q < PA; q++) {
        int m = lrow + q*64;
        As[0][(lk+0)*BM+m]=ra[q].x; As[0][(lk+1)*BM+m]=ra[q].y;
        As[0][(lk+2)*BM+m]=ra[q].z; As[0][(lk+3)*BM+m]=ra[q].w;
    }
#pragma unroll
    for (int q = 0; q < PB; q++) {
        int n = lrow + q*64;
        Bs[0][(lk+0)*BN+n]=rb[q].x; Bs[0][(lk+1)*BN+n]=rb[q].y;
        Bs[0][(lk+2)*BN+n]=rb[q].z; Bs[0][(lk+3)*BN+n]=rb[q].w;
    }
    __syncthreads();

    for (int t = 0; t < nTiles; t++) {
        const int cur = t & 1;
        const bool more = (t + 1) < nTiles;
        if (more) {
            const int k0 = (t + 1) * BK;
#pragma unroll
            for (int q = 0; q < PA; q++) ra[q] = *(const float4*)(Abase + (size_t)q*64*p.lda + k0);
#pragma unroll
            for (int q = 0; q < PB; q++) rb[q] = *(const float4*)(Bbase + (size_t)q*64*p.ldb + k0);
        }
#pragma unroll
        for (int k = 0; k < BK; k++) {
            unsigned long long a2[TM/2], b2[TN];
#pragma unroll
            for (int i = 0; i < TM; i += 4) {
                ulonglong2 v = *(const ulonglong2*)&As[cur][k*BM + ty*TM + i];
                a2[i/2] = v.x; a2[i/2 + 1] = v.y;
            }
#pragma unroll
            for (int j = 0; j < TN; j += 4) {
                float4 v = *(const float4*)&Bs[cur][k*BN + tx*TN + j];
                b2[j+0] = pk2(v.x, v.x); b2[j+1] = pk2(v.y, v.y);
                b2[j+2] = pk2(v.z, v.z); b2[j+3] = pk2(v.w, v.w);
            }
#pragma unroll
            for (int i = 0; i < TM/2; i++)
#pragma unroll
                for (int j = 0; j < TN; j++) ffma2(acc2[i][j], a2[i], b2[j]);
        }
        if (more) {
            const int nxt = cur ^ 1;
            __syncthreads();
#pragma unroll
            for (int q = 0; q < PA; q++) {
                int m = lrow + q*64;
                As[nxt][(lk+0)*BM+m]=ra[q].x; As[nxt][(lk+1)*BM+m]=ra[q].y;
                As[nxt][(lk+2)*BM+m]=ra[q].z; As[nxt][(lk+3)*BM+m]=ra[q].w;
            }
#pragma unroll
            for (int q = 0; q < PB; q++) {
                int n = lrow + q*64;
                Bs[nxt][(lk+0)*BN+n]=rb[q].x; Bs[nxt][(lk+1)*BN+n]=rb[q].y;
                Bs[nxt][(lk+2)*BN+n]=rb[q].z; Bs[nxt][(lk+3)*BN+n]=rb[q].w;
            }
            __syncthreads();
        }
    }

    float accf[TM][TN];
#pragma unroll
    for (int i = 0; i < TM/2; i++)
#pragma unroll
        for (int j = 0; j < TN; j++) upk2(acc2[i][j], accf[2*i][j], accf[2*i+1][j]);

#pragma unroll
    for (int i = 0; i < TM; i++) {
        const int gm  = mBase + ty*TM + i;
        const int gn0 = nBase + tx*TN;
        if (EPI == EP_WPREP) {
#pragma unroll
            for (int j = 0; j < TN; j++) {
                const int d = gn0 + j;
                const float v = accf[i][j];
                if (d < 256)      p.hC[(size_t)gm*512 + 256 + d] = __float2half(v);
                else if (d < 512) p.O2[(size_t)gm*256 + (d-256)] = v;
                else              p.O3[(size_t)gm*256 + (d-512)] = v;
            }
        } else {
            float* co = p.C + (size_t)gm * p.ldc + p.coff + gn0;
#pragma unroll
            for (int j = 0; j < TN; j++) {
                float v = accf[i][j];
                if (EPI == EP_BIAS) v += p.vec[gn0 + j];
                co[j] = v;
            }
        }
    }
}

// --------------------- small helper kernels ---------------------------------
__global__ void pack_kernel(const float* kt_w, const float* vt_w,
                            const float* Wq_w, const float* Wq_b,
                            const float* kc_w, const float* vc_w,
                            const float* kp2_w, const float* vp2_w,
                            const float* g_w, const float* kp2_b,
                            const float* vp2_b) {
    int i = blockIdx.x * 256 + threadIdx.x;
    if (i < 196608) {
        s_Wt[i] = (i < 65536) ? kt_w[i]
                : (i < 131072) ? vt_w[i - 65536] : Wq_w[i - 131072];
    } else if (i < 327680) {
        int j = i - 196608;
        s_Wc[j] = (j < 65536) ? kc_w[j] : vc_w[j - 65536];
    } else if (i < 720896) {
        int j = i - 327680;
        int d = j >> 9, k = j & 511;
        float v;
        if (d < 128)       v = (k < 256) ? kp2_w[k*128 + d] : 0.f;
        else if (d < 256)  v = (k >= 256) ? vp2_w[(k-256)*128 + (d-128)] : 0.f;
        else if (d < 512)  v = (k < 256) ? kt_w[k*256 + (d-256)] : vt_w[(k-256)*256 + (d-256)];
        else               v = (k < 256) ? kc_w[k*256 + (d-512)] : vc_w[(k-256)*256 + (d-512)];
        s_WB[j] = v;
    } else if (i < 786432) {
        int j = i - 720896;
        int n = j >> 8, c = j & 255;
        s_BGh[n*512 + c] = __float2half(g_w[n*768 + 512 + c]);
    } else if (i < 819200) {
        int j = i - 786432;
        s_kp2h[j] = __float2half(kp2_w[j]);
    } else if (i < 851968) {
        int j = i - 819200;
        s_vp2h[j] = __float2half(vp2_w[j]);
    } else if (i < 852992) {
        int j = i - 851968;
        s_bt[j] = (j >= 512 && j < 768) ? Wq_b[j - 512] : 0.f;
    } else if (i < 853504) {
        int j = i - 852992;
        if (j < 256) s_kpb[j] = kp2_b[j];
        else         s_vpb[j - 256] = vp2_b[j - 256];
    }
}

__global__ void cb_kernel(const float* g_w, const float* g_b,
                          const float* kp2_b, const float* vp2_b) {
    int n = threadIdx.x;
    float s = g_b[n];
    const float* r = g_w + (size_t)n * 768;
    for (int d = 0; d < 256; d++)
        s += r[d] * kp2_b[d] + r[256 + d] * vp2_b[d];
    s_cb[n] = s;
}

__global__ void __launch_bounds__(256) hphi_kernel(
    const float* phi_t, const float* phi_c,
    const float* kp1_w, const float* kp1_b,
    const float* vp1_w, const float* vp1_b) {
    const int tg = blockIdx.x;
    const int b  = tg >> 7;
    const int tid = threadIdx.x;
    __shared__ float pt[DPHI_];
    __shared__ float pc[NC_*DPHI_];
    if (tid < DPHI_) pt[tid] = phi_t[tg*DPHI_ + tid];
    for (int i = tid; i < NC_*DPHI_; i += 256) pc[i] = phi_c[b*NC_*DPHI_ + i];
    const int h   = tid & 127;
    const int ncl = tid >> 7;
    float w1r[DPHI_], w2r[DPHI_];
#pragma unroll
    for (int j = 0; j < DPHI_; j++) {
        w1r[j] = kp1_w[h*DPHI_ + j];
        w2r[j] = vp1_w[h*DPHI_ + j];
    }
    const float b1 = kp1_b[h], b2 = vp1_b[h];
    __syncthreads();
    for (int it = 0; it < NC_/2; it++) {
        int nc = it*2 + ncl;
        float hk = b1, hv = b2;
#pragma unroll
        for (int j = 0; j < DPHI_; j++) {
            float dd = pt[j] - pc[nc*DPHI_ + j];
            hk = fmaf(w1r[j], dd, hk);
            hv = fmaf(w2r[j], dd, hv);
        }
        size_t o = ((size_t)tg*NC_ + nc) * 256 + h;
        s_Hh[o]       = __float2half(fmaxf(hk, 0.f));
        s_Hh[o + 128] = __float2half(fmaxf(hv, 0.f));
    }
}

__global__ void __launch_bounds__(128) attn_kernel(const __half* Kg, const __half* Vg,
                                                   float* ctxOut) {
    const int tg = blockIdx.x >> 3;
    const int h  = blockIdx.x & 7;
    const int t  = threadIdx.x;
    __shared__ float qv[32];
    __shared__ float sc[512];
    __shared__ float red[128];
    __shared__ float cpart[4][32];
    if (t < 32) qv[t] = s_Tt[tg*1024 + 512 + h*32 + t];
    __syncthreads();
    const float scale = 0.17677669529663687f;
    float ls[4];
    float lmax = -1e30f;
#pragma unroll
    for (int j = 0; j < 4; j++) {
        int nc = t + j*128;
        const __half* kr = Kg + ((size_t)tg*NC_ + nc)*256 + h*32;
        float s = 0.f;
#pragma unroll
        for (int d = 0; d < 32; d += 2) {
            float2 kv = __half22float2(*(const __half2*)(kr + d));
            s += qv[d]*kv.x + qv[d+1]*kv.y;
        }
        s *= scale;
        ls[j] = s;
        lmax = fmaxf(lmax, s);
    }
    red[t] = lmax; __syncthreads();
    for (int o = 64; o > 0; o >>= 1) {
        if (t < o) red[t] = fmaxf(red[t], red[t+o]);
        __syncthreads();
    }
    const float mx = red[0];
    __syncthreads();
    float lsum = 0.f;
#pragma unroll
    for (int j = 0; j < 4; j++) {
        float e = __expf(ls[j] - mx);
        sc[t + j*128] = e;
        lsum += e;
    }
    red[t] = lsum; __syncthreads();
    for (int o = 64; o > 0; o >>= 1) {
        if (t < o) red[t] += red[t+o];
        __syncthreads();
    }
    const float inv = 1.f / red[0];
    const int dk = t & 31, part = t >> 5;
    float acc = 0.f;
    const __half* vb = Vg + ((size_t)tg*NC_ + part*128)*256 + h*32 + dk;
    for (int nc = 0; nc < 128; nc++)
        acc = fmaf(sc[part*128 + nc], __half2float(vb[(size_t)nc*256]), acc);
    cpart[part][dk] = acc;
    __syncthreads();
    if (t < 32)
        ctxOut[tg*256 + h*32 + t] =
            (cpart[0][t] + cpart[1][t] + cpart[2][t] + cpart[3][t]) * inv;
}

// ------------------------------- launch -------------------------------------
static inline GemmP mk() { GemmP p; p.A=0;p.lda=0;p.aoff=0;p.B=0;p.ldb=0;
    p.boff=0;p.K=0;p.C=0;p.ldc=0;p.coff=0;p.vec=0;p.hC=0;p.O2=0;p.O3=0; return p; }

extern "C" void kernel_launch(void* const* d_in, const int* in_sizes, int n_in,
                              void* d_out, int out_size) {
    const float* R_t   = (const float*)d_in[0];
    const float* R_ctx = (const float*)d_in[1];
    const float* phi_t = (const float*)d_in[2];
    const float* phi_c = (const float*)d_in[3];
    const float* Wq_w  = (const float*)d_in[5];
    const float* Wq_b  = (const float*)d_in[6];
    const float* kc_w  = (const float*)d_in[7];
    const float* kt_w  = (const float*)d_in[8];
    const float* kp1_w = (const float*)d_in[9];
    const float* kp1_b = (const float*)d_in[10];
    const float* kp2_w = (const float*)d_in[11];
    const float* kp2_b = (const float*)d_in[12];
    const float* vc_w  = (const float*)d_in[13];
    const float* vt_w  = (const float*)d_in[14];
    const float* vp1_w = (const float*)d_in[15];
    const float* vp1_b = (const float*)d_in[16];
    const float* vp2_w = (const float*)d_in[17];
    const float* vp2_b = (const float*)d_in[18];
    const float* g_w   = (const float*)d_in[19];
    const float* g_b   = (const float*)d_in[20];
    const float* out_w = (const float*)d_in[21];
    const float* out_b = (const float*)d_in[22];
    float* outp = (float*)d_out;

    __half *pHh, *pKg, *pVg, *pBGh, *pkp2h, *pvp2h;
    float *pTt, *pCc, *pAt, *pWt, *pbt, *pWc, *pWB, *pcb, *pkpb, *pvpb;
    cudaGetSymbolAddress((void**)&pHh,  s_Hh);
    cudaGetSymbolAddress((void**)&pKg,  s_Kg);
    cudaGetSymbolAddress((void**)&pVg,  s_Vg);
    cudaGetSymbolAddress((void**)&pBGh, s_BGh);
    cudaGetSymbolAddress((void**)&pkp2h, s_kp2h);
    cudaGetSymbolAddress((void**)&pvp2h, s_vp2h);
    cudaGetSymbolAddress((void**)&pTt, s_Tt);
    cudaGetSymbolAddress((void**)&pCc, s_Cc);
    cudaGetSymbolAddress((void**)&pAt, s_At);
    cudaGetSymbolAddress((void**)&pWt, s_Wt);
    cudaGetSymbolAddress((void**)&pbt, s_bt);
    cudaGetSymbolAddress((void**)&pWc, s_Wc);
    cudaGetSymbolAddress((void**)&pWB, s_WB);
    cudaGetSymbolAddress((void**)&pcb, s_cb);
    cudaGetSymbolAddress((void**)&pkpb, s_kpb);
    cudaGetSymbolAddress((void**)&pvpb, s_vpb);

    cudaFuncSetAttribute(fused_pair,
                         cudaFuncAttributeMaxDynamicSharedMemorySize, FUSED_SMEM);

    pack_kernel<<<3335, 256>>>(kt_w, vt_w, Wq_w, Wq_b, kc_w, vc_w,
                               kp2_w, vp2_w, g_w, kp2_b, vp2_b);
    cb_kernel<<<1, 256>>>(g_w, g_b, kp2_b, vp2_b);
    hphi_kernel<<<256, 256>>>(phi_t, phi_c, kp1_w, kp1_b, vp1_w, vp1_b);

    {   // weight-prep: G1|G2 -> s_BGh cols 256:512 (half), Wat -> s_Wt, Wac -> s_Wc
        GemmP p = mk(); p.A=g_w; p.lda=768; p.B=pWB; p.ldb=512; p.K=512;
        p.hC=pBGh; p.O2=pWt + 768*256; p.O3=pWc + 512*256;
        gemm_nt<64,64,4,4,EP_WPREP><<<dim3(12,4), 256>>>(p);
    }
    {   // [kt|vt|Q|At] = R_t @ s_Wt^T (+s_bt) -> s_Tt (ld 1024)
        GemmP p = mk(); p.A=R_t; p.lda=256; p.B=pWt; p.ldb=256; p.K=256;
        p.C=pTt; p.ldc=1024; p.vec=pbt;
        gemm_nt<64,64,4,4,EP_BIAS><<<dim3(16,4), 256>>>(p);
    }
    {   // [kc|vc|Ac] = R_ctx @ s_Wc^T -> s_Cc (ld 768)
        GemmP p = mk(); p.A=R_ctx; p.lda=256; p.B=pWc; p.ldb=256; p.K=256;
        p.C=pCc; p.ldc=768;
        gemm_nt<128,128,8,8,EP_NONE><<<dim3(6,8), 256>>>(p);
    }

    // --- fused pair kernel ---
    {
        FusedP fp;
        fp.Hh = pHh; fp.kp2h = pkp2h; fp.vp2h = pvp2h; fp.BGh = pBGh;
        fp.Kg = pKg; fp.Vg = pVg;
        fp.Tt = pTt; fp.Cc = pCc; fp.kpb = pkpb; fp.vpb = pvpb; fp.cb = pcb;
        fused_pair<<<NP_/128, 256, FUSED_SMEM>>>(fp);
    }

    // --- attention: ctx -> s_At ---
    attn_kernel<<<NTT_*8, 128>>>(pKg, pVg, pAt);

    // --- output projection ---
    {
        GemmP p = mk(); p.A=pAt; p.lda=256; p.B=out_w; p.ldb=256; p.K=256;
        p.C=outp; p.ldc=256; p.vec=out_b;
        gemm_nt<64,64,4,4,EP_BIAS><<<dim3(4,4), 256>>>(p);
    }
}

// round 10
// speedup vs baseline: 1.4785x; 1.4785x over previous
#include <cuda_runtime.h>
#include <cuda_fp16.h>
#include <math.h>
#include <stdint.h>

// ---------------------------------------------------------------------------
// TargetAwareContextAttention — fused pair kernel, 512 threads (16 warps),
// smem-staged B, K/V tiles in smem. fp16 mma.sync.
// B=2, Nt=128, Nc=512, D=256, DPHI=16, HID=128, H=8, dk=32; NP=131072 pairs.
// ---------------------------------------------------------------------------

#define D_    256
#define DPHI_ 16
#define HID_  128
#define B_    2
#define NT_   128
#define NC_   512
#define NTT_  (B_*NT_)    // 256
#define NCC_  (B_*NC_)    // 1024
#define NP_   (NTT_*NC_)  // 131072

// ------------------------------- scratch -----------------------------------
__device__ __half s_Hh[(size_t)NP_*256]; // [hk(128)|hv(128)]
__device__ __half s_Kg[(size_t)NP_*256];
__device__ __half s_Vg[(size_t)NP_*256];
__device__ __half s_BGh [256*512];      // gate B rows: [gw3 | G1|G2]
__device__ __half s_kp2h[256*128];
__device__ __half s_vp2h[256*128];
__device__ float s_Tt [NTT_*1024];      // [kt|vt|Q|At] per target row
__device__ float s_Cc [NCC_*768];       // [kc|vc|Ac] per ctx row
__device__ float s_At [NTT_*256];       // ctx (attention output)
__device__ float s_Wt [1024*256];       // [kt_w; vt_w; Wq_w; Wat]
__device__ float s_bt [1024];
__device__ float s_Wc [768*256];        // [kc_w; vc_w; Wac]
__device__ float s_WB [768*512];        // weight-prep B
__device__ float s_cb [256];
__device__ float s_kpb[256];
__device__ float s_vpb[256];

// --------------------------- helpers ----------------------------------------
__device__ __forceinline__ void mma16(float* c, const uint32_t* a, const uint32_t* b) {
    asm volatile(
        "mma.sync.aligned.m16n8k16.row.col.f32.f16.f16.f32 "
        "{%0,%1,%2,%3}, {%4,%5,%6,%7}, {%8,%9}, {%0,%1,%2,%3};"
        : "+f"(c[0]), "+f"(c[1]), "+f"(c[2]), "+f"(c[3])
        : "r"(a[0]), "r"(a[1]), "r"(a[2]), "r"(a[3]), "r"(b[0]), "r"(b[1]));
}
__device__ __forceinline__ uint32_t habsdiff2(uint32_t a, uint32_t b) {
    __half2 ha = *reinterpret_cast<__half2*>(&a);
    __half2 hb = *reinterpret_cast<__half2*>(&b);
    __half2 r = __habs2(__hsub2(ha, hb));
    return *reinterpret_cast<uint32_t*>(&r);
}

// ---------------------- fused pair kernel -----------------------------------
#define TP 132                                  // tile pitch (u32), 256-half rows
#define BP 20                                   // B staging pitch (u32)
#define FUSED_SMEM ((3*128*TP + 256*BP) * 4)    // 223232 B

struct FusedP {
    const __half *Hh, *kp2h, *vp2h, *BGh;
    __half *Kg, *Vg;
    const float *Tt, *Cc, *kpb, *vpb, *cb;
};

__global__ void __launch_bounds__(512) fused_pair(FusedP p) {
    extern __shared__ __align__(16) uint32_t sm[];
    uint32_t* Ht = sm;
    uint32_t* Kt = sm + 128*TP;
    uint32_t* Vt = sm + 2*128*TP;
    uint32_t* Bs = sm + 3*128*TP;   // 256 rows x BP

    const int tid   = threadIdx.x;
    const int lane  = tid & 31;
    const int wid   = tid >> 5;     // 0..15
    const int warpM = wid & 3;      // 32-row slice
    const int warpN = wid >> 2;     // 0..3 -> 64-col slice of 256
    const int g     = lane >> 2;
    const int t4    = lane & 3;
    const int mBase = blockIdx.x * 128;

    // load H tile (128 rows x 256 halves = 4096 uint4)
    for (int i = tid; i < 128*32; i += 512) {
        const int row = i >> 5, c4 = i & 31;
        *(uint4*)(Ht + row*TP + c4*4) =
            *(const uint4*)(p.Hh + (size_t)(mBase + row)*256 + c4*8);
    }
    __syncthreads();

    float acc[2][8][4];
    uint4 rb[2];   // B staging: 256 rows x 4 uint4 = 1024; 512 thr -> 2 each

    auto zeroAcc = [&]() {
#pragma unroll
        for (int mf = 0; mf < 2; mf++)
#pragma unroll
            for (int nf = 0; nf < 8; nf++)
#pragma unroll
                for (int q = 0; q < 4; q++) acc[mf][nf][q] = 0.f;
    };
    auto loadB = [&](const __half* Bp, int ldb, int kc) {
#pragma unroll
        for (int q = 0; q < 2; q++) {
            const int idx = q*512 + tid, row = idx >> 2, f4 = idx & 3;
            rb[q] = *(const uint4*)(Bp + (size_t)row*ldb + kc + f4*8);
        }
    };
    auto storeB = [&]() {
#pragma unroll
        for (int q = 0; q < 2; q++) {
            const int idx = q*512 + tid, row = idx >> 2, f4 = idx & 3;
            *(uint4*)(Bs + row*BP + f4*4) = rb[q];
        }
    };
    // one 32-half k-chunk; amode 0 -> A from Ht at u32 col aU; 1 -> |Kt-Vt|
    auto compute = [&](int amode, int aU) {
        const uint32_t* b_s = Bs + (warpN*64)*BP;
#pragma unroll
        for (int kf = 0; kf < 2; kf++) {
            const int kb = kf*8 + t4;
            uint32_t af[2][4];
#pragma unroll
            for (int mf = 0; mf < 2; mf++) {
                const int ro = (warpM*32 + mf*16 + g)*TP + aU + kb;
                if (amode == 0) {
                    af[mf][0] = Ht[ro];          af[mf][1] = Ht[ro + 8*TP];
                    af[mf][2] = Ht[ro + 4];      af[mf][3] = Ht[ro + 8*TP + 4];
                } else {
                    af[mf][0] = habsdiff2(Kt[ro],          Vt[ro]);
                    af[mf][1] = habsdiff2(Kt[ro + 8*TP],   Vt[ro + 8*TP]);
                    af[mf][2] = habsdiff2(Kt[ro + 4],      Vt[ro + 4]);
                    af[mf][3] = habsdiff2(Kt[ro + 8*TP+4], Vt[ro + 8*TP+4]);
                }
            }
            uint32_t bf[8][2];
#pragma unroll
            for (int nf = 0; nf < 8; nf++) {
                const uint32_t* bp = b_s + (nf*8 + g)*BP + kb;
                bf[nf][0] = bp[0]; bf[nf][1] = bp[4];
            }
#pragma unroll
            for (int mf = 0; mf < 2; mf++)
#pragma unroll
                for (int nf = 0; nf < 8; nf++)
                    mma16(acc[mf][nf], af[mf], bf[nf]);
        }
    };

    // ---- K and V phases: outputs to smem tiles ----
    for (int sel = 0; sel < 2; sel++) {
        const __half* Bp = sel ? p.vp2h : p.kp2h;
        const int   aBase = sel ? 64 : 0;
        uint32_t*   Ot    = sel ? Vt : Kt;
        const float* bias = sel ? p.vpb : p.kpb;
        const int   poff  = sel ? 256 : 0;
        zeroAcc();
        loadB(Bp, HID_, 0);
#pragma unroll
        for (int c = 0; c < 4; c++) {
            __syncthreads();
            storeB();
            __syncthreads();
            if (c < 3) loadB(Bp, HID_, (c+1)*32);
            compute(0, aBase + c*16);
        }
#pragma unroll
        for (int mf = 0; mf < 2; mf++)
#pragma unroll
        for (int hf = 0; hf < 2; hf++) {
            const int row  = warpM*32 + mf*16 + g + hf*8;
            const int grow = mBase + row;
            const int tg = grow >> 9;
            const int cx = ((grow >> 16) << 9) + (grow & 511);
            const float* r1 = p.Tt + (size_t)tg*1024 + poff;
            const float* r2 = p.Cc + (size_t)cx*768  + poff;
#pragma unroll
            for (int nf = 0; nf < 8; nf++) {
                const int col = warpN*64 + nf*8 + t4*2;
                float2 a = __ldg((const float2*)(r1 + col));
                float2 b = __ldg((const float2*)(r2 + col));
                float2 v = __ldg((const float2*)(bias + col));
                __half2 h = __floats2half2_rn(
                    acc[mf][nf][hf*2+0] + a.x + b.x + v.x,
                    acc[mf][nf][hf*2+1] + a.y + b.y + v.y);
                Ot[row*TP + (col >> 1)] = *reinterpret_cast<uint32_t*>(&h);
            }
        }
    }

    __syncthreads();   // K/V tiles visible cross-warp for gate A operand

    // ---- gate phase: K=512 (|K-V| then H) -> Kg/Vg in HBM ----
    zeroAcc();
    loadB(p.BGh, 512, 0);
#pragma unroll
    for (int c = 0; c < 16; c++) {
        __syncthreads();
        storeB();
        __syncthreads();
        if (c < 15) loadB(p.BGh, 512, (c+1)*32);
        if (c < 8) compute(1, c*16);
        else       compute(0, (c-8)*16);
    }
#pragma unroll
    for (int mf = 0; mf < 2; mf++)
#pragma unroll
    for (int hf = 0; hf < 2; hf++) {
        const int row  = warpM*32 + mf*16 + g + hf*8;
        const int grow = mBase + row;
        const size_t ro = (size_t)grow * 256;
        const int tg = grow >> 9;
        const int cx = ((grow >> 16) << 9) + (grow & 511);
        const float* r1 = p.Tt + (size_t)tg*1024 + 768;
        const float* r2 = p.Cc + (size_t)cx*768  + 512;
#pragma unroll
        for (int nf = 0; nf < 8; nf++) {
            const int col = warpN*64 + nf*8 + t4*2;
            float2 at = __ldg((const float2*)(r1 + col));
            float2 ac = __ldg((const float2*)(r2 + col));
            float2 cb = __ldg((const float2*)(p.cb + col));
            uint32_t ku = Kt[row*TP + (col >> 1)];
            uint32_t vu = Vt[row*TP + (col >> 1)];
            float2 kk = __half22float2(*reinterpret_cast<__half2*>(&ku));
            float2 vv = __half22float2(*reinterpret_cast<__half2*>(&vu));
            float g0 = 1.f / (1.f + __expf(-(acc[mf][nf][hf*2+0] + at.x + ac.x + cb.x)));
            float g1 = 1.f / (1.f + __expf(-(acc[mf][nf][hf*2+1] + at.y + ac.y + cb.y)));
            *(__half2*)(p.Kg + ro + col) = __floats2half2_rn(kk.x*g0, kk.y*g1);
            *(__half2*)(p.Vg + ro + col) = __floats2half2_rn(vv.x*g0, vv.y*g1);
        }
    }
}

// ------------------- fp32 FFMA2 GEMM (prologue-sized) -----------------------
__device__ __forceinline__ unsigned long long pk2(float lo, float hi) {
    unsigned long long r;
    asm("mov.b64 %0, {%1, %2};" : "=l"(r) : "f"(lo), "f"(hi));
    return r;
}
__device__ __forceinline__ void upk2(unsigned long long v, float& lo, float& hi) {
    asm("mov.b64 {%0, %1}, %2;" : "=f"(lo), "=f"(hi) : "l"(v));
}
__device__ __forceinline__ void ffma2(unsigned long long& d,
                                      unsigned long long a, unsigned long long b) {
    asm("fma.rn.f32x2 %0, %1, %2, %0;" : "+l"(d) : "l"(a), "l"(b));
}

struct GemmP {
    const float* A; int lda; int aoff;
    const float* B; int ldb; int boff;
    int K;
    float* C; int ldc; int coff;
    const float* vec;
    __half* hC; float* O2; float* O3;
};

enum { EP_NONE = 0, EP_BIAS = 1, EP_WPREP = 4 };

template<int BM, int BN, int TM, int TN, int EPI>
__global__ void __launch_bounds__(256, 1) gemm_nt(GemmP p) {
    constexpr int BK  = 16;
    constexpr int NTX = BN / TN;
    constexpr int PA  = BM / 64;
    constexpr int PB  = BN / 64;
    __shared__ __align__(16) float As[2][BK*BM];
    __shared__ __align__(16) float Bs[2][BK*BN];

    const int tid   = threadIdx.x;
    const int mBase = blockIdx.y * BM;
    const int nBase = blockIdx.x * BN;
    const int tx = tid % NTX;
    const int ty = tid / NTX;
    const int lrow = tid >> 2;
    const int lk   = (tid & 3) << 2;

    const float* Abase = p.A + (size_t)(mBase + lrow) * p.lda + p.aoff + lk;
    const float* Bbase = p.B + (size_t)(nBase + lrow) * p.ldb + p.boff + lk;

    unsigned long long acc2[TM/2][TN];
#pragma unroll
    for (int i = 0; i < TM/2; i++)
#pragma unroll
        for (int j = 0; j < TN; j++) acc2[i][j] = 0ull;

    const int nTiles = p.K / BK;
    float4 ra[PA], rb[PB];

#pragma unroll
    for (int q = 0; q < PA; q++) ra[q] = *(const float4*)(Abase + (size_t)q*64*p.lda);
#pragma unroll
    for (int q = 0; q < PB; q++) rb[q] = *(const float4*)(Bbase + (size_t)q*64*p.ldb);
#pragma unroll
    for (int q = 0; q < PA; q++) {
        int m = lrow + q*64;
        As[0][(lk+0)*BM+m]=ra[q].x; As[0][(lk+1)*BM+m]=ra[q].y;
        As[0][(lk+2)*BM+m]=ra[q].z; As[0][(lk+3)*BM+m]=ra[q].w;
    }
#pragma unroll
    for (int q = 0; q < PB; q++) {
        int n = lrow + q*64;
        Bs[0][(lk+0)*BN+n]=rb[q].x; Bs[0][(lk+1)*BN+n]=rb[q].y;
        Bs[0][(lk+2)*BN+n]=rb[q].z; Bs[0][(lk+3)*BN+n]=rb[q].w;
    }
    __syncthreads();

    for (int t = 0; t < nTiles; t++) {
        const int cur = t & 1;
        const bool more = (t + 1) < nTiles;
        if (more) {
            const int k0 = (t + 1) * BK;
#pragma unroll
            for (int q = 0; q < PA; q++) ra[q] = *(const float4*)(Abase + (size_t)q*64*p.lda + k0);
#pragma unroll
            for (int q = 0; q < PB; q++) rb[q] = *(const float4*)(Bbase + (size_t)q*64*p.ldb + k0);
        }
#pragma unroll
        for (int k = 0; k < BK; k++) {
            unsigned long long a2[TM/2], b2[TN];
#pragma unroll
            for (int i = 0; i < TM; i += 4) {
                ulonglong2 v = *(const ulonglong2*)&As[cur][k*BM + ty*TM + i];
                a2[i/2] = v.x; a2[i/2 + 1] = v.y;
            }
#pragma unroll
            for (int j = 0; j < TN; j += 4) {
                float4 v = *(const float4*)&Bs[cur][k*BN + tx*TN + j];
                b2[j+0] = pk2(v.x, v.x); b2[j+1] = pk2(v.y, v.y);
                b2[j+2] = pk2(v.z, v.z); b2[j+3] = pk2(v.w, v.w);
            }
#pragma unroll
            for (int i = 0; i < TM/2; i++)
#pragma unroll
                for (int j = 0; j < TN; j++) ffma2(acc2[i][j], a2[i], b2[j]);
        }
        if (more) {
            const int nxt = cur ^ 1;
            __syncthreads();
#pragma unroll
            for (int q = 0; q < PA; q++) {
                int m = lrow + q*64;
                As[nxt][(lk+0)*BM+m]=ra[q].x; As[nxt][(lk+1)*BM+m]=ra[q].y;
                As[nxt][(lk+2)*BM+m]=ra[q].z; As[nxt][(lk+3)*BM+m]=ra[q].w;
            }
#pragma unroll
            for (int q = 0; q < PB; q++) {
                int n = lrow + q*64;
                Bs[nxt][(lk+0)*BN+n]=rb[q].x; Bs[nxt][(lk+1)*BN+n]=rb[q].y;
                Bs[nxt][(lk+2)*BN+n]=rb[q].z; Bs[nxt][(lk+3)*BN+n]=rb[q].w;
            }
            __syncthreads();
        }
    }

    float accf[TM][TN];
#pragma unroll
    for (int i = 0; i < TM/2; i++)
#pragma unroll
        for (int j = 0; j < TN; j++) upk2(acc2[i][j], accf[2*i][j], accf[2*i+1][j]);

#pragma unroll
    for (int i = 0; i < TM; i++) {
        const int gm  = mBase + ty*TM + i;
        const int gn0 = nBase + tx*TN;
        if (EPI == EP_WPREP) {
#pragma unroll
            for (int j = 0; j < TN; j++) {
                const int d = gn0 + j;
                const float v = accf[i][j];
                if (d < 256)      p.hC[(size_t)gm*512 + 256 + d] = __float2half(v);
                else if (d < 512) p.O2[(size_t)gm*256 + (d-256)] = v;
                else              p.O3[(size_t)gm*256 + (d-512)] = v;
            }
        } else {
            float* co = p.C + (size_t)gm * p.ldc + p.coff + gn0;
#pragma unroll
            for (int j = 0; j < TN; j++) {
                float v = accf[i][j];
                if (EPI == EP_BIAS) v += p.vec[gn0 + j];
                co[j] = v;
            }
        }
    }
}

// --------------------- small helper kernels ---------------------------------
__global__ void pack_kernel(const float* kt_w, const float* vt_w,
                            const float* Wq_w, const float* Wq_b,
                            const float* kc_w, const float* vc_w,
                            const float* kp2_w, const float* vp2_w,
                            const float* g_w, const float* kp2_b,
                            const float* vp2_b) {
    int i = blockIdx.x * 256 + threadIdx.x;
    if (i < 196608) {
        s_Wt[i] = (i < 65536) ? kt_w[i]
                : (i < 131072) ? vt_w[i - 65536] : Wq_w[i - 131072];
    } else if (i < 327680) {
        int j = i - 196608;
        s_Wc[j] = (j < 65536) ? kc_w[j] : vc_w[j - 65536];
    } else if (i < 720896) {
        int j = i - 327680;
        int d = j >> 9, k = j & 511;
        float v;
        if (d < 128)       v = (k < 256) ? kp2_w[k*128 + d] : 0.f;
        else if (d < 256)  v = (k >= 256) ? vp2_w[(k-256)*128 + (d-128)] : 0.f;
        else if (d < 512)  v = (k < 256) ? kt_w[k*256 + (d-256)] : vt_w[(k-256)*256 + (d-256)];
        else               v = (k < 256) ? kc_w[k*256 + (d-512)] : vc_w[(k-256)*256 + (d-512)];
        s_WB[j] = v;
    } else if (i < 786432) {
        int j = i - 720896;
        int n = j >> 8, c = j & 255;
        s_BGh[n*512 + c] = __float2half(g_w[n*768 + 512 + c]);
    } else if (i < 819200) {
        int j = i - 786432;
        s_kp2h[j] = __float2half(kp2_w[j]);
    } else if (i < 851968) {
        int j = i - 819200;
        s_vp2h[j] = __float2half(vp2_w[j]);
    } else if (i < 852992) {
        int j = i - 851968;
        s_bt[j] = (j >= 512 && j < 768) ? Wq_b[j - 512] : 0.f;
    } else if (i < 853504) {
        int j = i - 852992;
        if (j < 256) s_kpb[j] = kp2_b[j];
        else         s_vpb[j - 256] = vp2_b[j - 256];
    }
}

__global__ void cb_kernel(const float* g_w, const float* g_b,
                          const float* kp2_b, const float* vp2_b) {
    int n = threadIdx.x;
    float s = g_b[n];
    const float* r = g_w + (size_t)n * 768;
    for (int d = 0; d < 256; d++)
        s += r[d] * kp2_b[d] + r[256 + d] * vp2_b[d];
    s_cb[n] = s;
}

__global__ void __launch_bounds__(256) hphi_kernel(
    const float* phi_t, const float* phi_c,
    const float* kp1_w, const float* kp1_b,
    const float* vp1_w, const float* vp1_b) {
    const int tg = blockIdx.x;
    const int b  = tg >> 7;
    const int tid = threadIdx.x;
    __shared__ float pt[DPHI_];
    __shared__ float pc[NC_*DPHI_];
    if (tid < DPHI_) pt[tid] = phi_t[tg*DPHI_ + tid];
    for (int i = tid; i < NC_*DPHI_; i += 256) pc[i] = phi_c[b*NC_*DPHI_ + i];
    const int h   = tid & 127;
    const int ncl = tid >> 7;
    float w1r[DPHI_], w2r[DPHI_];
#pragma unroll
    for (int j = 0; j < DPHI_; j++) {
        w1r[j] = kp1_w[h*DPHI_ + j];
        w2r[j] = vp1_w[h*DPHI_ + j];
    }
    const float b1 = kp1_b[h], b2 = vp1_b[h];
    __syncthreads();
    for (int it = 0; it < NC_/2; it++) {
        int nc = it*2 + ncl;
        float hk = b1, hv = b2;
#pragma unroll
        for (int j = 0; j < DPHI_; j++) {
            float dd = pt[j] - pc[nc*DPHI_ + j];
            hk = fmaf(w1r[j], dd, hk);
            hv = fmaf(w2r[j], dd, hv);
        }
        size_t o = ((size_t)tg*NC_ + nc) * 256 + h;
        s_Hh[o]       = __float2half(fmaxf(hk, 0.f));
        s_Hh[o + 128] = __float2half(fmaxf(hv, 0.f));
    }
}

__global__ void __launch_bounds__(128) attn_kernel(const __half* Kg, const __half* Vg,
                                                   float* ctxOut) {
    const int tg = blockIdx.x >> 3;
    const int h  = blockIdx.x & 7;
    const int t  = threadIdx.x;
    __shared__ float qv[32];
    __shared__ float sc[512];
    __shared__ float red[128];
    __shared__ float cpart[4][32];
    if (t < 32) qv[t] = s_Tt[tg*1024 + 512 + h*32 + t];
    __syncthreads();
    const float scale = 0.17677669529663687f;
    float ls[4];
    float lmax = -1e30f;
#pragma unroll
    for (int j = 0; j < 4; j++) {
        int nc = t + j*128;
        const __half* kr = Kg + ((size_t)tg*NC_ + nc)*256 + h*32;
        float s = 0.f;
#pragma unroll
        for (int d = 0; d < 32; d += 2) {
            float2 kv = __half22float2(*(const __half2*)(kr + d));
            s += qv[d]*kv.x + qv[d+1]*kv.y;
        }
        s *= scale;
        ls[j] = s;
        lmax = fmaxf(lmax, s);
    }
    red[t] = lmax; __syncthreads();
    for (int o = 64; o > 0; o >>= 1) {
        if (t < o) red[t] = fmaxf(red[t], red[t+o]);
        __syncthreads();
    }
    const float mx = red[0];
    __syncthreads();
    float lsum = 0.f;
#pragma unroll
    for (int j = 0; j < 4; j++) {
        float e = __expf(ls[j] - mx);
        sc[t + j*128] = e;
        lsum += e;
    }
    red[t] = lsum; __syncthreads();
    for (int o = 64; o > 0; o >>= 1) {
        if (t < o) red[t] += red[t+o];
        __syncthreads();
    }
    const float inv = 1.f / red[0];
    const int dk = t & 31, part = t >> 5;
    float acc = 0.f;
    const __half* vb = Vg + ((size_t)tg*NC_ + part*128)*256 + h*32 + dk;
    for (int nc = 0; nc < 128; nc++)
        acc = fmaf(sc[part*128 + nc], __half2float(vb[(size_t)nc*256]), acc);
    cpart[part][dk] = acc;
    __syncthreads();
    if (t < 32)
        ctxOut[tg*256 + h*32 + t] =
            (cpart[0][t] + cpart[1][t] + cpart[2][t] + cpart[3][t]) * inv;
}

// ------------------------------- launch -------------------------------------
static inline GemmP mk() { GemmP p; p.A=0;p.lda=0;p.aoff=0;p.B=0;p.ldb=0;
    p.boff=0;p.K=0;p.C=0;p.ldc=0;p.coff=0;p.vec=0;p.hC=0;p.O2=0;p.O3=0; return p; }

extern "C" void kernel_launch(void* const* d_in, const int* in_sizes, int n_in,
                              void* d_out, int out_size) {
    const float* R_t   = (const float*)d_in[0];
    const float* R_ctx = (const float*)d_in[1];
    const float* phi_t = (const float*)d_in[2];
    const float* phi_c = (const float*)d_in[3];
    const float* Wq_w  = (const float*)d_in[5];
    const float* Wq_b  = (const float*)d_in[6];
    const float* kc_w  = (const float*)d_in[7];
    const float* kt_w  = (const float*)d_in[8];
    const float* kp1_w = (const float*)d_in[9];
    const float* kp1_b = (const float*)d_in[10];
    const float* kp2_w = (const float*)d_in[11];
    const float* kp2_b = (const float*)d_in[12];
    const float* vc_w  = (const float*)d_in[13];
    const float* vt_w  = (const float*)d_in[14];
    const float* vp1_w = (const float*)d_in[15];
    const float* vp1_b = (const float*)d_in[16];
    const float* vp2_w = (const float*)d_in[17];
    const float* vp2_b = (const float*)d_in[18];
    const float* g_w   = (const float*)d_in[19];
    const float* g_b   = (const float*)d_in[20];
    const float* out_w = (const float*)d_in[21];
    const float* out_b = (const float*)d_in[22];
    float* outp = (float*)d_out;

    __half *pHh, *pKg, *pVg, *pBGh, *pkp2h, *pvp2h;
    float *pTt, *pCc, *pAt, *pWt, *pbt, *pWc, *pWB, *pcb, *pkpb, *pvpb;
    cudaGetSymbolAddress((void**)&pHh,  s_Hh);
    cudaGetSymbolAddress((void**)&pKg,  s_Kg);
    cudaGetSymbolAddress((void**)&pVg,  s_Vg);
    cudaGetSymbolAddress((void**)&pBGh, s_BGh);
    cudaGetSymbolAddress((void**)&pkp2h, s_kp2h);
    cudaGetSymbolAddress((void**)&pvp2h, s_vp2h);
    cudaGetSymbolAddress((void**)&pTt, s_Tt);
    cudaGetSymbolAddress((void**)&pCc, s_Cc);
    cudaGetSymbolAddress((void**)&pAt, s_At);
    cudaGetSymbolAddress((void**)&pWt, s_Wt);
    cudaGetSymbolAddress((void**)&pbt, s_bt);
    cudaGetSymbolAddress((void**)&pWc, s_Wc);
    cudaGetSymbolAddress((void**)&pWB, s_WB);
    cudaGetSymbolAddress((void**)&pcb, s_cb);
    cudaGetSymbolAddress((void**)&pkpb, s_kpb);
    cudaGetSymbolAddress((void**)&pvpb, s_vpb);

    cudaFuncSetAttribute(fused_pair,
                         cudaFuncAttributeMaxDynamicSharedMemorySize, FUSED_SMEM);

    pack_kernel<<<3335, 256>>>(kt_w, vt_w, Wq_w, Wq_b, kc_w, vc_w,
                               kp2_w, vp2_w, g_w, kp2_b, vp2_b);
    cb_kernel<<<1, 256>>>(g_w, g_b, kp2_b, vp2_b);
    hphi_kernel<<<256, 256>>>(phi_t, phi_c, kp1_w, kp1_b, vp1_w, vp1_b);

    {   // weight-prep: G1|G2 -> s_BGh cols 256:512 (half), Wat -> s_Wt, Wac -> s_Wc
        GemmP p = mk(); p.A=g_w; p.lda=768; p.B=pWB; p.ldb=512; p.K=512;
        p.hC=pBGh; p.O2=pWt + 768*256; p.O3=pWc + 512*256;
        gemm_nt<64,64,4,4,EP_WPREP><<<dim3(12,4), 256>>>(p);
    }
    {   // [kt|vt|Q|At] = R_t @ s_Wt^T (+s_bt) -> s_Tt (ld 1024)
        GemmP p = mk(); p.A=R_t; p.lda=256; p.B=pWt; p.ldb=256; p.K=256;
        p.C=pTt; p.ldc=1024; p.vec=pbt;
        gemm_nt<64,64,4,4,EP_BIAS><<<dim3(16,4), 256>>>(p);
    }
    {   // [kc|vc|Ac] = R_ctx @ s_Wc^T -> s_Cc (ld 768)
        GemmP p = mk(); p.A=R_ctx; p.lda=256; p.B=pWc; p.ldb=256; p.K=256;
        p.C=pCc; p.ldc=768;
        gemm_nt<128,128,8,8,EP_NONE><<<dim3(6,8), 256>>>(p);
    }

    // --- fused pair kernel (512 threads / 16 warps) ---
    {
        FusedP fp;
        fp.Hh = pHh; fp.kp2h = pkp2h; fp.vp2h = pvp2h; fp.BGh = pBGh;
        fp.Kg = pKg; fp.Vg = pVg;
        fp.Tt = pTt; fp.Cc = pCc; fp.kpb = pkpb; fp.vpb = pvpb; fp.cb = pcb;
        fused_pair<<<NP_/128, 512, FUSED_SMEM>>>(fp);
    }

    // --- attention: ctx -> s_At ---
    attn_kernel<<<NTT_*8, 128>>>(pKg, pVg, pAt);

    // --- output projection ---
    {
        GemmP p = mk(); p.A=pAt; p.lda=256; p.B=out_w; p.ldb=256; p.K=256;
        p.C=outp; p.ldc=256; p.vec=out_b;
        gemm_nt<64,64,4,4,EP_BIAS><<<dim3(4,4), 256>>>(p);
    }
}

// round 11
// speedup vs baseline: 1.6063x; 1.0864x over previous
#include <cuda_runtime.h>
#include <cuda_fp16.h>
#include <math.h>
#include <stdint.h>

// ---------------------------------------------------------------------------
// TargetAwareContextAttention — fused pair kernel (16 warps) with in-kernel
// flash-style partial attention; Kg/Vg never touch HBM.
// B=2, Nt=128, Nc=512, D=256, DPHI=16, HID=128, H=8, dk=32; NP=131072 pairs.
// ---------------------------------------------------------------------------

#define D_    256
#define DPHI_ 16
#define HID_  128
#define B_    2
#define NT_   128
#define NC_   512
#define NTT_  (B_*NT_)    // 256
#define NCC_  (B_*NC_)    // 1024
#define NP_   (NTT_*NC_)  // 131072

// ------------------------------- scratch -----------------------------------
__device__ __half s_Hh[(size_t)NP_*256]; // [hk(128)|hv(128)]
__device__ __half s_BGh [256*512];      // gate B rows: [gw3 | G1|G2]
__device__ __half s_kp2h[256*128];
__device__ __half s_vp2h[256*128];
__device__ float s_Tt [NTT_*1024];      // [kt|vt|Q|At] per target row
__device__ float s_Cc [NCC_*768];       // [kc|vc|Ac] per ctx row
__device__ float s_At [NTT_*256];       // ctx (attention output)
__device__ float s_Part[256*4*8*36];    // per-(tg,chunk,head): o[32], m, l
__device__ float s_Wt [1024*256];       // [kt_w; vt_w; Wq_w; Wat]
__device__ float s_bt [1024];
__device__ float s_Wc [768*256];        // [kc_w; vc_w; Wac]
__device__ float s_WB [768*512];        // weight-prep B
__device__ float s_cb [256];
__device__ float s_kpb[256];
__device__ float s_vpb[256];

// --------------------------- helpers ----------------------------------------
__device__ __forceinline__ void mma16(float* c, const uint32_t* a, const uint32_t* b) {
    asm volatile(
        "mma.sync.aligned.m16n8k16.row.col.f32.f16.f16.f32 "
        "{%0,%1,%2,%3}, {%4,%5,%6,%7}, {%8,%9}, {%0,%1,%2,%3};"
        : "+f"(c[0]), "+f"(c[1]), "+f"(c[2]), "+f"(c[3])
        : "r"(a[0]), "r"(a[1]), "r"(a[2]), "r"(a[3]), "r"(b[0]), "r"(b[1]));
}
__device__ __forceinline__ uint32_t habsdiff2(uint32_t a, uint32_t b) {
    __half2 ha = *reinterpret_cast<__half2*>(&a);
    __half2 hb = *reinterpret_cast<__half2*>(&b);
    __half2 r = __habs2(__hsub2(ha, hb));
    return *reinterpret_cast<uint32_t*>(&r);
}

// ---------------------- fused pair kernel -----------------------------------
#define TP 132                                  // tile pitch (u32), 256-half rows
#define BP 20                                   // B staging pitch (u32)
#define SP 132                                  // score pitch (floats)
#define FUSED_SMEM ((3*128*TP + 256*BP) * 4)    // 223232 B

struct FusedP {
    const __half *Hh, *kp2h, *vp2h, *BGh;
    float* Part;
    const float *Tt, *Cc, *kpb, *vpb, *cb;
};

__global__ void __launch_bounds__(512) fused_pair(FusedP p) {
    extern __shared__ __align__(16) uint32_t sm[];
    uint32_t* Ht = sm;
    uint32_t* Kt = sm + 128*TP;
    uint32_t* Vt = sm + 2*128*TP;
    uint32_t* Bs = sm + 3*128*TP;   // 256 rows x BP; reused for attn scratch

    const int tid   = threadIdx.x;
    const int lane  = tid & 31;
    const int wid   = tid >> 5;     // 0..15
    const int warpM = wid & 3;      // 32-row slice
    const int warpN = wid >> 2;     // 0..3 -> 64-col slice of 256
    const int g     = lane >> 2;
    const int t4    = lane & 3;
    const int mBase = blockIdx.x * 128;

    // load H tile (128 rows x 256 halves)
    for (int i = tid; i < 128*32; i += 512) {
        const int row = i >> 5, c4 = i & 31;
        *(uint4*)(Ht + row*TP + c4*4) =
            *(const uint4*)(p.Hh + (size_t)(mBase + row)*256 + c4*8);
    }
    __syncthreads();

    float acc[2][8][4];
    uint4 rb[2];

    auto zeroAcc = [&]() {
#pragma unroll
        for (int mf = 0; mf < 2; mf++)
#pragma unroll
            for (int nf = 0; nf < 8; nf++)
#pragma unroll
                for (int q = 0; q < 4; q++) acc[mf][nf][q] = 0.f;
    };
    auto loadB = [&](const __half* Bp, int ldb, int kc) {
#pragma unroll
        for (int q = 0; q < 2; q++) {
            const int idx = q*512 + tid, row = idx >> 2, f4 = idx & 3;
            rb[q] = *(const uint4*)(Bp + (size_t)row*ldb + kc + f4*8);
        }
    };
    auto storeB = [&]() {
#pragma unroll
        for (int q = 0; q < 2; q++) {
            const int idx = q*512 + tid, row = idx >> 2, f4 = idx & 3;
            *(uint4*)(Bs + row*BP + f4*4) = rb[q];
        }
    };
    auto compute = [&](int amode, int aU) {
        const uint32_t* b_s = Bs + (warpN*64)*BP;
#pragma unroll
        for (int kf = 0; kf < 2; kf++) {
            const int kb = kf*8 + t4;
            uint32_t af[2][4];
#pragma unroll
            for (int mf = 0; mf < 2; mf++) {
                const int ro = (warpM*32 + mf*16 + g)*TP + aU + kb;
                if (amode == 0) {
                    af[mf][0] = Ht[ro];          af[mf][1] = Ht[ro + 8*TP];
                    af[mf][2] = Ht[ro + 4];      af[mf][3] = Ht[ro + 8*TP + 4];
                } else {
                    af[mf][0] = habsdiff2(Kt[ro],          Vt[ro]);
                    af[mf][1] = habsdiff2(Kt[ro + 8*TP],   Vt[ro + 8*TP]);
                    af[mf][2] = habsdiff2(Kt[ro + 4],      Vt[ro + 4]);
                    af[mf][3] = habsdiff2(Kt[ro + 8*TP+4], Vt[ro + 8*TP+4]);
                }
            }
            uint32_t bf[8][2];
#pragma unroll
            for (int nf = 0; nf < 8; nf++) {
                const uint32_t* bp = b_s + (nf*8 + g)*BP + kb;
                bf[nf][0] = bp[0]; bf[nf][1] = bp[4];
            }
#pragma unroll
            for (int mf = 0; mf < 2; mf++)
#pragma unroll
                for (int nf = 0; nf < 8; nf++)
                    mma16(acc[mf][nf], af[mf], bf[nf]);
        }
    };

    // ---- K and V phases: outputs to smem tiles ----
    for (int sel = 0; sel < 2; sel++) {
        const __half* Bp = sel ? p.vp2h : p.kp2h;
        const int   aBase = sel ? 64 : 0;
        uint32_t*   Ot    = sel ? Vt : Kt;
        const float* bias = sel ? p.vpb : p.kpb;
        const int   poff  = sel ? 256 : 0;
        zeroAcc();
        loadB(Bp, HID_, 0);
#pragma unroll
        for (int c = 0; c < 4; c++) {
            __syncthreads();
            storeB();
            __syncthreads();
            if (c < 3) loadB(Bp, HID_, (c+1)*32);
            compute(0, aBase + c*16);
        }
#pragma unroll
        for (int mf = 0; mf < 2; mf++)
#pragma unroll
        for (int hf = 0; hf < 2; hf++) {
            const int row  = warpM*32 + mf*16 + g + hf*8;
            const int grow = mBase + row;
            const int tg = grow >> 9;
            const int cx = ((grow >> 16) << 9) + (grow & 511);
            const float* r1 = p.Tt + (size_t)tg*1024 + poff;
            const float* r2 = p.Cc + (size_t)cx*768  + poff;
#pragma unroll
            for (int nf = 0; nf < 8; nf++) {
                const int col = warpN*64 + nf*8 + t4*2;
                float2 a = __ldg((const float2*)(r1 + col));
                float2 b = __ldg((const float2*)(r2 + col));
                float2 v = __ldg((const float2*)(bias + col));
                __half2 h = __floats2half2_rn(
                    acc[mf][nf][hf*2+0] + a.x + b.x + v.x,
                    acc[mf][nf][hf*2+1] + a.y + b.y + v.y);
                Ot[row*TP + (col >> 1)] = *reinterpret_cast<uint32_t*>(&h);
            }
        }
    }

    __syncthreads();   // K/V tiles visible cross-warp for gate A operand

    // ---- gate phase: K=512 (|K-V| chunks 0-7, H chunks 8-15) ----
    zeroAcc();
    loadB(p.BGh, 512, 0);
#pragma unroll
    for (int c = 0; c < 16; c++) {
        __syncthreads();
        storeB();
        __syncthreads();
        if (c < 15) loadB(p.BGh, 512, (c+1)*32);
        if (c < 8) compute(1, c*16);
        else       compute(0, (c-8)*16);
    }
    // epilogue: g=sigmoid(pre); Kg,Vg overwrite Kt,Vt in smem.
    // Safe: |K-V| reads happen only in chunks 0-7, barrier-separated.
#pragma unroll
    for (int mf = 0; mf < 2; mf++)
#pragma unroll
    for (int hf = 0; hf < 2; hf++) {
        const int row  = warpM*32 + mf*16 + g + hf*8;
        const int grow = mBase + row;
        const int tg = grow >> 9;
        const int cx = ((grow >> 16) << 9) + (grow & 511);
        const float* r1 = p.Tt + (size_t)tg*1024 + 768;
        const float* r2 = p.Cc + (size_t)cx*768  + 512;
#pragma unroll
        for (int nf = 0; nf < 8; nf++) {
            const int col = warpN*64 + nf*8 + t4*2;
            float2 at = __ldg((const float2*)(r1 + col));
            float2 ac = __ldg((const float2*)(r2 + col));
            float2 cb = __ldg((const float2*)(p.cb + col));
            uint32_t ku = Kt[row*TP + (col >> 1)];
            uint32_t vu = Vt[row*TP + (col >> 1)];
            float2 kk = __half22float2(*reinterpret_cast<__half2*>(&ku));
            float2 vv = __half22float2(*reinterpret_cast<__half2*>(&vu));
            float g0 = 1.f / (1.f + __expf(-(acc[mf][nf][hf*2+0] + at.x + ac.x + cb.x)));
            float g1 = 1.f / (1.f + __expf(-(acc[mf][nf][hf*2+1] + at.y + ac.y + cb.y)));
            __half2 hk = __floats2half2_rn(kk.x*g0, kk.y*g1);
            __half2 hv = __floats2half2_rn(vv.x*g0, vv.y*g1);
            Kt[row*TP + (col >> 1)] = *reinterpret_cast<uint32_t*>(&hk);
            Vt[row*TP + (col >> 1)] = *reinterpret_cast<uint32_t*>(&hv);
        }
    }
    __syncthreads();

    // ---- in-CTA partial attention over this CTA's 128 ctx rows ----
    float* fs = (float*)Bs;   // scores h*SP+r (1056), Q at 1056, m at 1320
    const int tg    = blockIdx.x >> 2;
    const int chunk = blockIdx.x & 3;
    for (int i = tid; i < 256; i += 512)
        fs[1056 + i] = p.Tt[(size_t)tg*1024 + 512 + i];
    __syncthreads();

    const float scale = 0.17677669529663687f;  // 1/sqrt(32)
#pragma unroll
    for (int i = 0; i < 2; i++) {
        const int idx = i*512 + tid;            // 0..1023
        const int r = idx >> 3, h = idx & 7;
        const uint32_t* kr = Kt + r*TP + h*16;
        const float* qh = fs + 1056 + h*32;
        float s = 0.f;
#pragma unroll
        for (int j = 0; j < 16; j++) {
            uint32_t u = kr[j];
            float2 kv = __half22float2(*reinterpret_cast<__half2*>(&u));
            s += qh[2*j]*kv.x + qh[2*j+1]*kv.y;
        }
        fs[h*SP + r] = s * scale;
    }
    __syncthreads();
    if (tid < 8) {
        float m = -1e30f;
        for (int r = 0; r < 128; r++) m = fmaxf(m, fs[tid*SP + r]);
        fs[1320 + tid] = m;
    }
    __syncthreads();
#pragma unroll
    for (int i = 0; i < 2; i++) {
        const int idx = i*512 + tid;
        const int r = idx >> 3, h = idx & 7;
        fs[h*SP + r] = __expf(fs[h*SP + r] - fs[1320 + h]);
    }
    __syncthreads();

    float* pp = p.Part + ((size_t)(tg*4 + chunk) * 8) * 36;
    if (tid < 8) {
        float l = 0.f;
        for (int r = 0; r < 128; r++) l += fs[tid*SP + r];
        pp[tid*36 + 32] = fs[1320 + tid];
        pp[tid*36 + 33] = l;
    }
    if (tid < 128) {
        const int h = tid >> 4, dp = tid & 15;
        const uint32_t* vr = Vt + h*16 + dp;
        const float* pr = fs + h*SP;
        float o0 = 0.f, o1 = 0.f;
        for (int r = 0; r < 128; r++) {
            uint32_t u = vr[r*TP];
            float2 vv = __half22float2(*reinterpret_cast<__half2*>(&u));
            o0 = fmaf(pr[r], vv.x, o0);
            o1 = fmaf(pr[r], vv.y, o1);
        }
        pp[h*36 + dp*2]     = o0;
        pp[h*36 + dp*2 + 1] = o1;
    }
}

// ---------------------- attention partial reduce -----------------------------
__global__ void __launch_bounds__(256) attn_reduce(const float* Part, float* ctxOut) {
    const int tg = blockIdx.x;
    const int h = threadIdx.x >> 5, d = threadIdx.x & 31;
    const float* pp = Part + ((size_t)(tg*4) * 8 + h) * 36;   // chunk stride 288
    float m0 = pp[32], m1 = pp[288+32], m2 = pp[576+32], m3 = pp[864+32];
    float ms = fmaxf(fmaxf(m0, m1), fmaxf(m2, m3));
    float w0 = __expf(m0-ms), w1 = __expf(m1-ms), w2 = __expf(m2-ms), w3 = __expf(m3-ms);
    float l = w0*pp[33] + w1*pp[288+33] + w2*pp[576+33] + w3*pp[864+33];
    float o = w0*pp[d]  + w1*pp[288+d]  + w2*pp[576+d]  + w3*pp[864+d];
    ctxOut[tg*256 + h*32 + d] = o / l;
}

// ------------------- fp32 FFMA2 GEMM (prologue-sized) -----------------------
__device__ __forceinline__ unsigned long long pk2(float lo, float hi) {
    unsigned long long r;
    asm("mov.b64 %0, {%1, %2};" : "=l"(r) : "f"(lo), "f"(hi));
    return r;
}
__device__ __forceinline__ void upk2(unsigned long long v, float& lo, float& hi) {
    asm("mov.b64 {%0, %1}, %2;" : "=f"(lo), "=f"(hi) : "l"(v));
}
__device__ __forceinline__ void ffma2(unsigned long long& d,
                                      unsigned long long a, unsigned long long b) {
    asm("fma.rn.f32x2 %0, %1, %2, %0;" : "+l"(d) : "l"(a), "l"(b));
}

struct GemmP {
    const float* A; int lda; int aoff;
    const float* B; int ldb; int boff;
    int K;
    float* C; int ldc; int coff;
    const float* vec;
    __half* hC; float* O2; float* O3;
};

enum { EP_NONE = 0, EP_BIAS = 1, EP_WPREP = 4 };

template<int BM, int BN, int TM, int TN, int EPI>
__global__ void __launch_bounds__(256, 1) gemm_nt(GemmP p) {
    constexpr int BK  = 16;
    constexpr int NTX = BN / TN;
    constexpr int PA  = BM / 64;
    constexpr int PB  = BN / 64;
    __shared__ __align__(16) float As[2][BK*BM];
    __shared__ __align__(16) float Bs[2][BK*BN];

    const int tid   = threadIdx.x;
    const int mBase = blockIdx.y * BM;
    const int nBase = blockIdx.x * BN;
    const int tx = tid % NTX;
    const int ty = tid / NTX;
    const int lrow = tid >> 2;
    const int lk   = (tid & 3) << 2;

    const float* Abase = p.A + (size_t)(mBase + lrow) * p.lda + p.aoff + lk;
    const float* Bbase = p.B + (size_t)(nBase + lrow) * p.ldb + p.boff + lk;

    unsigned long long acc2[TM/2][TN];
#pragma unroll
    for (int i = 0; i < TM/2; i++)
#pragma unroll
        for (int j = 0; j < TN; j++) acc2[i][j] = 0ull;

    const int nTiles = p.K / BK;
    float4 ra[PA], rb[PB];

#pragma unroll
    for (int q = 0; q < PA; q++) ra[q] = *(const float4*)(Abase + (size_t)q*64*p.lda);
#pragma unroll
    for (int q = 0; q < PB; q++) rb[q] = *(const float4*)(Bbase + (size_t)q*64*p.ldb);
#pragma unroll
    for (int q = 0; q < PA; q++) {
        int m = lrow + q*64;
        As[0][(lk+0)*BM+m]=ra[q].x; As[0][(lk+1)*BM+m]=ra[q].y;
        As[0][(lk+2)*BM+m]=ra[q].z; As[0][(lk+3)*BM+m]=ra[q].w;
    }
#pragma unroll
    for (int q = 0; q < PB; q++) {
        int n = lrow + q*64;
        Bs[0][(lk+0)*BN+n]=rb[q].x; Bs[0][(lk+1)*BN+n]=rb[q].y;
        Bs[0][(lk+2)*BN+n]=rb[q].z; Bs[0][(lk+3)*BN+n]=rb[q].w;
    }
    __syncthreads();

    for (int t = 0; t < nTiles; t++) {
        const int cur = t & 1;
        const bool more = (t + 1) < nTiles;
        if (more) {
            const int k0 = (t + 1) * BK;
#pragma unroll
            for (int q = 0; q < PA; q++) ra[q] = *(const float4*)(Abase + (size_t)q*64*p.lda + k0);
#pragma unroll
            for (int q = 0; q < PB; q++) rb[q] = *(const float4*)(Bbase + (size_t)q*64*p.ldb + k0);
        }
#pragma unroll
        for (int k = 0; k < BK; k++) {
            unsigned long long a2[TM/2], b2[TN];
#pragma unroll
            for (int i = 0; i < TM; i += 4) {
                ulonglong2 v = *(const ulonglong2*)&As[cur][k*BM + ty*TM + i];
                a2[i/2] = v.x; a2[i/2 + 1] = v.y;
            }
#pragma unroll
            for (int j = 0; j < TN; j += 4) {
                float4 v = *(const float4*)&Bs[cur][k*BN + tx*TN + j];
                b2[j+0] = pk2(v.x, v.x); b2[j+1] = pk2(v.y, v.y);
                b2[j+2] = pk2(v.z, v.z); b2[j+3] = pk2(v.w, v.w);
            }
#pragma unroll
            for (int i = 0; i < TM/2; i++)
#pragma unroll
                for (int j = 0; j < TN; j++) ffma2(acc2[i][j], a2[i], b2[j]);
        }
        if (more) {
            const int nxt = cur ^ 1;
            __syncthreads();
#pragma unroll
            for (int q = 0; q < PA; q++) {
                int m = lrow + q*64;
                As[nxt][(lk+0)*BM+m]=ra[q].x; As[nxt][(lk+1)*BM+m]=ra[q].y;
                As[nxt][(lk+2)*BM+m]=ra[q].z; As[nxt][(lk+3)*BM+m]=ra[q].w;
            }
#pragma unroll
            for (int q = 0; q < PB; q++) {
                int n = lrow + q*64;
                Bs[nxt][(lk+0)*BN+n]=rb[q].x; Bs[nxt][(lk+1)*BN+n]=rb[q].y;
                Bs[nxt][(lk+2)*BN+n]=rb[q].z; Bs[nxt][(lk+3)*BN+n]=rb[q].w;
            }
            __syncthreads();
        }
    }

    float accf[TM][TN];
#pragma unroll
    for (int i = 0; i < TM/2; i++)
#pragma unroll
        for (int j = 0; j < TN; j++) upk2(acc2[i][j], accf[2*i][j], accf[2*i+1][j]);

#pragma unroll
    for (int i = 0; i < TM; i++) {
        const int gm  = mBase + ty*TM + i;
        const int gn0 = nBase + tx*TN;
        if (EPI == EP_WPREP) {
#pragma unroll
            for (int j = 0; j < TN; j++) {
                const int d = gn0 + j;
                const float v = accf[i][j];
                if (d < 256)      p.hC[(size_t)gm*512 + 256 + d] = __float2half(v);
                else if (d < 512) p.O2[(size_t)gm*256 + (d-256)] = v;
                else              p.O3[(size_t)gm*256 + (d-512)] = v;
            }
        } else {
            float* co = p.C + (size_t)gm * p.ldc + p.coff + gn0;
#pragma unroll
            for (int j = 0; j < TN; j++) {
                float v = accf[i][j];
                if (EPI == EP_BIAS) v += p.vec[gn0 + j];
                co[j] = v;
            }
        }
    }
}

// --------------------- small helper kernels ---------------------------------
__global__ void pack_kernel(const float* kt_w, const float* vt_w,
                            const float* Wq_w, const float* Wq_b,
                            const float* kc_w, const float* vc_w,
                            const float* kp2_w, const float* vp2_w,
                            const float* g_w, const float* kp2_b,
                            const float* vp2_b) {
    int i = blockIdx.x * 256 + threadIdx.x;
    if (i < 196608) {
        s_Wt[i] = (i < 65536) ? kt_w[i]
                : (i < 131072) ? vt_w[i - 65536] : Wq_w[i - 131072];
    } else if (i < 327680) {
        int j = i - 196608;
        s_Wc[j] = (j < 65536) ? kc_w[j] : vc_w[j - 65536];
    } else if (i < 720896) {
        int j = i - 327680;
        int d = j >> 9, k = j & 511;
        float v;
        if (d < 128)       v = (k < 256) ? kp2_w[k*128 + d] : 0.f;
        else if (d < 256)  v = (k >= 256) ? vp2_w[(k-256)*128 + (d-128)] : 0.f;
        else if (d < 512)  v = (k < 256) ? kt_w[k*256 + (d-256)] : vt_w[(k-256)*256 + (d-256)];
        else               v = (k < 256) ? kc_w[k*256 + (d-512)] : vc_w[(k-256)*256 + (d-512)];
        s_WB[j] = v;
    } else if (i < 786432) {
        int j = i - 720896;
        int n = j >> 8, c = j & 255;
        s_BGh[n*512 + c] = __float2half(g_w[n*768 + 512 + c]);
    } else if (i < 819200) {
        int j = i - 786432;
        s_kp2h[j] = __float2half(kp2_w[j]);
    } else if (i < 851968) {
        int j = i - 819200;
        s_vp2h[j] = __float2half(vp2_w[j]);
    } else if (i < 852992) {
        int j = i - 851968;
        s_bt[j] = (j >= 512 && j < 768) ? Wq_b[j - 512] : 0.f;
    } else if (i < 853504) {
        int j = i - 852992;
        if (j < 256) s_kpb[j] = kp2_b[j];
        else         s_vpb[j - 256] = vp2_b[j - 256];
    }
}

__global__ void cb_kernel(const float* g_w, const float* g_b,
                          const float* kp2_b, const float* vp2_b) {
    int n = threadIdx.x;
    float s = g_b[n];
    const float* r = g_w + (size_t)n * 768;
    for (int d = 0; d < 256; d++)
        s += r[d] * kp2_b[d] + r[256 + d] * vp2_b[d];
    s_cb[n] = s;
}

__global__ void __launch_bounds__(256) hphi_kernel(
    const float* phi_t, const float* phi_c,
    const float* kp1_w, const float* kp1_b,
    const float* vp1_w, const float* vp1_b) {
    const int tg = blockIdx.x;
    const int b  = tg >> 7;
    const int tid = threadIdx.x;
    __shared__ float pt[DPHI_];
    __shared__ float pc[NC_*DPHI_];
    if (tid < DPHI_) pt[tid] = phi_t[tg*DPHI_ + tid];
    for (int i = tid; i < NC_*DPHI_; i += 256) pc[i] = phi_c[b*NC_*DPHI_ + i];
    const int h   = tid & 127;
    const int ncl = tid >> 7;
    float w1r[DPHI_], w2r[DPHI_];
#pragma unroll
    for (int j = 0; j < DPHI_; j++) {
        w1r[j] = kp1_w[h*DPHI_ + j];
        w2r[j] = vp1_w[h*DPHI_ + j];
    }
    const float b1 = kp1_b[h], b2 = vp1_b[h];
    __syncthreads();
    for (int it = 0; it < NC_/2; it++) {
        int nc = it*2 + ncl;
        float hk = b1, hv = b2;
#pragma unroll
        for (int j = 0; j < DPHI_; j++) {
            float dd = pt[j] - pc[nc*DPHI_ + j];
            hk = fmaf(w1r[j], dd, hk);
            hv = fmaf(w2r[j], dd, hv);
        }
        size_t o = ((size_t)tg*NC_ + nc) * 256 + h;
        s_Hh[o]       = __float2half(fmaxf(hk, 0.f));
        s_Hh[o + 128] = __float2half(fmaxf(hv, 0.f));
    }
}

// ------------------------------- launch -------------------------------------
static inline GemmP mk() { GemmP p; p.A=0;p.lda=0;p.aoff=0;p.B=0;p.ldb=0;
    p.boff=0;p.K=0;p.C=0;p.ldc=0;p.coff=0;p.vec=0;p.hC=0;p.O2=0;p.O3=0; return p; }

extern "C" void kernel_launch(void* const* d_in, const int* in_sizes, int n_in,
                              void* d_out, int out_size) {
    const float* R_t   = (const float*)d_in[0];
    const float* R_ctx = (const float*)d_in[1];
    const float* phi_t = (const float*)d_in[2];
    const float* phi_c = (const float*)d_in[3];
    const float* Wq_w  = (const float*)d_in[5];
    const float* Wq_b  = (const float*)d_in[6];
    const float* kc_w  = (const float*)d_in[7];
    const float* kt_w  = (const float*)d_in[8];
    const float* kp1_w = (const float*)d_in[9];
    const float* kp1_b = (const float*)d_in[10];
    const float* kp2_w = (const float*)d_in[11];
    const float* kp2_b = (const float*)d_in[12];
    const float* vc_w  = (const float*)d_in[13];
    const float* vt_w  = (const float*)d_in[14];
    const float* vp1_w = (const float*)d_in[15];
    const float* vp1_b = (const float*)d_in[16];
    const float* vp2_w = (const float*)d_in[17];
    const float* vp2_b = (const float*)d_in[18];
    const float* g_w   = (const float*)d_in[19];
    const float* g_b   = (const float*)d_in[20];
    const float* out_w = (const float*)d_in[21];
    const float* out_b = (const float*)d_in[22];
    float* outp = (float*)d_out;

    __half *pHh, *pBGh, *pkp2h, *pvp2h;
    float *pTt, *pCc, *pAt, *pPart, *pWt, *pbt, *pWc, *pWB, *pcb, *pkpb, *pvpb;
    cudaGetSymbolAddress((void**)&pHh,  s_Hh);
    cudaGetSymbolAddress((void**)&pBGh, s_BGh);
    cudaGetSymbolAddress((void**)&pkp2h, s_kp2h);
    cudaGetSymbolAddress((void**)&pvp2h, s_vp2h);
    cudaGetSymbolAddress((void**)&pTt, s_Tt);
    cudaGetSymbolAddress((void**)&pCc, s_Cc);
    cudaGetSymbolAddress((void**)&pAt, s_At);
    cudaGetSymbolAddress((void**)&pPart, s_Part);
    cudaGetSymbolAddress((void**)&pWt, s_Wt);
    cudaGetSymbolAddress((void**)&pbt, s_bt);
    cudaGetSymbolAddress((void**)&pWc, s_Wc);
    cudaGetSymbolAddress((void**)&pWB, s_WB);
    cudaGetSymbolAddress((void**)&pcb, s_cb);
    cudaGetSymbolAddress((void**)&pkpb, s_kpb);
    cudaGetSymbolAddress((void**)&pvpb, s_vpb);

    cudaFuncSetAttribute(fused_pair,
                         cudaFuncAttributeMaxDynamicSharedMemorySize, FUSED_SMEM);

    pack_kernel<<<3335, 256>>>(kt_w, vt_w, Wq_w, Wq_b, kc_w, vc_w,
                               kp2_w, vp2_w, g_w, kp2_b, vp2_b);
    cb_kernel<<<1, 256>>>(g_w, g_b, kp2_b, vp2_b);
    hphi_kernel<<<256, 256>>>(phi_t, phi_c, kp1_w, kp1_b, vp1_w, vp1_b);

    {   // weight-prep: G1|G2 -> s_BGh cols 256:512 (half), Wat -> s_Wt, Wac -> s_Wc
        GemmP p = mk(); p.A=g_w; p.lda=768; p.B=pWB; p.ldb=512; p.K=512;
        p.hC=pBGh; p.O2=pWt + 768*256; p.O3=pWc + 512*256;
        gemm_nt<64,64,4,4,EP_WPREP><<<dim3(12,4), 256>>>(p);
    }
    {   // [kt|vt|Q|At] = R_t @ s_Wt^T (+s_bt) -> s_Tt (ld 1024)
        GemmP p = mk(); p.A=R_t; p.lda=256; p.B=pWt; p.ldb=256; p.K=256;
        p.C=pTt; p.ldc=1024; p.vec=pbt;
        gemm_nt<64,64,4,4,EP_BIAS><<<dim3(16,4), 256>>>(p);
    }
    {   // [kc|vc|Ac] = R_ctx @ s_Wc^T -> s_Cc (ld 768)
        GemmP p = mk(); p.A=R_ctx; p.lda=256; p.B=pWc; p.ldb=256; p.K=256;
        p.C=pCc; p.ldc=768;
        gemm_nt<128,128,8,8,EP_NONE><<<dim3(6,8), 256>>>(p);
    }

    // --- fused pair kernel (K/V/gate + partial attention) ---
    {
        FusedP fp;
        fp.Hh = pHh; fp.kp2h = pkp2h; fp.vp2h = pvp2h; fp.BGh = pBGh;
        fp.Part = pPart;
        fp.Tt = pTt; fp.Cc = pCc; fp.kpb = pkpb; fp.vpb = pvpb; fp.cb = pcb;
        fused_pair<<<NP_/128, 512, FUSED_SMEM>>>(fp);
    }

    // --- reduce partials -> ctx (s_At) ---
    attn_reduce<<<NTT_, 256>>>(pPart, pAt);

    // --- output projection ---
    {
        GemmP p = mk(); p.A=pAt; p.lda=256; p.B=out_w; p.ldb=256; p.K=256;
        p.C=outp; p.ldc=256; p.vec=out_b;
        gemm_nt<64,64,4,4,EP_BIAS><<<dim3(4,4), 256>>>(p);
    }
}

// round 12
// speedup vs baseline: 1.8538x; 1.1541x over previous
#include <cuda_runtime.h>
#include <cuda_fp16.h>
#include <math.h>
#include <stdint.h>

// ---------------------------------------------------------------------------
// TargetAwareContextAttention — fused pair kernel (16 warps) with in-kernel
// H construction (separable phi-MLP) + flash-style partial attention.
// B=2, Nt=128, Nc=512, D=256, DPHI=16, HID=128, H=8, dk=32; NP=131072 pairs.
// ---------------------------------------------------------------------------

#define D_    256
#define DPHI_ 16
#define HID_  128
#define B_    2
#define NT_   128
#define NC_   512
#define NTT_  (B_*NT_)    // 256
#define NCC_  (B_*NC_)    // 1024
#define NP_   (NTT_*NC_)  // 131072

// ------------------------------- scratch -----------------------------------
__device__ __half s_apt[NTT_*256];      // W1*phi_t + b (k|v halves)
__device__ __half s_Cph[NCC_*256];      // W1*phi_c (k|v halves)
__device__ __half s_BGh [256*512];      // gate B rows: [gw3 | G1|G2]
__device__ __half s_kp2h[256*128];
__device__ __half s_vp2h[256*128];
__device__ float s_Tt [NTT_*1024];      // [kt|vt|Q|At] per target row
__device__ float s_Cc [NCC_*768];       // [kc|vc|Ac] per ctx row
__device__ float s_At [NTT_*256];       // ctx (attention output)
__device__ float s_Part[256*4*8*36];    // per-(tg,chunk,head): o[32], m, l
__device__ float s_Wt [1024*256];       // [kt_w; vt_w; Wq_w; Wat]
__device__ float s_bt [1024];
__device__ float s_Wc [768*256];        // [kc_w; vc_w; Wac]
__device__ float s_WB [768*512];        // weight-prep B
__device__ float s_cb [256];
__device__ float s_kpb[256];
__device__ float s_vpb[256];
__device__ float s_zero[1024];          // stays zero

// --------------------------- helpers ----------------------------------------
__device__ __forceinline__ void mma16(float* c, const uint32_t* a, const uint32_t* b) {
    asm volatile(
        "mma.sync.aligned.m16n8k16.row.col.f32.f16.f16.f32 "
        "{%0,%1,%2,%3}, {%4,%5,%6,%7}, {%8,%9}, {%0,%1,%2,%3};"
        : "+f"(c[0]), "+f"(c[1]), "+f"(c[2]), "+f"(c[3])
        : "r"(a[0]), "r"(a[1]), "r"(a[2]), "r"(a[3]), "r"(b[0]), "r"(b[1]));
}
__device__ __forceinline__ uint32_t habsdiff2(uint32_t a, uint32_t b) {
    __half2 ha = *reinterpret_cast<__half2*>(&a);
    __half2 hb = *reinterpret_cast<__half2*>(&b);
    __half2 r = __habs2(__hsub2(ha, hb));
    return *reinterpret_cast<uint32_t*>(&r);
}
__device__ __forceinline__ uint32_t relusub2(uint32_t a, uint32_t c) {
    __half2 ha = *reinterpret_cast<__half2*>(&a);
    __half2 hc = *reinterpret_cast<__half2*>(&c);
    __half2 r = __hmax2(__hsub2(ha, hc), __float2half2_rn(0.f));
    return *reinterpret_cast<uint32_t*>(&r);
}

// ---------------------- fused pair kernel -----------------------------------
#define TP 132                                  // tile pitch (u32), 256-half rows
#define BP 20                                   // B staging pitch (u32)
#define SP 132                                  // score pitch (floats)
#define FUSED_SMEM ((3*128*TP + 256*BP) * 4)    // 223232 B

struct FusedP {
    const __half *apt, *Cph, *kp2h, *vp2h, *BGh;
    float* Part;
    const float *Tt, *Cc, *kpb, *vpb, *cb;
};

__global__ void __launch_bounds__(512) fused_pair(FusedP p) {
    extern __shared__ __align__(16) uint32_t sm[];
    uint32_t* Ht = sm;
    uint32_t* Kt = sm + 128*TP;
    uint32_t* Vt = sm + 2*128*TP;
    uint32_t* Bs = sm + 3*128*TP;   // 256 rows x BP; reused as scratch

    const int tid   = threadIdx.x;
    const int lane  = tid & 31;
    const int wid   = tid >> 5;     // 0..15
    const int warpM = wid & 3;      // 32-row slice
    const int warpN = wid >> 2;     // 0..3 -> 64-col slice of 256
    const int g     = lane >> 2;
    const int t4    = lane & 3;
    const int mBase = blockIdx.x * 128;
    const int tg    = blockIdx.x >> 2;
    const int chunk = blockIdx.x & 3;
    const int cx0   = (tg >> 7) * 512 + chunk * 128;

    // ---- build H tile: Ht[r][h] = relu(apt[tg][h] - Cph[cx0+r][h]) ----
    if (tid < 128) Bs[tid] = ((const uint32_t*)p.apt)[tg*128 + tid];
    __syncthreads();
    for (int i = tid; i < 128*32; i += 512) {
        const int row = i >> 5, c4 = i & 31;
        uint4 c = *(const uint4*)(p.Cph + (size_t)(cx0 + row)*256 + c4*8);
        uint4 o;
        o.x = relusub2(Bs[c4*4+0], c.x);
        o.y = relusub2(Bs[c4*4+1], c.y);
        o.z = relusub2(Bs[c4*4+2], c.z);
        o.w = relusub2(Bs[c4*4+3], c.w);
        *(uint4*)(Ht + row*TP + c4*4) = o;
    }
    __syncthreads();

    float acc[2][8][4];
    uint4 rb[2];

    auto zeroAcc = [&]() {
#pragma unroll
        for (int mf = 0; mf < 2; mf++)
#pragma unroll
            for (int nf = 0; nf < 8; nf++)
#pragma unroll
                for (int q = 0; q < 4; q++) acc[mf][nf][q] = 0.f;
    };
    auto loadB = [&](const __half* Bp, int ldb, int kc) {
#pragma unroll
        for (int q = 0; q < 2; q++) {
            const int idx = q*512 + tid, row = idx >> 2, f4 = idx & 3;
            rb[q] = *(const uint4*)(Bp + (size_t)row*ldb + kc + f4*8);
        }
    };
    auto storeB = [&]() {
#pragma unroll
        for (int q = 0; q < 2; q++) {
            const int idx = q*512 + tid, row = idx >> 2, f4 = idx & 3;
            *(uint4*)(Bs + row*BP + f4*4) = rb[q];
        }
    };
    auto compute = [&](int amode, int aU) {
        const uint32_t* b_s = Bs + (warpN*64)*BP;
#pragma unroll
        for (int kf = 0; kf < 2; kf++) {
            const int kb = kf*8 + t4;
            uint32_t af[2][4];
#pragma unroll
            for (int mf = 0; mf < 2; mf++) {
                const int ro = (warpM*32 + mf*16 + g)*TP + aU + kb;
                if (amode == 0) {
                    af[mf][0] = Ht[ro];          af[mf][1] = Ht[ro + 8*TP];
                    af[mf][2] = Ht[ro + 4];      af[mf][3] = Ht[ro + 8*TP + 4];
                } else {
                    af[mf][0] = habsdiff2(Kt[ro],          Vt[ro]);
                    af[mf][1] = habsdiff2(Kt[ro + 8*TP],   Vt[ro + 8*TP]);
                    af[mf][2] = habsdiff2(Kt[ro + 4],      Vt[ro + 4]);
                    af[mf][3] = habsdiff2(Kt[ro + 8*TP+4], Vt[ro + 8*TP+4]);
                }
            }
            uint32_t bf[8][2];
#pragma unroll
            for (int nf = 0; nf < 8; nf++) {
                const uint32_t* bp = b_s + (nf*8 + g)*BP + kb;
                bf[nf][0] = bp[0]; bf[nf][1] = bp[4];
            }
#pragma unroll
            for (int mf = 0; mf < 2; mf++)
#pragma unroll
                for (int nf = 0; nf < 8; nf++)
                    mma16(acc[mf][nf], af[mf], bf[nf]);
        }
    };

    // ---- K and V phases: outputs to smem tiles ----
    for (int sel = 0; sel < 2; sel++) {
        const __half* Bp = sel ? p.vp2h : p.kp2h;
        const int   aBase = sel ? 64 : 0;
        uint32_t*   Ot    = sel ? Vt : Kt;
        const float* bias = sel ? p.vpb : p.kpb;
        const int   poff  = sel ? 256 : 0;
        zeroAcc();
        loadB(Bp, HID_, 0);
#pragma unroll
        for (int c = 0; c < 4; c++) {
            __syncthreads();
            storeB();
            __syncthreads();
            if (c < 3) loadB(Bp, HID_, (c+1)*32);
            compute(0, aBase + c*16);
        }
#pragma unroll
        for (int mf = 0; mf < 2; mf++)
#pragma unroll
        for (int hf = 0; hf < 2; hf++) {
            const int row  = warpM*32 + mf*16 + g + hf*8;
            const int cx = cx0 + row;
            const float* r1 = p.Tt + (size_t)tg*1024 + poff;
            const float* r2 = p.Cc + (size_t)cx*768  + poff;
#pragma unroll
            for (int nf = 0; nf < 8; nf++) {
                const int col = warpN*64 + nf*8 + t4*2;
                float2 a = __ldg((const float2*)(r1 + col));
                float2 b = __ldg((const float2*)(r2 + col));
                float2 v = __ldg((const float2*)(bias + col));
                __half2 h = __floats2half2_rn(
                    acc[mf][nf][hf*2+0] + a.x + b.x + v.x,
                    acc[mf][nf][hf*2+1] + a.y + b.y + v.y);
                Ot[row*TP + (col >> 1)] = *reinterpret_cast<uint32_t*>(&h);
            }
        }
    }

    __syncthreads();   // K/V tiles visible cross-warp for gate A operand

    // ---- gate phase: K=512 (|K-V| chunks 0-7, H chunks 8-15) ----
    zeroAcc();
    loadB(p.BGh, 512, 0);
#pragma unroll
    for (int c = 0; c < 16; c++) {
        __syncthreads();
        storeB();
        __syncthreads();
        if (c < 15) loadB(p.BGh, 512, (c+1)*32);
        if (c < 8) compute(1, c*16);
        else       compute(0, (c-8)*16);
    }
    // epilogue: g=sigmoid(pre); Kg,Vg overwrite Kt,Vt in smem.
#pragma unroll
    for (int mf = 0; mf < 2; mf++)
#pragma unroll
    for (int hf = 0; hf < 2; hf++) {
        const int row  = warpM*32 + mf*16 + g + hf*8;
        const int cx = cx0 + row;
        const float* r1 = p.Tt + (size_t)tg*1024 + 768;
        const float* r2 = p.Cc + (size_t)cx*768  + 512;
#pragma unroll
        for (int nf = 0; nf < 8; nf++) {
            const int col = warpN*64 + nf*8 + t4*2;
            float2 at = __ldg((const float2*)(r1 + col));
            float2 ac = __ldg((const float2*)(r2 + col));
            float2 cb = __ldg((const float2*)(p.cb + col));
            uint32_t ku = Kt[row*TP + (col >> 1)];
            uint32_t vu = Vt[row*TP + (col >> 1)];
            float2 kk = __half22float2(*reinterpret_cast<__half2*>(&ku));
            float2 vv = __half22float2(*reinterpret_cast<__half2*>(&vu));
            float g0 = 1.f / (1.f + __expf(-(acc[mf][nf][hf*2+0] + at.x + ac.x + cb.x)));
            float g1 = 1.f / (1.f + __expf(-(acc[mf][nf][hf*2+1] + at.y + ac.y + cb.y)));
            __half2 hk = __floats2half2_rn(kk.x*g0, kk.y*g1);
            __half2 hv = __floats2half2_rn(vv.x*g0, vv.y*g1);
            Kt[row*TP + (col >> 1)] = *reinterpret_cast<uint32_t*>(&hk);
            Vt[row*TP + (col >> 1)] = *reinterpret_cast<uint32_t*>(&hv);
        }
    }
    __syncthreads();

    // ---- in-CTA partial attention over this CTA's 128 ctx rows ----
    float* fs = (float*)Bs;   // scores h*SP+r (1056), Q at 1056, m at 1320
    for (int i = tid; i < 256; i += 512)
        fs[1056 + i] = p.Tt[(size_t)tg*1024 + 512 + i];
    __syncthreads();

    const float scale = 0.17677669529663687f;  // 1/sqrt(32)
#pragma unroll
    for (int i = 0; i < 2; i++) {
        const int idx = i*512 + tid;            // 0..1023
        const int r = idx >> 3, h = idx & 7;
        const uint32_t* kr = Kt + r*TP + h*16;
        const float* qh = fs + 1056 + h*32;
        float s = 0.f;
#pragma unroll
        for (int j = 0; j < 16; j++) {
            uint32_t u = kr[j];
            float2 kv = __half22float2(*reinterpret_cast<__half2*>(&u));
            s += qh[2*j]*kv.x + qh[2*j+1]*kv.y;
        }
        fs[h*SP + r] = s * scale;
    }
    __syncthreads();
    if (tid < 8) {
        float m = -1e30f;
        for (int r = 0; r < 128; r++) m = fmaxf(m, fs[tid*SP + r]);
        fs[1320 + tid] = m;
    }
    __syncthreads();
#pragma unroll
    for (int i = 0; i < 2; i++) {
        const int idx = i*512 + tid;
        const int r = idx >> 3, h = idx & 7;
        fs[h*SP + r] = __expf(fs[h*SP + r] - fs[1320 + h]);
    }
    __syncthreads();

    float* pp = p.Part + ((size_t)(tg*4 + chunk) * 8) * 36;
    if (tid < 8) {
        float l = 0.f;
        for (int r = 0; r < 128; r++) l += fs[tid*SP + r];
        pp[tid*36 + 32] = fs[1320 + tid];
        pp[tid*36 + 33] = l;
    }
    if (tid < 128) {
        const int h = tid >> 4, dp = tid & 15;
        const uint32_t* vr = Vt + h*16 + dp;
        const float* pr = fs + h*SP;
        float o0 = 0.f, o1 = 0.f;
        for (int r = 0; r < 128; r++) {
            uint32_t u = vr[r*TP];
            float2 vv = __half22float2(*reinterpret_cast<__half2*>(&u));
            o0 = fmaf(pr[r], vv.x, o0);
            o1 = fmaf(pr[r], vv.y, o1);
        }
        pp[h*36 + dp*2]     = o0;
        pp[h*36 + dp*2 + 1] = o1;
    }
}

// ---------------------- attention partial reduce -----------------------------
__global__ void __launch_bounds__(256) attn_reduce(const float* Part, float* ctxOut) {
    const int tg = blockIdx.x;
    const int h = threadIdx.x >> 5, d = threadIdx.x & 31;
    const float* pp = Part + ((size_t)(tg*4) * 8 + h) * 36;   // chunk stride 288
    float m0 = pp[32], m1 = pp[288+32], m2 = pp[576+32], m3 = pp[864+32];
    float ms = fmaxf(fmaxf(m0, m1), fmaxf(m2, m3));
    float w0 = __expf(m0-ms), w1 = __expf(m1-ms), w2 = __expf(m2-ms), w3 = __expf(m3-ms);
    float l = w0*pp[33] + w1*pp[288+33] + w2*pp[576+33] + w3*pp[864+33];
    float o = w0*pp[d]  + w1*pp[288+d]  + w2*pp[576+d]  + w3*pp[864+d];
    ctxOut[tg*256 + h*32 + d] = o / l;
}

// ------------------- fp32 FFMA2 GEMM (prologue-sized) -----------------------
__device__ __forceinline__ unsigned long long pk2(float lo, float hi) {
    unsigned long long r;
    asm("mov.b64 %0, {%1, %2};" : "=l"(r) : "f"(lo), "f"(hi));
    return r;
}
__device__ __forceinline__ void upk2(unsigned long long v, float& lo, float& hi) {
    asm("mov.b64 {%0, %1}, %2;" : "=f"(lo), "=f"(hi) : "l"(v));
}
__device__ __forceinline__ void ffma2(unsigned long long& d,
                                      unsigned long long a, unsigned long long b) {
    asm("fma.rn.f32x2 %0, %1, %2, %0;" : "+l"(d) : "l"(a), "l"(b));
}

struct GemmP {
    const float* A; int lda; int aoff;
    const float* B; int ldb; int boff;
    int K;
    float* C; int ldc; int coff;
    const float* vec;
    __half* hC; float* O2; float* O3;
};

enum { EP_NONE = 0, EP_BIAS = 1, EP_WPREP = 4 };

// 64x64 tile, TM=TN=4, 256 threads, EP_BIAS body (shared by two kernels)
__device__ __forceinline__ void gemm64_body(const GemmP& p, int mBase, int nBase) {
    constexpr int BM = 64, BN = 64, BK = 16, TM = 4, TN = 4, NTX = 16;
    __shared__ __align__(16) float As[2][BK*BM];
    __shared__ __align__(16) float Bs[2][BK*BN];

    const int tid = threadIdx.x;
    const int tx = tid % NTX;
    const int ty = tid / NTX;
    const int lrow = tid >> 2;
    const int lk   = (tid & 3) << 2;

    const float* Abase = p.A + (size_t)(mBase + lrow) * p.lda + p.aoff + lk;
    const float* Bbase = p.B + (size_t)(nBase + lrow) * p.ldb + p.boff + lk;

    unsigned long long acc2[TM/2][TN];
#pragma unroll
    for (int i = 0; i < TM/2; i++)
#pragma unroll
        for (int j = 0; j < TN; j++) acc2[i][j] = 0ull;

    const int nTiles = p.K / BK;
    float4 ra, rbv;
    ra  = *(const float4*)(Abase);
    rbv = *(const float4*)(Bbase);
    {
        int m = lrow;
        As[0][(lk+0)*BM+m]=ra.x; As[0][(lk+1)*BM+m]=ra.y;
        As[0][(lk+2)*BM+m]=ra.z; As[0][(lk+3)*BM+m]=ra.w;
        Bs[0][(lk+0)*BN+m]=rbv.x; Bs[0][(lk+1)*BN+m]=rbv.y;
        Bs[0][(lk+2)*BN+m]=rbv.z; Bs[0][(lk+3)*BN+m]=rbv.w;
    }
    __syncthreads();

    for (int t = 0; t < nTiles; t++) {
        const int cur = t & 1;
        const bool more = (t + 1) < nTiles;
        if (more) {
            const int k0 = (t + 1) * BK;
            ra  = *(const float4*)(Abase + k0);
            rbv = *(const float4*)(Bbase + k0);
        }
#pragma unroll
        for (int k = 0; k < BK; k++) {
            unsigned long long a2[TM/2], b2[TN];
            ulonglong2 va = *(const ulonglong2*)&As[cur][k*BM + ty*TM];
            a2[0] = va.x; a2[1] = va.y;
            float4 vb = *(const float4*)&Bs[cur][k*BN + tx*TN];
            b2[0] = pk2(vb.x, vb.x); b2[1] = pk2(vb.y, vb.y);
            b2[2] = pk2(vb.z, vb.z); b2[3] = pk2(vb.w, vb.w);
#pragma unroll
            for (int i = 0; i < TM/2; i++)
#pragma unroll
                for (int j = 0; j < TN; j++) ffma2(acc2[i][j], a2[i], b2[j]);
        }
        if (more) {
            const int nxt = cur ^ 1;
            __syncthreads();
            int m = lrow;
            As[nxt][(lk+0)*BM+m]=ra.x; As[nxt][(lk+1)*BM+m]=ra.y;
            As[nxt][(lk+2)*BM+m]=ra.z; As[nxt][(lk+3)*BM+m]=ra.w;
            Bs[nxt][(lk+0)*BN+m]=rbv.x; Bs[nxt][(lk+1)*BN+m]=rbv.y;
            Bs[nxt][(lk+2)*BN+m]=rbv.z; Bs[nxt][(lk+3)*BN+m]=rbv.w;
            __syncthreads();
        }
    }

    float accf[TM][TN];
#pragma unroll
    for (int i = 0; i < TM/2; i++)
#pragma unroll
        for (int j = 0; j < TN; j++) upk2(acc2[i][j], accf[2*i][j], accf[2*i+1][j]);

#pragma unroll
    for (int i = 0; i < TM; i++) {
        const int gm  = mBase + ty*TM + i;
        const int gn0 = nBase + tx*TN;
        float* co = p.C + (size_t)gm * p.ldc + p.coff + gn0;
#pragma unroll
        for (int j = 0; j < TN; j++)
            co[j] = accf[i][j] + p.vec[gn0 + j];
    }
}

// combined Tt + Cc projection launch (flat grid)
__global__ void __launch_bounds__(256, 1) gemm64_dual(GemmP pa, int nba, int gxa,
                                                      GemmP pb, int gxb) {
    const int bid = blockIdx.x;
    if (bid < nba) gemm64_body(pa, (bid / gxa) * 64, (bid % gxa) * 64);
    else {
        const int b2 = bid - nba;
        gemm64_body(pb, (b2 / gxb) * 64, (b2 % gxb) * 64);
    }
}

template<int EPI>
__global__ void __launch_bounds__(256, 1) gemm_nt(GemmP p) {
    constexpr int BM = 64, BN = 64, BK = 16, TM = 4, TN = 4, NTX = 16;
    __shared__ __align__(16) float As[2][BK*BM];
    __shared__ __align__(16) float Bs[2][BK*BN];

    const int tid   = threadIdx.x;
    const int mBase = blockIdx.y * BM;
    const int nBase = blockIdx.x * BN;
    const int tx = tid % NTX;
    const int ty = tid / NTX;
    const int lrow = tid >> 2;
    const int lk   = (tid & 3) << 2;

    const float* Abase = p.A + (size_t)(mBase + lrow) * p.lda + p.aoff + lk;
    const float* Bbase = p.B + (size_t)(nBase + lrow) * p.ldb + p.boff + lk;

    unsigned long long acc2[TM/2][TN];
#pragma unroll
    for (int i = 0; i < TM/2; i++)
#pragma unroll
        for (int j = 0; j < TN; j++) acc2[i][j] = 0ull;

    const int nTiles = p.K / BK;
    float4 ra, rbv;
    ra  = *(const float4*)(Abase);
    rbv = *(const float4*)(Bbase);
    {
        int m = lrow;
        As[0][(lk+0)*BM+m]=ra.x; As[0][(lk+1)*BM+m]=ra.y;
        As[0][(lk+2)*BM+m]=ra.z; As[0][(lk+3)*BM+m]=ra.w;
        Bs[0][(lk+0)*BN+m]=rbv.x; Bs[0][(lk+1)*BN+m]=rbv.y;
        Bs[0][(lk+2)*BN+m]=rbv.z; Bs[0][(lk+3)*BN+m]=rbv.w;
    }
    __syncthreads();

    for (int t = 0; t < nTiles; t++) {
        const int cur = t & 1;
        const bool more = (t + 1) < nTiles;
        if (more) {
            const int k0 = (t + 1) * BK;
            ra  = *(const float4*)(Abase + k0);
            rbv = *(const float4*)(Bbase + k0);
        }
#pragma unroll
        for (int k = 0; k < BK; k++) {
            unsigned long long a2[TM/2], b2[TN];
            ulonglong2 va = *(const ulonglong2*)&As[cur][k*BM + ty*TM];
            a2[0] = va.x; a2[1] = va.y;
            float4 vb = *(const float4*)&Bs[cur][k*BN + tx*TN];
            b2[0] = pk2(vb.x, vb.x); b2[1] = pk2(vb.y, vb.y);
            b2[2] = pk2(vb.z, vb.z); b2[3] = pk2(vb.w, vb.w);
#pragma unroll
            for (int i = 0; i < TM/2; i++)
#pragma unroll
                for (int j = 0; j < TN; j++) ffma2(acc2[i][j], a2[i], b2[j]);
        }
        if (more) {
            const int nxt = cur ^ 1;
            __syncthreads();
            int m = lrow;
            As[nxt][(lk+0)*BM+m]=ra.x; As[nxt][(lk+1)*BM+m]=ra.y;
            As[nxt][(lk+2)*BM+m]=ra.z; As[nxt][(lk+3)*BM+m]=ra.w;
            Bs[nxt][(lk+0)*BN+m]=rbv.x; Bs[nxt][(lk+1)*BN+m]=rbv.y;
            Bs[nxt][(lk+2)*BN+m]=rbv.z; Bs[nxt][(lk+3)*BN+m]=rbv.w;
            __syncthreads();
        }
    }

    float accf[TM][TN];
#pragma unroll
    for (int i = 0; i < TM/2; i++)
#pragma unroll
        for (int j = 0; j < TN; j++) upk2(acc2[i][j], accf[2*i][j], accf[2*i+1][j]);

#pragma unroll
    for (int i = 0; i < TM; i++) {
        const int gm  = mBase + ty*TM + i;
        const int gn0 = nBase + tx*TN;
        if (EPI == EP_WPREP) {
#pragma unroll
            for (int j = 0; j < TN; j++) {
                const int d = gn0 + j;
                const float v = accf[i][j];
                if (d < 256)      p.hC[(size_t)gm*512 + 256 + d] = __float2half(v);
                else if (d < 512) p.O2[(size_t)gm*256 + (d-256)] = v;
                else              p.O3[(size_t)gm*256 + (d-512)] = v;
            }
        } else {
            float* co = p.C + (size_t)gm * p.ldc + p.coff + gn0;
#pragma unroll
            for (int j = 0; j < TN; j++) {
                float v = accf[i][j];
                if (EPI == EP_BIAS) v += p.vec[gn0 + j];
                co[j] = v;
            }
        }
    }
}

// --------------------- small helper kernels ---------------------------------
__global__ void pack_kernel(const float* kt_w, const float* vt_w,
                            const float* Wq_w, const float* Wq_b,
                            const float* kc_w, const float* vc_w,
                            const float* kp2_w, const float* vp2_w,
                            const float* g_w, const float* kp2_b,
                            const float* vp2_b) {
    int i = blockIdx.x * 256 + threadIdx.x;
    if (i < 196608) {
        s_Wt[i] = (i < 65536) ? kt_w[i]
                : (i < 131072) ? vt_w[i - 65536] : Wq_w[i - 131072];
    } else if (i < 327680) {
        int j = i - 196608;
        s_Wc[j] = (j < 65536) ? kc_w[j] : vc_w[j - 65536];
    } else if (i < 720896) {
        int j = i - 327680;
        int d = j >> 9, k = j & 511;
        float v;
        if (d < 128)       v = (k < 256) ? kp2_w[k*128 + d] : 0.f;
        else if (d < 256)  v = (k >= 256) ? vp2_w[(k-256)*128 + (d-128)] : 0.f;
        else if (d < 512)  v = (k < 256) ? kt_w[k*256 + (d-256)] : vt_w[(k-256)*256 + (d-256)];
        else               v = (k < 256) ? kc_w[k*256 + (d-512)] : vc_w[(k-256)*256 + (d-512)];
        s_WB[j] = v;
    } else if (i < 786432) {
        int j = i - 720896;
        int n = j >> 8, c = j & 255;
        s_BGh[n*512 + c] = __float2half(g_w[n*768 + 512 + c]);
    } else if (i < 819200) {
        int j = i - 786432;
        s_kp2h[j] = __float2half(kp2_w[j]);
    } else if (i < 851968) {
        int j = i - 819200;
        s_vp2h[j] = __float2half(vp2_w[j]);
    } else if (i < 852992) {
        int j = i - 851968;
        s_bt[j] = (j >= 512 && j < 768) ? Wq_b[j - 512] : 0.f;
    } else if (i < 853504) {
        int j = i - 852992;
        if (j < 256) s_kpb[j] = kp2_b[j];
        else         s_vpb[j - 256] = vp2_b[j - 256];
    }
}

__global__ void cb_kernel(const float* g_w, const float* g_b,
                          const float* kp2_b, const float* vp2_b) {
    int n = threadIdx.x;
    float s = g_b[n];
    const float* r = g_w + (size_t)n * 768;
    for (int d = 0; d < 256; d++)
        s += r[d] * kp2_b[d] + r[256 + d] * vp2_b[d];
    s_cb[n] = s;
}

// phi projections: apt = W1*phi_t + b (targets), Cph = W1*phi_c (ctx)
__global__ void __launch_bounds__(256) phiproj_kernel(
    const float* phi_t, const float* phi_c,
    const float* kp1_w, const float* kp1_b,
    const float* vp1_w, const float* vp1_b) {
    const int rowId = blockIdx.x;           // 0..1279
    const int h = threadIdx.x;              // 0..255
    const bool isT = rowId < NTT_;
    const float* src = isT ? (phi_t + rowId*DPHI_)
                           : (phi_c + (size_t)(rowId - NTT_)*DPHI_);
    __shared__ float ph[DPHI_];
    if (h < DPHI_) ph[h] = src[h];
    __syncthreads();
    const float* W = (h < 128) ? (kp1_w + h*DPHI_) : (vp1_w + (h-128)*DPHI_);
    float s = 0.f;
#pragma unroll
    for (int j = 0; j < DPHI_; j++) s = fmaf(W[j], ph[j], s);
    if (isT) s += (h < 128) ? kp1_b[h] : vp1_b[h-128];
    __half* dst = isT ? (s_apt + (size_t)rowId*256)
                      : (s_Cph + (size_t)(rowId - NTT_)*256);
    dst[h] = __float2half(s);
}

// ------------------------------- launch -------------------------------------
static inline GemmP mk() { GemmP p; p.A=0;p.lda=0;p.aoff=0;p.B=0;p.ldb=0;
    p.boff=0;p.K=0;p.C=0;p.ldc=0;p.coff=0;p.vec=0;p.hC=0;p.O2=0;p.O3=0; return p; }

extern "C" void kernel_launch(void* const* d_in, const int* in_sizes, int n_in,
                              void* d_out, int out_size) {
    const float* R_t   = (const float*)d_in[0];
    const float* R_ctx = (const float*)d_in[1];
    const float* phi_t = (const float*)d_in[2];
    const float* phi_c = (const float*)d_in[3];
    const float* Wq_w  = (const float*)d_in[5];
    const float* Wq_b  = (const float*)d_in[6];
    const float* kc_w  = (const float*)d_in[7];
    const float* kt_w  = (const float*)d_in[8];
    const float* kp1_w = (const float*)d_in[9];
    const float* kp1_b = (const float*)d_in[10];
    const float* kp2_w = (const float*)d_in[11];
    const float* kp2_b = (const float*)d_in[12];
    const float* vc_w  = (const float*)d_in[13];
    const float* vt_w  = (const float*)d_in[14];
    const float* vp1_w = (const float*)d_in[15];
    const float* vp1_b = (const float*)d_in[16];
    const float* vp2_w = (const float*)d_in[17];
    const float* vp2_b = (const float*)d_in[18];
    const float* g_w   = (const float*)d_in[19];
    const float* g_b   = (const float*)d_in[20];
    const float* out_w = (const float*)d_in[21];
    const float* out_b = (const float*)d_in[22];
    float* outp = (float*)d_out;

    __half *papt, *pCph, *pBGh, *pkp2h, *pvp2h;
    float *pTt, *pCc, *pAt, *pPart, *pWt, *pbt, *pWc, *pWB, *pcb, *pkpb, *pvpb, *pzero;
    cudaGetSymbolAddress((void**)&papt, s_apt);
    cudaGetSymbolAddress((void**)&pCph, s_Cph);
    cudaGetSymbolAddress((void**)&pBGh, s_BGh);
    cudaGetSymbolAddress((void**)&pkp2h, s_kp2h);
    cudaGetSymbolAddress((void**)&pvp2h, s_vp2h);
    cudaGetSymbolAddress((void**)&pTt, s_Tt);
    cudaGetSymbolAddress((void**)&pCc, s_Cc);
    cudaGetSymbolAddress((void**)&pAt, s_At);
    cudaGetSymbolAddress((void**)&pPart, s_Part);
    cudaGetSymbolAddress((void**)&pWt, s_Wt);
    cudaGetSymbolAddress((void**)&pbt, s_bt);
    cudaGetSymbolAddress((void**)&pWc, s_Wc);
    cudaGetSymbolAddress((void**)&pWB, s_WB);
    cudaGetSymbolAddress((void**)&pcb, s_cb);
    cudaGetSymbolAddress((void**)&pkpb, s_kpb);
    cudaGetSymbolAddress((void**)&pvpb, s_vpb);
    cudaGetSymbolAddress((void**)&pzero, s_zero);

    cudaFuncSetAttribute(fused_pair,
                         cudaFuncAttributeMaxDynamicSharedMemorySize, FUSED_SMEM);

    pack_kernel<<<3335, 256>>>(kt_w, vt_w, Wq_w, Wq_b, kc_w, vc_w,
                               kp2_w, vp2_w, g_w, kp2_b, vp2_b);
    cb_kernel<<<1, 256>>>(g_w, g_b, kp2_b, vp2_b);
    phiproj_kernel<<<NTT_ + NCC_, 256>>>(phi_t, phi_c, kp1_w, kp1_b, vp1_w, vp1_b);

    {   // weight-prep: G1|G2 -> s_BGh cols 256:512 (half), Wat -> s_Wt, Wac -> s_Wc
        GemmP p = mk(); p.A=g_w; p.lda=768; p.B=pWB; p.ldb=512; p.K=512;
        p.hC=pBGh; p.O2=pWt + 768*256; p.O3=pWc + 512*256;
        gemm_nt<EP_WPREP><<<dim3(12,4), 256>>>(p);
    }
    {   // combined: [kt|vt|Q|At] = R_t @ s_Wt^T + s_bt (64 blocks, gx=16)
        //           [kc|vc|Ac]   = R_ctx @ s_Wc^T      (192 blocks, gx=12)
        GemmP pa = mk(); pa.A=R_t; pa.lda=256; pa.B=pWt; pa.ldb=256; pa.K=256;
        pa.C=pTt; pa.ldc=1024; pa.vec=pbt;
        GemmP pb = mk(); pb.A=R_ctx; pb.lda=256; pb.B=pWc; pb.ldb=256; pb.K=256;
        pb.C=pCc; pb.ldc=768; pb.vec=pzero;
        gemm64_dual<<<64 + 192, 256>>>(pa, 64, 16, pb, 12);
    }

    // --- fused pair kernel (H build + K/V/gate + partial attention) ---
    {
        FusedP fp;
        fp.apt = papt; fp.Cph = pCph;
        fp.kp2h = pkp2h; fp.vp2h = pvp2h; fp.BGh = pBGh;
        fp.Part = pPart;
        fp.Tt = pTt; fp.Cc = pCc; fp.kpb = pkpb; fp.vpb = pvpb; fp.cb = pcb;
        fused_pair<<<NP_/128, 512, FUSED_SMEM>>>(fp);
    }

    // --- reduce partials -> ctx (s_At) ---
    attn_reduce<<<NTT_, 256>>>(pPart, pAt);

    // --- output projection ---
    {
        GemmP p = mk(); p.A=pAt; p.lda=256; p.B=out_w; p.ldb=256; p.K=256;
        p.C=outp; p.ldc=256; p.vec=out_b;
        gemm_nt<EP_BIAS><<<dim3(4,4), 256>>>(p);
    }
}

// round 13
// speedup vs baseline: 1.9478x; 1.0507x over previous
#include <cuda_runtime.h>
#include <cuda_fp16.h>
#include <math.h>
#include <stdint.h>

// ---------------------------------------------------------------------------
// TargetAwareContextAttention — fused pair kernel (16 warps): ldmatrix frags,
// group-scoped barriers, in-kernel H build + flash partial attention.
// B=2, Nt=128, Nc=512, D=256, DPHI=16, HID=128, H=8, dk=32; NP=131072 pairs.
// ---------------------------------------------------------------------------

#define D_    256
#define DPHI_ 16
#define HID_  128
#define B_    2
#define NT_   128
#define NC_   512
#define NTT_  (B_*NT_)    // 256
#define NCC_  (B_*NC_)    // 1024
#define NP_   (NTT_*NC_)  // 131072

// ------------------------------- scratch -----------------------------------
__device__ __half s_apt[NTT_*256];      // W1*phi_t + b (k|v halves)
__device__ __half s_Cph[NCC_*256];      // W1*phi_c (k|v halves)
__device__ __half s_BGh [256*512];      // gate B rows: [gw3 | G1|G2]
__device__ __half s_kp2h[256*128];
__device__ __half s_vp2h[256*128];
__device__ float s_Tt [NTT_*1024];      // [kt|vt|Q|At] per target row
__device__ float s_Cc [NCC_*768];       // [kc|vc|Ac] per ctx row
__device__ float s_At [NTT_*256];       // ctx (attention output)
__device__ float s_Part[256*4*8*36];    // per-(tg,chunk,head): o[32], m, l
__device__ float s_Wt [1024*256];       // [kt_w; vt_w; Wq_w; Wat]
__device__ float s_bt [1024];
__device__ float s_Wc [768*256];        // [kc_w; vc_w; Wac]
__device__ float s_WB [768*512];        // weight-prep B
__device__ float s_cb [256];
__device__ float s_kpb[256];
__device__ float s_vpb[256];
__device__ float s_zero[1024];          // stays zero

// --------------------------- helpers ----------------------------------------
__device__ __forceinline__ void mma16(float* c, const uint32_t* a, const uint32_t* b) {
    asm volatile(
        "mma.sync.aligned.m16n8k16.row.col.f32.f16.f16.f32 "
        "{%0,%1,%2,%3}, {%4,%5,%6,%7}, {%8,%9}, {%0,%1,%2,%3};"
        : "+f"(c[0]), "+f"(c[1]), "+f"(c[2]), "+f"(c[3])
        : "r"(a[0]), "r"(a[1]), "r"(a[2]), "r"(a[3]), "r"(b[0]), "r"(b[1]));
}
__device__ __forceinline__ void ldsm4(uint32_t& r0, uint32_t& r1,
                                      uint32_t& r2, uint32_t& r3, uint32_t addr) {
    asm volatile("ldmatrix.sync.aligned.m8n8.x4.shared.b16 {%0,%1,%2,%3}, [%4];"
        : "=r"(r0), "=r"(r1), "=r"(r2), "=r"(r3) : "r"(addr));
}
__device__ __forceinline__ uint32_t habsdiff2(uint32_t a, uint32_t b) {
    __half2 ha = *reinterpret_cast<__half2*>(&a);
    __half2 hb = *reinterpret_cast<__half2*>(&b);
    __half2 r = __habs2(__hsub2(ha, hb));
    return *reinterpret_cast<uint32_t*>(&r);
}
__device__ __forceinline__ uint32_t relusub2(uint32_t a, uint32_t c) {
    __half2 ha = *reinterpret_cast<__half2*>(&a);
    __half2 hc = *reinterpret_cast<__half2*>(&c);
    __half2 r = __hmax2(__hsub2(ha, hc), __float2half2_rn(0.f));
    return *reinterpret_cast<uint32_t*>(&r);
}

// ---------------------- fused pair kernel -----------------------------------
#define TP 132                                  // tile pitch (u32), 256-half rows
#define BP 20                                   // B staging pitch (u32)
#define SP 132                                  // score pitch (floats)
#define FUSED_SMEM ((3*128*TP + 256*BP) * 4)    // 223232 B

struct FusedP {
    const __half *apt, *Cph, *kp2h, *vp2h, *BGh;
    float* Part;
    const float *Tt, *Cc, *kpb, *vpb, *cb;
};

__global__ void __launch_bounds__(512) fused_pair(FusedP p) {
    extern __shared__ __align__(16) uint32_t sm[];
    uint32_t* Ht = sm;
    uint32_t* Kt = sm + 128*TP;
    uint32_t* Vt = sm + 2*128*TP;
    uint32_t* Bs = sm + 3*128*TP;   // 256 rows x BP; group-partitioned

    uint32_t smBase;
    asm("{ .reg .u64 t; cvta.to.shared.u64 t, %1; cvt.u32.u64 %0, t; }"
        : "=r"(smBase) : "l"(sm));

    const int tid   = threadIdx.x;
    const int lane  = tid & 31;
    const int wid   = tid >> 5;     // 0..15
    const int warpM = wid & 3;      // 32-row slice
    const int warpN = wid >> 2;     // 0..3 -> 64-col slice of 256
    const int g     = lane >> 2;
    const int t4    = lane & 3;
    const int tg    = blockIdx.x >> 2;
    const int chunk = blockIdx.x & 3;
    const int cx0   = (tg >> 7) * 512 + chunk * 128;

    // ldmatrix per-thread base addresses (bytes)
    uint32_t aAB[2], bAB[4];
#pragma unroll
    for (int mf = 0; mf < 2; mf++)
        aAB[mf] = smBase + (((warpM*32 + mf*16 + (lane&7) + ((lane>>3)&1)*8)*TP)
                            + ((lane>>4)&1)*4) * 4;
#pragma unroll
    for (int np = 0; np < 4; np++)
        bAB[np] = smBase + (((3*128*TP) +
                   (warpN*64 + np*16 + ((lane>>4)&1)*8 + (lane&7))*BP)
                            + ((lane>>3)&1)*4) * 4;

    // group barrier: 4 warps sharing warpN (contiguous 128 threads)
    auto gbar = [&]() {
        asm volatile("bar.sync %0, %1;" :: "r"(warpN + 1), "r"(128) : "memory");
    };

    // ---- build H tile: Ht[r][h] = relu(apt[tg][h] - Cph[cx0+r][h]) ----
    if (tid < 128) Bs[tid] = ((const uint32_t*)p.apt)[tg*128 + tid];
    __syncthreads();
    for (int i = tid; i < 128*32; i += 512) {
        const int row = i >> 5, c4 = i & 31;
        uint4 c = *(const uint4*)(p.Cph + (size_t)(cx0 + row)*256 + c4*8);
        uint4 o;
        o.x = relusub2(Bs[c4*4+0], c.x);
        o.y = relusub2(Bs[c4*4+1], c.y);
        o.z = relusub2(Bs[c4*4+2], c.z);
        o.w = relusub2(Bs[c4*4+3], c.w);
        *(uint4*)(Ht + row*TP + c4*4) = o;
    }
    __syncthreads();

    float acc[2][8][4];
    uint4 rb[2];

    auto zeroAcc = [&]() {
#pragma unroll
        for (int mf = 0; mf < 2; mf++)
#pragma unroll
            for (int nf = 0; nf < 8; nf++)
#pragma unroll
                for (int q = 0; q < 4; q++) acc[mf][nf][q] = 0.f;
    };
    // group-local B staging: group warpN handles B rows [warpN*64, +64)
    auto loadB = [&](const __half* Bp, int ldb, int kc) {
        const int lt = tid & 127;
#pragma unroll
        for (int q = 0; q < 2; q++) {
            const int idx = q*128 + lt;            // 0..255
            const int row = warpN*64 + (idx >> 2), f4 = idx & 3;
            rb[q] = *(const uint4*)(Bp + (size_t)row*ldb + kc + f4*8);
        }
    };
    auto storeB = [&]() {
        const int lt = tid & 127;
#pragma unroll
        for (int q = 0; q < 2; q++) {
            const int idx = q*128 + lt;
            const int row = warpN*64 + (idx >> 2), f4 = idx & 3;
            *(uint4*)(Bs + row*BP + f4*4) = rb[q];
        }
    };
    // plain-H chunk via ldmatrix (A from Ht at u32 col aU)
    auto computeL = [&](int aU) {
#pragma unroll
        for (int kf = 0; kf < 2; kf++) {
            uint32_t af[2][4], bf[8][2];
#pragma unroll
            for (int mf = 0; mf < 2; mf++)
                ldsm4(af[mf][0], af[mf][1], af[mf][2], af[mf][3],
                      aAB[mf] + (aU + kf*8)*4);
#pragma unroll
            for (int np = 0; np < 4; np++)
                ldsm4(bf[2*np][0], bf[2*np][1], bf[2*np+1][0], bf[2*np+1][1],
                      bAB[np] + (kf*8)*4);
#pragma unroll
            for (int mf = 0; mf < 2; mf++)
#pragma unroll
                for (int nf = 0; nf < 8; nf++)
                    mma16(acc[mf][nf], af[mf], bf[nf]);
        }
    };
    // |K-V| chunk (scalar loads + habs)
    auto computeAbs = [&](int aU) {
        const uint32_t* b_s = Bs + (warpN*64)*BP;
#pragma unroll
        for (int kf = 0; kf < 2; kf++) {
            const int kb = kf*8 + t4;
            uint32_t af[2][4];
#pragma unroll
            for (int mf = 0; mf < 2; mf++) {
                const int ro = (warpM*32 + mf*16 + g)*TP + aU + kb;
                af[mf][0] = habsdiff2(Kt[ro],          Vt[ro]);
                af[mf][1] = habsdiff2(Kt[ro + 8*TP],   Vt[ro + 8*TP]);
                af[mf][2] = habsdiff2(Kt[ro + 4],      Vt[ro + 4]);
                af[mf][3] = habsdiff2(Kt[ro + 8*TP+4], Vt[ro + 8*TP+4]);
            }
            uint32_t bf[8][2];
#pragma unroll
            for (int nf = 0; nf < 8; nf++) {
                const uint32_t* bp = b_s + (nf*8 + g)*BP + kb;
                bf[nf][0] = bp[0]; bf[nf][1] = bp[4];
            }
#pragma unroll
            for (int mf = 0; mf < 2; mf++)
#pragma unroll
                for (int nf = 0; nf < 8; nf++)
                    mma16(acc[mf][nf], af[mf], bf[nf]);
        }
    };

    // ---- K and V phases: outputs to smem tiles ----
    for (int sel = 0; sel < 2; sel++) {
        const __half* Bp = sel ? p.vp2h : p.kp2h;
        const int   aBase = sel ? 64 : 0;
        uint32_t*   Ot    = sel ? Vt : Kt;
        const float* bias = sel ? p.vpb : p.kpb;
        const int   poff  = sel ? 256 : 0;
        zeroAcc();
        loadB(Bp, HID_, 0);
#pragma unroll
        for (int c = 0; c < 4; c++) {
            gbar();
            storeB();
            gbar();
            if (c < 3) loadB(Bp, HID_, (c+1)*32);
            computeL(aBase + c*16);
        }
#pragma unroll
        for (int mf = 0; mf < 2; mf++)
#pragma unroll
        for (int hf = 0; hf < 2; hf++) {
            const int row  = warpM*32 + mf*16 + g + hf*8;
            const int cx = cx0 + row;
            const float* r1 = p.Tt + (size_t)tg*1024 + poff;
            const float* r2 = p.Cc + (size_t)cx*768  + poff;
#pragma unroll
            for (int nf = 0; nf < 8; nf++) {
                const int col = warpN*64 + nf*8 + t4*2;
                float2 a = __ldg((const float2*)(r1 + col));
                float2 b = __ldg((const float2*)(r2 + col));
                float2 v = __ldg((const float2*)(bias + col));
                __half2 h = __floats2half2_rn(
                    acc[mf][nf][hf*2+0] + a.x + b.x + v.x,
                    acc[mf][nf][hf*2+1] + a.y + b.y + v.y);
                Ot[row*TP + (col >> 1)] = *reinterpret_cast<uint32_t*>(&h);
            }
        }
    }

    __syncthreads();   // K/V tiles visible cross-group for gate A operand

    // ---- gate phase: K=512 (|K-V| chunks 0-7, H chunks 8-15) ----
    zeroAcc();
    loadB(p.BGh, 512, 0);
#pragma unroll
    for (int c = 0; c < 16; c++) {
        gbar();
        storeB();
        gbar();
        if (c < 15) loadB(p.BGh, 512, (c+1)*32);
        if (c < 8) computeAbs(c*16);
        else       computeL((c-8)*16);
    }
    // epilogue: g=sigmoid(pre); Kg,Vg overwrite Kt,Vt in smem.
#pragma unroll
    for (int mf = 0; mf < 2; mf++)
#pragma unroll
    for (int hf = 0; hf < 2; hf++) {
        const int row  = warpM*32 + mf*16 + g + hf*8;
        const int cx = cx0 + row;
        const float* r1 = p.Tt + (size_t)tg*1024 + 768;
        const float* r2 = p.Cc + (size_t)cx*768  + 512;
#pragma unroll
        for (int nf = 0; nf < 8; nf++) {
            const int col = warpN*64 + nf*8 + t4*2;
            float2 at = __ldg((const float2*)(r1 + col));
            float2 ac = __ldg((const float2*)(r2 + col));
            float2 cb = __ldg((const float2*)(p.cb + col));
            uint32_t ku = Kt[row*TP + (col >> 1)];
            uint32_t vu = Vt[row*TP + (col >> 1)];
            float2 kk = __half22float2(*reinterpret_cast<__half2*>(&ku));
            float2 vv = __half22float2(*reinterpret_cast<__half2*>(&vu));
            float g0 = 1.f / (1.f + __expf(-(acc[mf][nf][hf*2+0] + at.x + ac.x + cb.x)));
            float g1 = 1.f / (1.f + __expf(-(acc[mf][nf][hf*2+1] + at.y + ac.y + cb.y)));
            __half2 hk = __floats2half2_rn(kk.x*g0, kk.y*g1);
            __half2 hv = __floats2half2_rn(vv.x*g0, vv.y*g1);
            Kt[row*TP + (col >> 1)] = *reinterpret_cast<uint32_t*>(&hk);
            Vt[row*TP + (col >> 1)] = *reinterpret_cast<uint32_t*>(&hv);
        }
    }
    __syncthreads();

    // ---- in-CTA partial attention over this CTA's 128 ctx rows ----
    // fs layout: scores [h*SP+r] (0..1055), Q 1056..1311, m 1320..1327,
    //            l 1328..1335, o-partials 1408..2431
    float* fs = (float*)Bs;
    for (int i = tid; i < 256; i += 512)
        fs[1056 + i] = p.Tt[(size_t)tg*1024 + 512 + i];
    __syncthreads();

    const float scale = 0.17677669529663687f;  // 1/sqrt(32)
#pragma unroll
    for (int i = 0; i < 2; i++) {
        const int idx = i*512 + tid;            // 0..1023
        const int r = idx >> 3, h = idx & 7;
        const uint32_t* kr = Kt + r*TP + h*16;
        const float* qh = fs + 1056 + h*32;
        float s = 0.f;
#pragma unroll
        for (int j = 0; j < 16; j++) {
            uint32_t u = kr[j];
            float2 kv = __half22float2(*reinterpret_cast<__half2*>(&u));
            s += qh[2*j]*kv.x + qh[2*j+1]*kv.y;
        }
        fs[h*SP + r] = s * scale;
    }
    __syncthreads();
    if (wid < 8) {   // per-head max via one warp each
        const int h = wid;
        float m = -1e30f;
#pragma unroll
        for (int j = 0; j < 4; j++) m = fmaxf(m, fs[h*SP + lane + j*32]);
#pragma unroll
        for (int o = 16; o; o >>= 1) m = fmaxf(m, __shfl_xor_sync(0xffffffffu, m, o));
        if (lane == 0) fs[1320 + h] = m;
    }
    __syncthreads();
#pragma unroll
    for (int i = 0; i < 2; i++) {
        const int idx = i*512 + tid;
        const int r = idx >> 3, h = idx & 7;
        fs[h*SP + r] = __expf(fs[h*SP + r] - fs[1320 + h]);
    }
    __syncthreads();
    if (wid < 8) {   // per-head sum
        const int h = wid;
        float l = 0.f;
#pragma unroll
        for (int j = 0; j < 4; j++) l += fs[h*SP + lane + j*32];
#pragma unroll
        for (int o = 16; o; o >>= 1) l += __shfl_xor_sync(0xffffffffu, l, o);
        if (lane == 0) fs[1328 + h] = l;
    }
    // o partials: 512 threads = h(8) x dp(16) x part(4), each 32 rows
    {
        const int h = tid >> 6, rem = tid & 63, dp = rem >> 2, part = rem & 3;
        const uint32_t* vr = Vt + h*16 + dp;
        const float* pr = fs + h*SP;
        float o0 = 0.f, o1 = 0.f;
        for (int r = part*32; r < part*32 + 32; r++) {
            uint32_t u = vr[r*TP];
            float2 vv = __half22float2(*reinterpret_cast<__half2*>(&u));
            o0 = fmaf(pr[r], vv.x, o0);
            o1 = fmaf(pr[r], vv.y, o1);
        }
        fs[1408 + ((h*16+dp)*4 + part)*2 + 0] = o0;
        fs[1408 + ((h*16+dp)*4 + part)*2 + 1] = o1;
    }
    __syncthreads();

    float* pp = p.Part + ((size_t)(tg*4 + chunk) * 8) * 36;
    if (tid < 8) {
        pp[tid*36 + 32] = fs[1320 + tid];
        pp[tid*36 + 33] = fs[1328 + tid];
    }
    if (tid < 256) {
        const int h = tid >> 5, rem = tid & 31, dp = rem >> 1, v = rem & 1;
        float s = 0.f;
#pragma unroll
        for (int part = 0; part < 4; part++)
            s += fs[1408 + ((h*16+dp)*4 + part)*2 + v];
        pp[h*36 + dp*2 + v] = s;
    }
}

// ---------------------- attention partial reduce -----------------------------
__global__ void __launch_bounds__(256) attn_reduce(const float* Part, float* ctxOut) {
    const int tg = blockIdx.x;
    const int h = threadIdx.x >> 5, d = threadIdx.x & 31;
    const float* pp = Part + ((size_t)(tg*4) * 8 + h) * 36;   // chunk stride 288
    float m0 = pp[32], m1 = pp[288+32], m2 = pp[576+32], m3 = pp[864+32];
    float ms = fmaxf(fmaxf(m0, m1), fmaxf(m2, m3));
    float w0 = __expf(m0-ms), w1 = __expf(m1-ms), w2 = __expf(m2-ms), w3 = __expf(m3-ms);
    float l = w0*pp[33] + w1*pp[288+33] + w2*pp[576+33] + w3*pp[864+33];
    float o = w0*pp[d]  + w1*pp[288+d]  + w2*pp[576+d]  + w3*pp[864+d];
    ctxOut[tg*256 + h*32 + d] = o / l;
}

// ------------------- fp32 FFMA2 GEMM (prologue-sized) -----------------------
__device__ __forceinline__ unsigned long long pk2(float lo, float hi) {
    unsigned long long r;
    asm("mov.b64 %0, {%1, %2};" : "=l"(r) : "f"(lo), "f"(hi));
    return r;
}
__device__ __forceinline__ void upk2(unsigned long long v, float& lo, float& hi) {
    asm("mov.b64 {%0, %1}, %2;" : "=f"(lo), "=f"(hi) : "l"(v));
}
__device__ __forceinline__ void ffma2(unsigned long long& d,
                                      unsigned long long a, unsigned long long b) {
    asm("fma.rn.f32x2 %0, %1, %2, %0;" : "+l"(d) : "l"(a), "l"(b));
}

struct GemmP {
    const float* A; int lda; int aoff;
    const float* B; int ldb; int boff;
    int K;
    float* C; int ldc; int coff;
    const float* vec;
    __half* hC; float* O2; float* O3;
};

enum { EP_NONE = 0, EP_BIAS = 1, EP_WPREP = 4 };

// 64x64 tile, TM=TN=4, 256 threads, EP_BIAS body
__device__ __forceinline__ void gemm64_body(const GemmP& p, int mBase, int nBase) {
    constexpr int BM = 64, BN = 64, BK = 16, TM = 4, TN = 4, NTX = 16;
    __shared__ __align__(16) float As[2][BK*BM];
    __shared__ __align__(16) float Bs[2][BK*BN];

    const int tid = threadIdx.x;
    const int tx = tid % NTX;
    const int ty = tid / NTX;
    const int lrow = tid >> 2;
    const int lk   = (tid & 3) << 2;

    const float* Abase = p.A + (size_t)(mBase + lrow) * p.lda + p.aoff + lk;
    const float* Bbase = p.B + (size_t)(nBase + lrow) * p.ldb + p.boff + lk;

    unsigned long long acc2[TM/2][TN];
#pragma unroll
    for (int i = 0; i < TM/2; i++)
#pragma unroll
        for (int j = 0; j < TN; j++) acc2[i][j] = 0ull;

    const int nTiles = p.K / BK;
    float4 ra, rbv;
    ra  = *(const float4*)(Abase);
    rbv = *(const float4*)(Bbase);
    {
        int m = lrow;
        As[0][(lk+0)*BM+m]=ra.x; As[0][(lk+1)*BM+m]=ra.y;
        As[0][(lk+2)*BM+m]=ra.z; As[0][(lk+3)*BM+m]=ra.w;
        Bs[0][(lk+0)*BN+m]=rbv.x; Bs[0][(lk+1)*BN+m]=rbv.y;
        Bs[0][(lk+2)*BN+m]=rbv.z; Bs[0][(lk+3)*BN+m]=rbv.w;
    }
    __syncthreads();

    for (int t = 0; t < nTiles; t++) {
        const int cur = t & 1;
        const bool more = (t + 1) < nTiles;
        if (more) {
            const int k0 = (t + 1) * BK;
            ra  = *(const float4*)(Abase + k0);
            rbv = *(const float4*)(Bbase + k0);
        }
#pragma unroll
        for (int k = 0; k < BK; k++) {
            unsigned long long a2[TM/2], b2[TN];
            ulonglong2 va = *(const ulonglong2*)&As[cur][k*BM + ty*TM];
            a2[0] = va.x; a2[1] = va.y;
            float4 vb = *(const float4*)&Bs[cur][k*BN + tx*TN];
            b2[0] = pk2(vb.x, vb.x); b2[1] = pk2(vb.y, vb.y);
            b2[2] = pk2(vb.z, vb.z); b2[3] = pk2(vb.w, vb.w);
#pragma unroll
            for (int i = 0; i < TM/2; i++)
#pragma unroll
                for (int j = 0; j < TN; j++) ffma2(acc2[i][j], a2[i], b2[j]);
        }
        if (more) {
            const int nxt = cur ^ 1;
            __syncthreads();
            int m = lrow;
            As[nxt][(lk+0)*BM+m]=ra.x; As[nxt][(lk+1)*BM+m]=ra.y;
            As[nxt][(lk+2)*BM+m]=ra.z; As[nxt][(lk+3)*BM+m]=ra.w;
            Bs[nxt][(lk+0)*BN+m]=rbv.x; Bs[nxt][(lk+1)*BN+m]=rbv.y;
            Bs[nxt][(lk+2)*BN+m]=rbv.z; Bs[nxt][(lk+3)*BN+m]=rbv.w;
            __syncthreads();
        }
    }

    float accf[TM][TN];
#pragma unroll
    for (int i = 0; i < TM/2; i++)
#pragma unroll
        for (int j = 0; j < TN; j++) upk2(acc2[i][j], accf[2*i][j], accf[2*i+1][j]);

#pragma unroll
    for (int i = 0; i < TM; i++) {
        const int gm  = mBase + ty*TM + i;
        const int gn0 = nBase + tx*TN;
        float* co = p.C + (size_t)gm * p.ldc + p.coff + gn0;
#pragma unroll
        for (int j = 0; j < TN; j++)
            co[j] = accf[i][j] + p.vec[gn0 + j];
    }
}

__global__ void __launch_bounds__(256, 1) gemm64_dual(GemmP pa, int nba, int gxa,
                                                      GemmP pb, int gxb) {
    const int bid = blockIdx.x;
    if (bid < nba) gemm64_body(pa, (bid / gxa) * 64, (bid % gxa) * 64);
    else {
        const int b2 = bid - nba;
        gemm64_body(pb, (b2 / gxb) * 64, (b2 % gxb) * 64);
    }
}

template<int EPI>
__global__ void __launch_bounds__(256, 1) gemm_nt(GemmP p) {
    constexpr int BM = 64, BN = 64, BK = 16, TM = 4, TN = 4, NTX = 16;
    __shared__ __align__(16) float As[2][BK*BM];
    __shared__ __align__(16) float Bs[2][BK*BN];

    const int tid   = threadIdx.x;
    const int mBase = blockIdx.y * BM;
    const int nBase = blockIdx.x * BN;
    const int tx = tid % NTX;
    const int ty = tid / NTX;
    const int lrow = tid >> 2;
    const int lk   = (tid & 3) << 2;

    const float* Abase = p.A + (size_t)(mBase + lrow) * p.lda + p.aoff + lk;
    const float* Bbase = p.B + (size_t)(nBase + lrow) * p.ldb + p.boff + lk;

    unsigned long long acc2[TM/2][TN];
#pragma unroll
    for (int i = 0; i < TM/2; i++)
#pragma unroll
        for (int j = 0; j < TN; j++) acc2[i][j] = 0ull;

    const int nTiles = p.K / BK;
    float4 ra, rbv;
    ra  = *(const float4*)(Abase);
    rbv = *(const float4*)(Bbase);
    {
        int m = lrow;
        As[0][(lk+0)*BM+m]=ra.x; As[0][(lk+1)*BM+m]=ra.y;
        As[0][(lk+2)*BM+m]=ra.z; As[0][(lk+3)*BM+m]=ra.w;
        Bs[0][(lk+0)*BN+m]=rbv.x; Bs[0][(lk+1)*BN+m]=rbv.y;
        Bs[0][(lk+2)*BN+m]=rbv.z; Bs[0][(lk+3)*BN+m]=rbv.w;
    }
    __syncthreads();

    for (int t = 0; t < nTiles; t++) {
        const int cur = t & 1;
        const bool more = (t + 1) < nTiles;
        if (more) {
            const int k0 = (t + 1) * BK;
            ra  = *(const float4*)(Abase + k0);
            rbv = *(const float4*)(Bbase + k0);
        }
#pragma unroll
        for (int k = 0; k < BK; k++) {
            unsigned long long a2[TM/2], b2[TN];
            ulonglong2 va = *(const ulonglong2*)&As[cur][k*BM + ty*TM];
            a2[0] = va.x; a2[1] = va.y;
            float4 vb = *(const float4*)&Bs[cur][k*BN + tx*TN];
            b2[0] = pk2(vb.x, vb.x); b2[1] = pk2(vb.y, vb.y);
            b2[2] = pk2(vb.z, vb.z); b2[3] = pk2(vb.w, vb.w);
#pragma unroll
            for (int i = 0; i < TM/2; i++)
#pragma unroll
                for (int j = 0; j < TN; j++) ffma2(acc2[i][j], a2[i], b2[j]);
        }
        if (more) {
            const int nxt = cur ^ 1;
            __syncthreads();
            int m = lrow;
            As[nxt][(lk+0)*BM+m]=ra.x; As[nxt][(lk+1)*BM+m]=ra.y;
            As[nxt][(lk+2)*BM+m]=ra.z; As[nxt][(lk+3)*BM+m]=ra.w;
            Bs[nxt][(lk+0)*BN+m]=rbv.x; Bs[nxt][(lk+1)*BN+m]=rbv.y;
            Bs[nxt][(lk+2)*BN+m]=rbv.z; Bs[nxt][(lk+3)*BN+m]=rbv.w;
            __syncthreads();
        }
    }

    float accf[TM][TN];
#pragma unroll
    for (int i = 0; i < TM/2; i++)
#pragma unroll
        for (int j = 0; j < TN; j++) upk2(acc2[i][j], accf[2*i][j], accf[2*i+1][j]);

#pragma unroll
    for (int i = 0; i < TM; i++) {
        const int gm  = mBase + ty*TM + i;
        const int gn0 = nBase + tx*TN;
        if (EPI == EP_WPREP) {
#pragma unroll
            for (int j = 0; j < TN; j++) {
                const int d = gn0 + j;
                const float v = accf[i][j];
                if (d < 256)      p.hC[(size_t)gm*512 + 256 + d] = __float2half(v);
                else if (d < 512) p.O2[(size_t)gm*256 + (d-256)] = v;
                else              p.O3[(size_t)gm*256 + (d-512)] = v;
            }
        } else {
            float* co = p.C + (size_t)gm * p.ldc + p.coff + gn0;
#pragma unroll
            for (int j = 0; j < TN; j++) {
                float v = accf[i][j];
                if (EPI == EP_BIAS) v += p.vec[gn0 + j];
                co[j] = v;
            }
        }
    }
}

// --------------------- small helper kernels ---------------------------------
__global__ void pack_kernel(const float* kt_w, const float* vt_w,
                            const float* Wq_w, const float* Wq_b,
                            const float* kc_w, const float* vc_w,
                            const float* kp2_w, const float* vp2_w,
                            const float* g_w, const float* kp2_b,
                            const float* vp2_b) {
    int i = blockIdx.x * 256 + threadIdx.x;
    if (i < 196608) {
        s_Wt[i] = (i < 65536) ? kt_w[i]
                : (i < 131072) ? vt_w[i - 65536] : Wq_w[i - 131072];
    } else if (i < 327680) {
        int j = i - 196608;
        s_Wc[j] = (j < 65536) ? kc_w[j] : vc_w[j - 65536];
    } else if (i < 720896) {
        int j = i - 327680;
        int d = j >> 9, k = j & 511;
        float v;
        if (d < 128)       v = (k < 256) ? kp2_w[k*128 + d] : 0.f;
        else if (d < 256)  v = (k >= 256) ? vp2_w[(k-256)*128 + (d-128)] : 0.f;
        else if (d < 512)  v = (k < 256) ? kt_w[k*256 + (d-256)] : vt_w[(k-256)*256 + (d-256)];
        else               v = (k < 256) ? kc_w[k*256 + (d-512)] : vc_w[(k-256)*256 + (d-512)];
        s_WB[j] = v;
    } else if (i < 786432) {
        int j = i - 720896;
        int n = j >> 8, c = j & 255;
        s_BGh[n*512 + c] = __float2half(g_w[n*768 + 512 + c]);
    } else if (i < 819200) {
        int j = i - 786432;
        s_kp2h[j] = __float2half(kp2_w[j]);
    } else if (i < 851968) {
        int j = i - 819200;
        s_vp2h[j] = __float2half(vp2_w[j]);
    } else if (i < 852992) {
        int j = i - 851968;
        s_bt[j] = (j >= 512 && j < 768) ? Wq_b[j - 512] : 0.f;
    } else if (i < 853504) {
        int j = i - 852992;
        if (j < 256) s_kpb[j] = kp2_b[j];
        else         s_vpb[j - 256] = vp2_b[j - 256];
    }
}

__global__ void cb_kernel(const float* g_w, const float* g_b,
                          const float* kp2_b, const float* vp2_b) {
    int n = threadIdx.x;
    float s = g_b[n];
    const float* r = g_w + (size_t)n * 768;
    for (int d = 0; d < 256; d++)
        s += r[d] * kp2_b[d] + r[256 + d] * vp2_b[d];
    s_cb[n] = s;
}

// phi projections: apt = W1*phi_t + b (targets), Cph = W1*phi_c (ctx)
__global__ void __launch_bounds__(256) phiproj_kernel(
    const float* phi_t, const float* phi_c,
    const float* kp1_w, const float* kp1_b,
    const float* vp1_w, const float* vp1_b) {
    const int rowId = blockIdx.x;           // 0..1279
    const int h = threadIdx.x;              // 0..255
    const bool isT = rowId < NTT_;
    const float* src = isT ? (phi_t + rowId*DPHI_)
                           : (phi_c + (size_t)(rowId - NTT_)*DPHI_);
    __shared__ float ph[DPHI_];
    if (h < DPHI_) ph[h] = src[h];
    __syncthreads();
    const float* W = (h < 128) ? (kp1_w + h*DPHI_) : (vp1_w + (h-128)*DPHI_);
    float s = 0.f;
#pragma unroll
    for (int j = 0; j < DPHI_; j++) s = fmaf(W[j], ph[j], s);
    if (isT) s += (h < 128) ? kp1_b[h] : vp1_b[h-128];
    __half* dst = isT ? (s_apt + (size_t)rowId*256)
                      : (s_Cph + (size_t)(rowId - NTT_)*256);
    dst[h] = __float2half(s);
}

// ------------------------------- launch -------------------------------------
static inline GemmP mk() { GemmP p; p.A=0;p.lda=0;p.aoff=0;p.B=0;p.ldb=0;
    p.boff=0;p.K=0;p.C=0;p.ldc=0;p.coff=0;p.vec=0;p.hC=0;p.O2=0;p.O3=0; return p; }

extern "C" void kernel_launch(void* const* d_in, const int* in_sizes, int n_in,
                              void* d_out, int out_size) {
    const float* R_t   = (const float*)d_in[0];
    const float* R_ctx = (const float*)d_in[1];
    const float* phi_t = (const float*)d_in[2];
    const float* phi_c = (const float*)d_in[3];
    const float* Wq_w  = (const float*)d_in[5];
    const float* Wq_b  = (const float*)d_in[6];
    const float* kc_w  = (const float*)d_in[7];
    const float* kt_w  = (const float*)d_in[8];
    const float* kp1_w = (const float*)d_in[9];
    const float* kp1_b = (const float*)d_in[10];
    const float* kp2_w = (const float*)d_in[11];
    const float* kp2_b = (const float*)d_in[12];
    const float* vc_w  = (const float*)d_in[13];
    const float* vt_w  = (const float*)d_in[14];
    const float* vp1_w = (const float*)d_in[15];
    const float* vp1_b = (const float*)d_in[16];
    const float* vp2_w = (const float*)d_in[17];
    const float* vp2_b = (const float*)d_in[18];
    const float* g_w   = (const float*)d_in[19];
    const float* g_b   = (const float*)d_in[20];
    const float* out_w = (const float*)d_in[21];
    const float* out_b = (const float*)d_in[22];
    float* outp = (float*)d_out;

    __half *papt, *pCph, *pBGh, *pkp2h, *pvp2h;
    float *pTt, *pCc, *pAt, *pPart, *pWt, *pbt, *pWc, *pWB, *pcb, *pkpb, *pvpb, *pzero;
    cudaGetSymbolAddress((void**)&papt, s_apt);
    cudaGetSymbolAddress((void**)&pCph, s_Cph);
    cudaGetSymbolAddress((void**)&pBGh, s_BGh);
    cudaGetSymbolAddress((void**)&pkp2h, s_kp2h);
    cudaGetSymbolAddress((void**)&pvp2h, s_vp2h);
    cudaGetSymbolAddress((void**)&pTt, s_Tt);
    cudaGetSymbolAddress((void**)&pCc, s_Cc);
    cudaGetSymbolAddress((void**)&pAt, s_At);
    cudaGetSymbolAddress((void**)&pPart, s_Part);
    cudaGetSymbolAddress((void**)&pWt, s_Wt);
    cudaGetSymbolAddress((void**)&pbt, s_bt);
    cudaGetSymbolAddress((void**)&pWc, s_Wc);
    cudaGetSymbolAddress((void**)&pWB, s_WB);
    cudaGetSymbolAddress((void**)&pcb, s_cb);
    cudaGetSymbolAddress((void**)&pkpb, s_kpb);
    cudaGetSymbolAddress((void**)&pvpb, s_vpb);
    cudaGetSymbolAddress((void**)&pzero, s_zero);

    cudaFuncSetAttribute(fused_pair,
                         cudaFuncAttributeMaxDynamicSharedMemorySize, FUSED_SMEM);

    pack_kernel<<<3335, 256>>>(kt_w, vt_w, Wq_w, Wq_b, kc_w, vc_w,
                               kp2_w, vp2_w, g_w, kp2_b, vp2_b);
    cb_kernel<<<1, 256>>>(g_w, g_b, kp2_b, vp2_b);
    phiproj_kernel<<<NTT_ + NCC_, 256>>>(phi_t, phi_c, kp1_w, kp1_b, vp1_w, vp1_b);

    {   // weight-prep: G1|G2 -> s_BGh cols 256:512 (half), Wat -> s_Wt, Wac -> s_Wc
        GemmP p = mk(); p.A=g_w; p.lda=768; p.B=pWB; p.ldb=512; p.K=512;
        p.hC=pBGh; p.O2=pWt + 768*256; p.O3=pWc + 512*256;
        gemm_nt<EP_WPREP><<<dim3(12,4), 256>>>(p);
    }
    {   // combined: [kt|vt|Q|At] = R_t @ s_Wt^T + s_bt (64 blocks, gx=16)
        //           [kc|vc|Ac]   = R_ctx @ s_Wc^T      (192 blocks, gx=12)
        GemmP pa = mk(); pa.A=R_t; pa.lda=256; pa.B=pWt; pa.ldb=256; pa.K=256;
        pa.C=pTt; pa.ldc=1024; pa.vec=pbt;
        GemmP pb = mk(); pb.A=R_ctx; pb.lda=256; pb.B=pWc; pb.ldb=256; pb.K=256;
        pb.C=pCc; pb.ldc=768; pb.vec=pzero;
        gemm64_dual<<<64 + 192, 256>>>(pa, 64, 16, pb, 12);
    }

    // --- fused pair kernel (H build + K/V/gate + partial attention) ---
    {
        FusedP fp;
        fp.apt = papt; fp.Cph = pCph;
        fp.kp2h = pkp2h; fp.vp2h = pvp2h; fp.BGh = pBGh;
        fp.Part = pPart;
        fp.Tt = pTt; fp.Cc = pCc; fp.kpb = pkpb; fp.vpb = pvpb; fp.cb = pcb;
        fused_pair<<<NP_/128, 512, FUSED_SMEM>>>(fp);
    }

    // --- reduce partials -> ctx (s_At) ---
    attn_reduce<<<NTT_, 256>>>(pPart, pAt);

    // --- output projection ---
    {
        GemmP p = mk(); p.A=pAt; p.lda=256; p.B=out_w; p.ldb=256; p.K=256;
        p.C=outp; p.ldc=256; p.vec=out_b;
        gemm_nt<EP_BIAS><<<dim3(4,4), 256>>>(p);
    }
}

// round 14
// speedup vs baseline: 1.9665x; 1.0096x over previous
#include <cuda_runtime.h>
#include <cuda_fp16.h>
#include <math.h>
#include <stdint.h>

// ---------------------------------------------------------------------------
// TargetAwareContextAttention — fused pair kernel (16 warps): ldmatrix frags,
// group-scoped barriers, in-kernel H build + flash partial attention.
// Prologue: merged prep kernel + wide weight-prep GEMM.
// B=2, Nt=128, Nc=512, D=256, DPHI=16, HID=128, H=8, dk=32; NP=131072 pairs.
// ---------------------------------------------------------------------------

#define D_    256
#define DPHI_ 16
#define HID_  128
#define B_    2
#define NT_   128
#define NC_   512
#define NTT_  (B_*NT_)    // 256
#define NCC_  (B_*NC_)    // 1024
#define NP_   (NTT_*NC_)  // 131072

// ------------------------------- scratch -----------------------------------
__device__ __half s_apt[NTT_*256];      // W1*phi_t + b (k|v halves)
__device__ __half s_Cph[NCC_*256];      // W1*phi_c (k|v halves)
__device__ __half s_BGh [256*512];      // gate B rows: [gw3 | G1|G2]
__device__ __half s_kp2h[256*128];
__device__ __half s_vp2h[256*128];
__device__ float s_Tt [NTT_*1024];      // [kt|vt|Q|At] per target row
__device__ float s_Cc [NCC_*768];       // [kc|vc|Ac] per ctx row
__device__ float s_At [NTT_*256];       // ctx (attention output)
__device__ float s_Part[256*4*8*36];    // per-(tg,chunk,head): o[32], m, l
__device__ float s_Wt [1024*256];       // [kt_w; vt_w; Wq_w; Wat]
__device__ float s_bt [1024];
__device__ float s_Wc [768*256];        // [kc_w; vc_w; Wac]
__device__ float s_WB [768*512];        // weight-prep B
__device__ float s_cb [256];
__device__ float s_kpb[256];
__device__ float s_vpb[256];
__device__ float s_zero[1024];          // stays zero

// --------------------------- helpers ----------------------------------------
__device__ __forceinline__ void mma16(float* c, const uint32_t* a, const uint32_t* b) {
    asm volatile(
        "mma.sync.aligned.m16n8k16.row.col.f32.f16.f16.f32 "
        "{%0,%1,%2,%3}, {%4,%5,%6,%7}, {%8,%9}, {%0,%1,%2,%3};"
        : "+f"(c[0]), "+f"(c[1]), "+f"(c[2]), "+f"(c[3])
        : "r"(a[0]), "r"(a[1]), "r"(a[2]), "r"(a[3]), "r"(b[0]), "r"(b[1]));
}
__device__ __forceinline__ void ldsm4(uint32_t& r0, uint32_t& r1,
                                      uint32_t& r2, uint32_t& r3, uint32_t addr) {
    asm volatile("ldmatrix.sync.aligned.m8n8.x4.shared.b16 {%0,%1,%2,%3}, [%4];"
        : "=r"(r0), "=r"(r1), "=r"(r2), "=r"(r3) : "r"(addr));
}
__device__ __forceinline__ uint32_t habsdiff2(uint32_t a, uint32_t b) {
    __half2 ha = *reinterpret_cast<__half2*>(&a);
    __half2 hb = *reinterpret_cast<__half2*>(&b);
    __half2 r = __habs2(__hsub2(ha, hb));
    return *reinterpret_cast<uint32_t*>(&r);
}
__device__ __forceinline__ uint32_t relusub2(uint32_t a, uint32_t c) {
    __half2 ha = *reinterpret_cast<__half2*>(&a);
    __half2 hc = *reinterpret_cast<__half2*>(&c);
    __half2 r = __hmax2(__hsub2(ha, hc), __float2half2_rn(0.f));
    return *reinterpret_cast<uint32_t*>(&r);
}

// ---------------------- fused pair kernel -----------------------------------
#define TP 132                                  // tile pitch (u32), 256-half rows
#define BP 20                                   // B staging pitch (u32)
#define SP 132                                  // score pitch (floats)
#define FUSED_SMEM ((3*128*TP + 256*BP) * 4)    // 223232 B

struct FusedP {
    const __half *apt, *Cph, *kp2h, *vp2h, *BGh;
    float* Part;
    const float *Tt, *Cc, *kpb, *vpb, *cb;
};

__global__ void __launch_bounds__(512) fused_pair(FusedP p) {
    extern __shared__ __align__(16) uint32_t sm[];
    uint32_t* Ht = sm;
    uint32_t* Kt = sm + 128*TP;
    uint32_t* Vt = sm + 2*128*TP;
    uint32_t* Bs = sm + 3*128*TP;   // 256 rows x BP; group-partitioned

    uint32_t smBase;
    asm("{ .reg .u64 t; cvta.to.shared.u64 t, %1; cvt.u32.u64 %0, t; }"
        : "=r"(smBase) : "l"(sm));

    const int tid   = threadIdx.x;
    const int lane  = tid & 31;
    const int wid   = tid >> 5;     // 0..15
    const int warpM = wid & 3;      // 32-row slice
    const int warpN = wid >> 2;     // 0..3 -> 64-col slice of 256
    const int g     = lane >> 2;
    const int t4    = lane & 3;
    const int tg    = blockIdx.x >> 2;
    const int chunk = blockIdx.x & 3;
    const int cx0   = (tg >> 7) * 512 + chunk * 128;

    // ldmatrix per-thread base addresses (bytes)
    uint32_t aAB[2], bAB[4];
#pragma unroll
    for (int mf = 0; mf < 2; mf++)
        aAB[mf] = smBase + (((warpM*32 + mf*16 + (lane&7) + ((lane>>3)&1)*8)*TP)
                            + ((lane>>4)&1)*4) * 4;
#pragma unroll
    for (int np = 0; np < 4; np++)
        bAB[np] = smBase + (((3*128*TP) +
                   (warpN*64 + np*16 + ((lane>>4)&1)*8 + (lane&7))*BP)
                            + ((lane>>3)&1)*4) * 4;

    auto gbar = [&]() {
        asm volatile("bar.sync %0, %1;" :: "r"(warpN + 1), "r"(128) : "memory");
    };

    // ---- build H tile: Ht[r][h] = relu(apt[tg][h] - Cph[cx0+r][h]) ----
    if (tid < 128) Bs[tid] = ((const uint32_t*)p.apt)[tg*128 + tid];
    __syncthreads();
    for (int i = tid; i < 128*32; i += 512) {
        const int row = i >> 5, c4 = i & 31;
        uint4 c = *(const uint4*)(p.Cph + (size_t)(cx0 + row)*256 + c4*8);
        uint4 o;
        o.x = relusub2(Bs[c4*4+0], c.x);
        o.y = relusub2(Bs[c4*4+1], c.y);
        o.z = relusub2(Bs[c4*4+2], c.z);
        o.w = relusub2(Bs[c4*4+3], c.w);
        *(uint4*)(Ht + row*TP + c4*4) = o;
    }
    __syncthreads();

    float acc[2][8][4];
    uint4 rb[2];

    auto zeroAcc = [&]() {
#pragma unroll
        for (int mf = 0; mf < 2; mf++)
#pragma unroll
            for (int nf = 0; nf < 8; nf++)
#pragma unroll
                for (int q = 0; q < 4; q++) acc[mf][nf][q] = 0.f;
    };
    auto loadB = [&](const __half* Bp, int ldb, int kc) {
        const int lt = tid & 127;
#pragma unroll
        for (int q = 0; q < 2; q++) {
            const int idx = q*128 + lt;
            const int row = warpN*64 + (idx >> 2), f4 = idx & 3;
            rb[q] = *(const uint4*)(Bp + (size_t)row*ldb + kc + f4*8);
        }
    };
    auto storeB = [&]() {
        const int lt = tid & 127;
#pragma unroll
        for (int q = 0; q < 2; q++) {
            const int idx = q*128 + lt;
            const int row = warpN*64 + (idx >> 2), f4 = idx & 3;
            *(uint4*)(Bs + row*BP + f4*4) = rb[q];
        }
    };
    auto computeL = [&](int aU) {
#pragma unroll
        for (int kf = 0; kf < 2; kf++) {
            uint32_t af[2][4], bf[8][2];
#pragma unroll
            for (int mf = 0; mf < 2; mf++)
                ldsm4(af[mf][0], af[mf][1], af[mf][2], af[mf][3],
                      aAB[mf] + (aU + kf*8)*4);
#pragma unroll
            for (int np = 0; np < 4; np++)
                ldsm4(bf[2*np][0], bf[2*np][1], bf[2*np+1][0], bf[2*np+1][1],
                      bAB[np] + (kf*8)*4);
#pragma unroll
            for (int mf = 0; mf < 2; mf++)
#pragma unroll
                for (int nf = 0; nf < 8; nf++)
                    mma16(acc[mf][nf], af[mf], bf[nf]);
        }
    };
    auto computeAbs = [&](int aU) {
        const uint32_t* b_s = Bs + (warpN*64)*BP;
#pragma unroll
        for (int kf = 0; kf < 2; kf++) {
            const int kb = kf*8 + t4;
            uint32_t af[2][4];
#pragma unroll
            for (int mf = 0; mf < 2; mf++) {
                const int ro = (warpM*32 + mf*16 + g)*TP + aU + kb;
                af[mf][0] = habsdiff2(Kt[ro],          Vt[ro]);
                af[mf][1] = habsdiff2(Kt[ro + 8*TP],   Vt[ro + 8*TP]);
                af[mf][2] = habsdiff2(Kt[ro + 4],      Vt[ro + 4]);
                af[mf][3] = habsdiff2(Kt[ro + 8*TP+4], Vt[ro + 8*TP+4]);
            }
            uint32_t bf[8][2];
#pragma unroll
            for (int nf = 0; nf < 8; nf++) {
                const uint32_t* bp = b_s + (nf*8 + g)*BP + kb;
                bf[nf][0] = bp[0]; bf[nf][1] = bp[4];
            }
#pragma unroll
            for (int mf = 0; mf < 2; mf++)
#pragma unroll
                for (int nf = 0; nf < 8; nf++)
                    mma16(acc[mf][nf], af[mf], bf[nf]);
        }
    };

    // ---- K and V phases: outputs to smem tiles ----
    for (int sel = 0; sel < 2; sel++) {
        const __half* Bp = sel ? p.vp2h : p.kp2h;
        const int   aBase = sel ? 64 : 0;
        uint32_t*   Ot    = sel ? Vt : Kt;
        const float* bias = sel ? p.vpb : p.kpb;
        const int   poff  = sel ? 256 : 0;
        zeroAcc();
        loadB(Bp, HID_, 0);
#pragma unroll
        for (int c = 0; c < 4; c++) {
            gbar();
            storeB();
            gbar();
            if (c < 3) loadB(Bp, HID_, (c+1)*32);
            computeL(aBase + c*16);
        }
#pragma unroll
        for (int mf = 0; mf < 2; mf++)
#pragma unroll
        for (int hf = 0; hf < 2; hf++) {
            const int row  = warpM*32 + mf*16 + g + hf*8;
            const int cx = cx0 + row;
            const float* r1 = p.Tt + (size_t)tg*1024 + poff;
            const float* r2 = p.Cc + (size_t)cx*768  + poff;
#pragma unroll
            for (int nf = 0; nf < 8; nf++) {
                const int col = warpN*64 + nf*8 + t4*2;
                float2 a = __ldg((const float2*)(r1 + col));
                float2 b = __ldg((const float2*)(r2 + col));
                float2 v = __ldg((const float2*)(bias + col));
                __half2 h = __floats2half2_rn(
                    acc[mf][nf][hf*2+0] + a.x + b.x + v.x,
                    acc[mf][nf][hf*2+1] + a.y + b.y + v.y);
                Ot[row*TP + (col >> 1)] = *reinterpret_cast<uint32_t*>(&h);
            }
        }
    }

    __syncthreads();

    // ---- gate phase: K=512 (|K-V| chunks 0-7, H chunks 8-15) ----
    zeroAcc();
    loadB(p.BGh, 512, 0);
#pragma unroll
    for (int c = 0; c < 16; c++) {
        gbar();
        storeB();
        gbar();
        if (c < 15) loadB(p.BGh, 512, (c+1)*32);
        if (c < 8) computeAbs(c*16);
        else       computeL((c-8)*16);
    }
#pragma unroll
    for (int mf = 0; mf < 2; mf++)
#pragma unroll
    for (int hf = 0; hf < 2; hf++) {
        const int row  = warpM*32 + mf*16 + g + hf*8;
        const int cx = cx0 + row;
        const float* r1 = p.Tt + (size_t)tg*1024 + 768;
        const float* r2 = p.Cc + (size_t)cx*768  + 512;
#pragma unroll
        for (int nf = 0; nf < 8; nf++) {
            const int col = warpN*64 + nf*8 + t4*2;
            float2 at = __ldg((const float2*)(r1 + col));
            float2 ac = __ldg((const float2*)(r2 + col));
            float2 cb = __ldg((const float2*)(p.cb + col));
            uint32_t ku = Kt[row*TP + (col >> 1)];
            uint32_t vu = Vt[row*TP + (col >> 1)];
            float2 kk = __half22float2(*reinterpret_cast<__half2*>(&ku));
            float2 vv = __half22float2(*reinterpret_cast<__half2*>(&vu));
            float g0 = 1.f / (1.f + __expf(-(acc[mf][nf][hf*2+0] + at.x + ac.x + cb.x)));
            float g1 = 1.f / (1.f + __expf(-(acc[mf][nf][hf*2+1] + at.y + ac.y + cb.y)));
            __half2 hk = __floats2half2_rn(kk.x*g0, kk.y*g1);
            __half2 hv = __floats2half2_rn(vv.x*g0, vv.y*g1);
            Kt[row*TP + (col >> 1)] = *reinterpret_cast<uint32_t*>(&hk);
            Vt[row*TP + (col >> 1)] = *reinterpret_cast<uint32_t*>(&hv);
        }
    }
    __syncthreads();

    // ---- in-CTA partial attention over this CTA's 128 ctx rows ----
    float* fs = (float*)Bs;
    for (int i = tid; i < 256; i += 512)
        fs[1056 + i] = p.Tt[(size_t)tg*1024 + 512 + i];
    __syncthreads();

    const float scale = 0.17677669529663687f;  // 1/sqrt(32)
#pragma unroll
    for (int i = 0; i < 2; i++) {
        const int idx = i*512 + tid;
        const int r = idx >> 3, h = idx & 7;
        const uint32_t* kr = Kt + r*TP + h*16;
        const float* qh = fs + 1056 + h*32;
        float s = 0.f;
#pragma unroll
        for (int j = 0; j < 16; j++) {
            uint32_t u = kr[j];
            float2 kv = __half22float2(*reinterpret_cast<__half2*>(&u));
            s += qh[2*j]*kv.x + qh[2*j+1]*kv.y;
        }
        fs[h*SP + r] = s * scale;
    }
    __syncthreads();
    if (wid < 8) {
        const int h = wid;
        float m = -1e30f;
#pragma unroll
        for (int j = 0; j < 4; j++) m = fmaxf(m, fs[h*SP + lane + j*32]);
#pragma unroll
        for (int o = 16; o; o >>= 1) m = fmaxf(m, __shfl_xor_sync(0xffffffffu, m, o));
        if (lane == 0) fs[1320 + h] = m;
    }
    __syncthreads();
#pragma unroll
    for (int i = 0; i < 2; i++) {
        const int idx = i*512 + tid;
        const int r = idx >> 3, h = idx & 7;
        fs[h*SP + r] = __expf(fs[h*SP + r] - fs[1320 + h]);
    }
    __syncthreads();
    if (wid < 8) {
        const int h = wid;
        float l = 0.f;
#pragma unroll
        for (int j = 0; j < 4; j++) l += fs[h*SP + lane + j*32];
#pragma unroll
        for (int o = 16; o; o >>= 1) l += __shfl_xor_sync(0xffffffffu, l, o);
        if (lane == 0) fs[1328 + h] = l;
    }
    {
        const int h = tid >> 6, rem = tid & 63, dp = rem >> 2, part = rem & 3;
        const uint32_t* vr = Vt + h*16 + dp;
        const float* pr = fs + h*SP;
        float o0 = 0.f, o1 = 0.f;
        for (int r = part*32; r < part*32 + 32; r++) {
            uint32_t u = vr[r*TP];
            float2 vv = __half22float2(*reinterpret_cast<__half2*>(&u));
            o0 = fmaf(pr[r], vv.x, o0);
            o1 = fmaf(pr[r], vv.y, o1);
        }
        fs[1408 + ((h*16+dp)*4 + part)*2 + 0] = o0;
        fs[1408 + ((h*16+dp)*4 + part)*2 + 1] = o1;
    }
    __syncthreads();

    float* pp = p.Part + ((size_t)(tg*4 + chunk) * 8) * 36;
    if (tid < 8) {
        pp[tid*36 + 32] = fs[1320 + tid];
        pp[tid*36 + 33] = fs[1328 + tid];
    }
    if (tid < 256) {
        const int h = tid >> 5, rem = tid & 31, dp = rem >> 1, v = rem & 1;
        float s = 0.f;
#pragma unroll
        for (int part = 0; part < 4; part++)
            s += fs[1408 + ((h*16+dp)*4 + part)*2 + v];
        pp[h*36 + dp*2 + v] = s;
    }
}

// ---------------------- attention partial reduce -----------------------------
__global__ void __launch_bounds__(256) attn_reduce(const float* Part, float* ctxOut) {
    const int tg = blockIdx.x;
    const int h = threadIdx.x >> 5, d = threadIdx.x & 31;
    const float* pp = Part + ((size_t)(tg*4) * 8 + h) * 36;
    float m0 = pp[32], m1 = pp[288+32], m2 = pp[576+32], m3 = pp[864+32];
    float ms = fmaxf(fmaxf(m0, m1), fmaxf(m2, m3));
    float w0 = __expf(m0-ms), w1 = __expf(m1-ms), w2 = __expf(m2-ms), w3 = __expf(m3-ms);
    float l = w0*pp[33] + w1*pp[288+33] + w2*pp[576+33] + w3*pp[864+33];
    float o = w0*pp[d]  + w1*pp[288+d]  + w2*pp[576+d]  + w3*pp[864+d];
    ctxOut[tg*256 + h*32 + d] = o / l;
}

// ------------------- fp32 FFMA2 GEMM (prologue-sized) -----------------------
__device__ __forceinline__ unsigned long long pk2(float lo, float hi) {
    unsigned long long r;
    asm("mov.b64 %0, {%1, %2};" : "=l"(r) : "f"(lo), "f"(hi));
    return r;
}
__device__ __forceinline__ void upk2(unsigned long long v, float& lo, float& hi) {
    asm("mov.b64 {%0, %1}, %2;" : "=f"(lo), "=f"(hi) : "l"(v));
}
__device__ __forceinline__ void ffma2(unsigned long long& d,
                                      unsigned long long a, unsigned long long b) {
    asm("fma.rn.f32x2 %0, %1, %2, %0;" : "+l"(d) : "l"(a), "l"(b));
}

struct GemmP {
    const float* A; int lda; int aoff;
    const float* B; int ldb; int boff;
    int K;
    float* C; int ldc; int coff;
    const float* vec;
    __half* hC; float* O2; float* O3;
};

enum { EP_NONE = 0, EP_BIAS = 1 };

// 64x64 tile, TM=TN=4, 256 threads, EP_BIAS body
__device__ __forceinline__ void gemm64_body(const GemmP& p, int mBase, int nBase) {
    constexpr int BM = 64, BN = 64, BK = 16, TM = 4, TN = 4, NTX = 16;
    __shared__ __align__(16) float As[2][BK*BM];
    __shared__ __align__(16) float Bs[2][BK*BN];

    const int tid = threadIdx.x;
    const int tx = tid % NTX;
    const int ty = tid / NTX;
    const int lrow = tid >> 2;
    const int lk   = (tid & 3) << 2;

    const float* Abase = p.A + (size_t)(mBase + lrow) * p.lda + p.aoff + lk;
    const float* Bbase = p.B + (size_t)(nBase + lrow) * p.ldb + p.boff + lk;

    unsigned long long acc2[TM/2][TN];
#pragma unroll
    for (int i = 0; i < TM/2; i++)
#pragma unroll
        for (int j = 0; j < TN; j++) acc2[i][j] = 0ull;

    const int nTiles = p.K / BK;
    float4 ra, rbv;
    ra  = *(const float4*)(Abase);
    rbv = *(const float4*)(Bbase);
    {
        int m = lrow;
        As[0][(lk+0)*BM+m]=ra.x; As[0][(lk+1)*BM+m]=ra.y;
        As[0][(lk+2)*BM+m]=ra.z; As[0][(lk+3)*BM+m]=ra.w;
        Bs[0][(lk+0)*BN+m]=rbv.x; Bs[0][(lk+1)*BN+m]=rbv.y;
        Bs[0][(lk+2)*BN+m]=rbv.z; Bs[0][(lk+3)*BN+m]=rbv.w;
    }
    __syncthreads();

    for (int t = 0; t < nTiles; t++) {
        const int cur = t & 1;
        const bool more = (t + 1) < nTiles;
        if (more) {
            const int k0 = (t + 1) * BK;
            ra  = *(const float4*)(Abase + k0);
            rbv = *(const float4*)(Bbase + k0);
        }
#pragma unroll
        for (int k = 0; k < BK; k++) {
            unsigned long long a2[TM/2], b2[TN];
            ulonglong2 va = *(const ulonglong2*)&As[cur][k*BM + ty*TM];
            a2[0] = va.x; a2[1] = va.y;
            float4 vb = *(const float4*)&Bs[cur][k*BN + tx*TN];
            b2[0] = pk2(vb.x, vb.x); b2[1] = pk2(vb.y, vb.y);
            b2[2] = pk2(vb.z, vb.z); b2[3] = pk2(vb.w, vb.w);
#pragma unroll
            for (int i = 0; i < TM/2; i++)
#pragma unroll
                for (int j = 0; j < TN; j++) ffma2(acc2[i][j], a2[i], b2[j]);
        }
        if (more) {
            const int nxt = cur ^ 1;
            __syncthreads();
            int m = lrow;
            As[nxt][(lk+0)*BM+m]=ra.x; As[nxt][(lk+1)*BM+m]=ra.y;
            As[nxt][(lk+2)*BM+m]=ra.z; As[nxt][(lk+3)*BM+m]=ra.w;
            Bs[nxt][(lk+0)*BN+m]=rbv.x; Bs[nxt][(lk+1)*BN+m]=rbv.y;
            Bs[nxt][(lk+2)*BN+m]=rbv.z; Bs[nxt][(lk+3)*BN+m]=rbv.w;
            __syncthreads();
        }
    }

    float accf[TM][TN];
#pragma unroll
    for (int i = 0; i < TM/2; i++)
#pragma unroll
        for (int j = 0; j < TN; j++) upk2(acc2[i][j], accf[2*i][j], accf[2*i+1][j]);

#pragma unroll
    for (int i = 0; i < TM; i++) {
        const int gm  = mBase + ty*TM + i;
        const int gn0 = nBase + tx*TN;
        float* co = p.C + (size_t)gm * p.ldc + p.coff + gn0;
#pragma unroll
        for (int j = 0; j < TN; j++)
            co[j] = accf[i][j] + p.vec[gn0 + j];
    }
}

__global__ void __launch_bounds__(256, 1) gemm64_dual(GemmP pa, int nba, int gxa,
                                                      GemmP pb, int gxb) {
    const int bid = blockIdx.x;
    if (bid < nba) gemm64_body(pa, (bid / gxa) * 64, (bid % gxa) * 64);
    else {
        const int b2 = bid - nba;
        gemm64_body(pb, (b2 / gxb) * 64, (b2 % gxb) * 64);
    }
}

__global__ void __launch_bounds__(256, 1) gemm64_single(GemmP p) {
    gemm64_body(p, blockIdx.y * 64, blockIdx.x * 64);
}

// --------------------- weight-prep: 32x32 tiles, load-once smem -------------
// C[m,n] = sum_k g_w[m, k] * s_WB[n, k],  M=256, N=768, K=512.
#define WP_SMEM (2 * 512 * 33 * 4)   // 135168 B
__global__ void __launch_bounds__(256) wprep32(const float* gw, const float* WB,
                                               __half* BGh, float* Wat, float* Wac) {
    extern __shared__ float ws[];
    float* As = ws;            // As[k*33 + row]
    float* Bs = ws + 512*33;
    const int tid = threadIdx.x;
    const int mBase = blockIdx.y * 32;
    const int nBase = blockIdx.x * 32;
#pragma unroll
    for (int i = 0; i < 16; i++) {
        int idx = i*256 + tid;              // 0..4095
        int row = idx >> 7, c4 = (idx & 127) << 2;
        float4 v = *(const float4*)(gw + (size_t)(mBase+row)*768 + c4);
        As[(c4+0)*33 + row] = v.x; As[(c4+1)*33 + row] = v.y;
        As[(c4+2)*33 + row] = v.z; As[(c4+3)*33 + row] = v.w;
        float4 w = *(const float4*)(WB + (size_t)(nBase+row)*512 + c4);
        Bs[(c4+0)*33 + row] = w.x; Bs[(c4+1)*33 + row] = w.y;
        Bs[(c4+2)*33 + row] = w.z; Bs[(c4+3)*33 + row] = w.w;
    }
    __syncthreads();
    const int ty = tid >> 4, tx = tid & 15;
    const int r0 = ty*2, c0 = tx*2;
    float a00 = 0.f, a01 = 0.f, a10 = 0.f, a11 = 0.f;
#pragma unroll 8
    for (int k = 0; k < 512; k++) {
        float x0 = As[k*33 + r0], x1 = As[k*33 + r0 + 1];
        float y0 = Bs[k*33 + c0], y1 = Bs[k*33 + c0 + 1];
        a00 = fmaf(x0, y0, a00); a01 = fmaf(x0, y1, a01);
        a10 = fmaf(x1, y0, a10); a11 = fmaf(x1, y1, a11);
    }
    float accv[2][2] = {{a00, a01}, {a10, a11}};
#pragma unroll
    for (int i = 0; i < 2; i++)
#pragma unroll
        for (int j = 0; j < 2; j++) {
            const int gm = mBase + r0 + i, d = nBase + c0 + j;
            const float v = accv[i][j];
            if (d < 256)      BGh[(size_t)gm*512 + 256 + d] = __float2half(v);
            else if (d < 512) Wat[(size_t)gm*256 + (d-256)] = v;
            else              Wac[(size_t)gm*256 + (d-512)] = v;
        }
}

// --------------------- merged prep kernel (pack + cb + phiproj) -------------
#define PACK_BLKS 3334
__global__ void prep_kernel(const float* kt_w, const float* vt_w,
                            const float* Wq_w, const float* Wq_b,
                            const float* kc_w, const float* vc_w,
                            const float* kp2_w, const float* vp2_w,
                            const float* g_w, const float* g_b,
                            const float* kp2_b, const float* vp2_b,
                            const float* phi_t, const float* phi_c,
                            const float* kp1_w, const float* kp1_b,
                            const float* vp1_w, const float* vp1_b) {
    const int bid = blockIdx.x;
    __shared__ float ph[DPHI_];
    if (bid < PACK_BLKS) {
        int i = bid * 256 + threadIdx.x;
        if (i < 196608) {
            s_Wt[i] = (i < 65536) ? kt_w[i]
                    : (i < 131072) ? vt_w[i - 65536] : Wq_w[i - 131072];
        } else if (i < 327680) {
            int j = i - 196608;
            s_Wc[j] = (j < 65536) ? kc_w[j] : vc_w[j - 65536];
        } else if (i < 720896) {
            int j = i - 327680;
            int d = j >> 9, k = j & 511;
            float v;
            if (d < 128)       v = (k < 256) ? kp2_w[k*128 + d] : 0.f;
            else if (d < 256)  v = (k >= 256) ? vp2_w[(k-256)*128 + (d-128)] : 0.f;
            else if (d < 512)  v = (k < 256) ? kt_w[k*256 + (d-256)] : vt_w[(k-256)*256 + (d-256)];
            else               v = (k < 256) ? kc_w[k*256 + (d-512)] : vc_w[(k-256)*256 + (d-512)];
            s_WB[j] = v;
        } else if (i < 786432) {
            int j = i - 720896;
            int n = j >> 8, c = j & 255;
            s_BGh[n*512 + c] = __float2half(g_w[n*768 + 512 + c]);
        } else if (i < 819200) {
            int j = i - 786432;
            s_kp2h[j] = __float2half(kp2_w[j]);
        } else if (i < 851968) {
            int j = i - 819200;
            s_vp2h[j] = __float2half(vp2_w[j]);
        } else if (i < 852992) {
            int j = i - 851968;
            s_bt[j] = (j >= 512 && j < 768) ? Wq_b[j - 512] : 0.f;
        } else if (i < 853504) {
            int j = i - 852992;
            if (j < 256) s_kpb[j] = kp2_b[j];
            else         s_vpb[j - 256] = vp2_b[j - 256];
        }
    } else if (bid == PACK_BLKS) {
        // cb: cb[n] = g_b[n] + gw1[n].kp2_b + gw2[n].vp2_b
        int n = threadIdx.x;
        float s = g_b[n];
        const float* r = g_w + (size_t)n * 768;
        for (int d = 0; d < 256; d++)
            s += r[d] * kp2_b[d] + r[256 + d] * vp2_b[d];
        s_cb[n] = s;
    } else {
        // phiproj
        const int rowId = bid - (PACK_BLKS + 1);   // 0..1279
        const int h = threadIdx.x;
        const bool isT = rowId < NTT_;
        const float* src = isT ? (phi_t + rowId*DPHI_)
                               : (phi_c + (size_t)(rowId - NTT_)*DPHI_);
        if (h < DPHI_) ph[h] = src[h];
        __syncthreads();
        const float* W = (h < 128) ? (kp1_w + h*DPHI_) : (vp1_w + (h-128)*DPHI_);
        float s = 0.f;
#pragma unroll
        for (int j = 0; j < DPHI_; j++) s = fmaf(W[j], ph[j], s);
        if (isT) s += (h < 128) ? kp1_b[h] : vp1_b[h-128];
        __half* dst = isT ? (s_apt + (size_t)rowId*256)
                          : (s_Cph + (size_t)(rowId - NTT_)*256);
        dst[h] = __float2half(s);
    }
}

// ------------------------------- launch -------------------------------------
static inline GemmP mk() { GemmP p; p.A=0;p.lda=0;p.aoff=0;p.B=0;p.ldb=0;
    p.boff=0;p.K=0;p.C=0;p.ldc=0;p.coff=0;p.vec=0;p.hC=0;p.O2=0;p.O3=0; return p; }

extern "C" void kernel_launch(void* const* d_in, const int* in_sizes, int n_in,
                              void* d_out, int out_size) {
    const float* R_t   = (const float*)d_in[0];
    const float* R_ctx = (const float*)d_in[1];
    const float* phi_t = (const float*)d_in[2];
    const float* phi_c = (const float*)d_in[3];
    const float* Wq_w  = (const float*)d_in[5];
    const float* Wq_b  = (const float*)d_in[6];
    const float* kc_w  = (const float*)d_in[7];
    const float* kt_w  = (const float*)d_in[8];
    const float* kp1_w = (const float*)d_in[9];
    const float* kp1_b = (const float*)d_in[10];
    const float* kp2_w = (const float*)d_in[11];
    const float* kp2_b = (const float*)d_in[12];
    const float* vc_w  = (const float*)d_in[13];
    const float* vt_w  = (const float*)d_in[14];
    const float* vp1_w = (const float*)d_in[15];
    const float* vp1_b = (const float*)d_in[16];
    const float* vp2_w = (const float*)d_in[17];
    const float* vp2_b = (const float*)d_in[18];
    const float* g_w   = (const float*)d_in[19];
    const float* g_b   = (const float*)d_in[20];
    const float* out_w = (const float*)d_in[21];
    const float* out_b = (const float*)d_in[22];
    float* outp = (float*)d_out;

    __half *papt, *pCph, *pBGh, *pkp2h, *pvp2h;
    float *pTt, *pCc, *pAt, *pPart, *pWt, *pbt, *pWc, *pWB, *pcb, *pkpb, *pvpb, *pzero;
    cudaGetSymbolAddress((void**)&papt, s_apt);
    cudaGetSymbolAddress((void**)&pCph, s_Cph);
    cudaGetSymbolAddress((void**)&pBGh, s_BGh);
    cudaGetSymbolAddress((void**)&pkp2h, s_kp2h);
    cudaGetSymbolAddress((void**)&pvp2h, s_vp2h);
    cudaGetSymbolAddress((void**)&pTt, s_Tt);
    cudaGetSymbolAddress((void**)&pCc, s_Cc);
    cudaGetSymbolAddress((void**)&pAt, s_At);
    cudaGetSymbolAddress((void**)&pPart, s_Part);
    cudaGetSymbolAddress((void**)&pWt, s_Wt);
    cudaGetSymbolAddress((void**)&pbt, s_bt);
    cudaGetSymbolAddress((void**)&pWc, s_Wc);
    cudaGetSymbolAddress((void**)&pWB, s_WB);
    cudaGetSymbolAddress((void**)&pcb, s_cb);
    cudaGetSymbolAddress((void**)&pkpb, s_kpb);
    cudaGetSymbolAddress((void**)&pvpb, s_vpb);
    cudaGetSymbolAddress((void**)&pzero, s_zero);

    cudaFuncSetAttribute(fused_pair,
                         cudaFuncAttributeMaxDynamicSharedMemorySize, FUSED_SMEM);
    cudaFuncSetAttribute(wprep32,
                         cudaFuncAttributeMaxDynamicSharedMemorySize, WP_SMEM);

    // merged prep: pack (3334) + cb (1) + phiproj (1280)
    prep_kernel<<<PACK_BLKS + 1 + NTT_ + NCC_, 256>>>(
        kt_w, vt_w, Wq_w, Wq_b, kc_w, vc_w, kp2_w, vp2_w,
        g_w, g_b, kp2_b, vp2_b, phi_t, phi_c, kp1_w, kp1_b, vp1_w, vp1_b);

    // weight-prep GEMM: 32x32 tiles, 192 CTAs
    wprep32<<<dim3(24, 8), 256, WP_SMEM>>>(g_w, pWB, pBGh,
                                           pWt + 768*256, pWc + 512*256);

    {   // combined: [kt|vt|Q|At] = R_t @ s_Wt^T + s_bt (64 blocks, gx=16)
        //           [kc|vc|Ac]   = R_ctx @ s_Wc^T      (192 blocks, gx=12)
        GemmP pa = mk(); pa.A=R_t; pa.lda=256; pa.B=pWt; pa.ldb=256; pa.K=256;
        pa.C=pTt; pa.ldc=1024; pa.vec=pbt;
        GemmP pb = mk(); pb.A=R_ctx; pb.lda=256; pb.B=pWc; pb.ldb=256; pb.K=256;
        pb.C=pCc; pb.ldc=768; pb.vec=pzero;
        gemm64_dual<<<64 + 192, 256>>>(pa, 64, 16, pb, 12);
    }

    // --- fused pair kernel (H build + K/V/gate + partial attention) ---
    {
        FusedP fp;
        fp.apt = papt; fp.Cph = pCph;
        fp.kp2h = pkp2h; fp.vp2h = pvp2h; fp.BGh = pBGh;
        fp.Part = pPart;
        fp.Tt = pTt; fp.Cc = pCc; fp.kpb = pkpb; fp.vpb = pvpb; fp.cb = pcb;
        fused_pair<<<NP_/128, 512, FUSED_SMEM>>>(fp);
    }

    // --- reduce partials -> ctx (s_At) ---
    attn_reduce<<<NTT_, 256>>>(pPart, pAt);

    // --- output projection ---
    {
        GemmP p = mk(); p.A=pAt; p.lda=256; p.B=out_w; p.ldb=256; p.K=256;
        p.C=outp; p.ldc=256; p.vec=out_b;
        gemm64_single<<<dim3(4,4), 256>>>(p);
    }
}

// round 15
// speedup vs baseline: 1.9935x; 1.0137x over previous
#include <cuda_runtime.h>
#include <cuda_fp16.h>
#include <math.h>
#include <stdint.h>

// ---------------------------------------------------------------------------
// TargetAwareContextAttention — fused pair kernel (16 warps): all-ldmatrix
// MMA path (gate |K-V| materialized once), vectorized attention loads.
// B=2, Nt=128, Nc=512, D=256, DPHI=16, HID=128, H=8, dk=32; NP=131072 pairs.
// ---------------------------------------------------------------------------

#define D_    256
#define DPHI_ 16
#define HID_  128
#define B_    2
#define NT_   128
#define NC_   512
#define NTT_  (B_*NT_)    // 256
#define NCC_  (B_*NC_)    // 1024
#define NP_   (NTT_*NC_)  // 131072

// ------------------------------- scratch -----------------------------------
__device__ __half s_apt[NTT_*256];      // W1*phi_t + b (k|v halves)
__device__ __half s_Cph[NCC_*256];      // W1*phi_c (k|v halves)
__device__ __half s_BGh [256*512];      // gate B rows: [gw3 | G1|G2]
__device__ __half s_kp2h[256*128];
__device__ __half s_vp2h[256*128];
__device__ float s_Tt [NTT_*1024];      // [kt|vt|Q|At] per target row
__device__ float s_Cc [NCC_*768];       // [kc|vc|Ac] per ctx row
__device__ float s_At [NTT_*256];       // ctx (attention output)
__device__ float s_Part[256*4*8*36];    // per-(tg,chunk,head): o[32], m, l
__device__ float s_Wt [1024*256];       // [kt_w; vt_w; Wq_w; Wat]
__device__ float s_bt [1024];
__device__ float s_Wc [768*256];        // [kc_w; vc_w; Wac]
__device__ float s_WB [768*512];        // weight-prep B
__device__ float s_cb [256];
__device__ float s_kpb[256];
__device__ float s_vpb[256];
__device__ float s_zero[1024];          // stays zero

// --------------------------- helpers ----------------------------------------
__device__ __forceinline__ void mma16(float* c, const uint32_t* a, const uint32_t* b) {
    asm volatile(
        "mma.sync.aligned.m16n8k16.row.col.f32.f16.f16.f32 "
        "{%0,%1,%2,%3}, {%4,%5,%6,%7}, {%8,%9}, {%0,%1,%2,%3};"
        : "+f"(c[0]), "+f"(c[1]), "+f"(c[2]), "+f"(c[3])
        : "r"(a[0]), "r"(a[1]), "r"(a[2]), "r"(a[3]), "r"(b[0]), "r"(b[1]));
}
__device__ __forceinline__ void ldsm4(uint32_t& r0, uint32_t& r1,
                                      uint32_t& r2, uint32_t& r3, uint32_t addr) {
    asm volatile("ldmatrix.sync.aligned.m8n8.x4.shared.b16 {%0,%1,%2,%3}, [%4];"
        : "=r"(r0), "=r"(r1), "=r"(r2), "=r"(r3) : "r"(addr));
}
__device__ __forceinline__ uint32_t habsdiff2(uint32_t a, uint32_t b) {
    __half2 ha = *reinterpret_cast<__half2*>(&a);
    __half2 hb = *reinterpret_cast<__half2*>(&b);
    __half2 r = __habs2(__hsub2(ha, hb));
    return *reinterpret_cast<uint32_t*>(&r);
}
__device__ __forceinline__ uint32_t relusub2(uint32_t a, uint32_t c) {
    __half2 ha = *reinterpret_cast<__half2*>(&a);
    __half2 hc = *reinterpret_cast<__half2*>(&c);
    __half2 r = __hmax2(__hsub2(ha, hc), __float2half2_rn(0.f));
    return *reinterpret_cast<uint32_t*>(&r);
}

// ---------------------- fused pair kernel -----------------------------------
#define TP 132                                  // tile pitch (u32), 256-half rows
#define BP 20                                   // B staging pitch (u32)
#define SP 132                                  // score pitch (floats)
#define FUSED_SMEM ((3*128*TP + 256*BP) * 4)    // 223232 B

struct FusedP {
    const __half *apt, *Cph, *kp2h, *vp2h, *BGh;
    float* Part;
    const float *Tt, *Cc, *kpb, *vpb, *cb;
};

__global__ void __launch_bounds__(512) fused_pair(FusedP p) {
    extern __shared__ __align__(16) uint32_t sm[];
    uint32_t* Ht = sm;
    uint32_t* Kt = sm + 128*TP;
    uint32_t* Vt = sm + 2*128*TP;
    uint32_t* Bs = sm + 3*128*TP;   // 256 rows x BP; group-partitioned

    uint32_t smBase;
    asm("{ .reg .u64 t; cvta.to.shared.u64 t, %1; cvt.u32.u64 %0, t; }"
        : "=r"(smBase) : "l"(sm));

    const int tid   = threadIdx.x;
    const int lane  = tid & 31;
    const int wid   = tid >> 5;     // 0..15
    const int warpM = wid & 3;      // 32-row slice
    const int warpN = wid >> 2;     // 0..3 -> 64-col slice of 256
    const int g     = lane >> 2;
    const int t4    = lane & 3;
    const int tg    = blockIdx.x >> 2;
    const int chunk = blockIdx.x & 3;
    const int cx0   = (tg >> 7) * 512 + chunk * 128;

    // ldmatrix per-thread base addresses (bytes)
    uint32_t aAB[2], bAB[4];
#pragma unroll
    for (int mf = 0; mf < 2; mf++)
        aAB[mf] = smBase + (((warpM*32 + mf*16 + (lane&7) + ((lane>>3)&1)*8)*TP)
                            + ((lane>>4)&1)*4) * 4;
#pragma unroll
    for (int np = 0; np < 4; np++)
        bAB[np] = smBase + (((3*128*TP) +
                   (warpN*64 + np*16 + ((lane>>4)&1)*8 + (lane&7))*BP)
                            + ((lane>>3)&1)*4) * 4;

    auto gbar = [&]() {
        asm volatile("bar.sync %0, %1;" :: "r"(warpN + 1), "r"(128) : "memory");
    };

    // ---- build H tile: Ht[r][h] = relu(apt[tg][h] - Cph[cx0+r][h]) ----
    if (tid < 128) Bs[tid] = ((const uint32_t*)p.apt)[tg*128 + tid];
    __syncthreads();
    for (int i = tid; i < 128*32; i += 512) {
        const int row = i >> 5, c4 = i & 31;
        uint4 c = *(const uint4*)(p.Cph + (size_t)(cx0 + row)*256 + c4*8);
        uint4 o;
        o.x = relusub2(Bs[c4*4+0], c.x);
        o.y = relusub2(Bs[c4*4+1], c.y);
        o.z = relusub2(Bs[c4*4+2], c.z);
        o.w = relusub2(Bs[c4*4+3], c.w);
        *(uint4*)(Ht + row*TP + c4*4) = o;
    }
    __syncthreads();

    float acc[2][8][4];
    uint4 rb[2];

    auto zeroAcc = [&]() {
#pragma unroll
        for (int mf = 0; mf < 2; mf++)
#pragma unroll
            for (int nf = 0; nf < 8; nf++)
#pragma unroll
                for (int q = 0; q < 4; q++) acc[mf][nf][q] = 0.f;
    };
    auto loadB = [&](const __half* Bp, int ldb, int kc) {
        const int lt = tid & 127;
#pragma unroll
        for (int q = 0; q < 2; q++) {
            const int idx = q*128 + lt;
            const int row = warpN*64 + (idx >> 2), f4 = idx & 3;
            rb[q] = *(const uint4*)(Bp + (size_t)row*ldb + kc + f4*8);
        }
    };
    auto storeB = [&]() {
        const int lt = tid & 127;
#pragma unroll
        for (int q = 0; q < 2; q++) {
            const int idx = q*128 + lt;
            const int row = warpN*64 + (idx >> 2), f4 = idx & 3;
            *(uint4*)(Bs + row*BP + f4*4) = rb[q];
        }
    };
    auto computeL = [&](int aU) {
#pragma unroll
        for (int kf = 0; kf < 2; kf++) {
            uint32_t af[2][4], bf[8][2];
#pragma unroll
            for (int mf = 0; mf < 2; mf++)
                ldsm4(af[mf][0], af[mf][1], af[mf][2], af[mf][3],
                      aAB[mf] + (aU + kf*8)*4);
#pragma unroll
            for (int np = 0; np < 4; np++)
                ldsm4(bf[2*np][0], bf[2*np][1], bf[2*np+1][0], bf[2*np+1][1],
                      bAB[np] + (kf*8)*4);
#pragma unroll
            for (int mf = 0; mf < 2; mf++)
#pragma unroll
                for (int nf = 0; nf < 8; nf++)
                    mma16(acc[mf][nf], af[mf], bf[nf]);
        }
    };

    // ---- K and V phases: outputs to smem tiles ----
    for (int sel = 0; sel < 2; sel++) {
        const __half* Bp = sel ? p.vp2h : p.kp2h;
        const int   aBase = sel ? 64 : 0;
        uint32_t*   Ot    = sel ? Vt : Kt;
        const float* bias = sel ? p.vpb : p.kpb;
        const int   poff  = sel ? 256 : 0;
        zeroAcc();
        loadB(Bp, HID_, 0);
#pragma unroll
        for (int c = 0; c < 4; c++) {
            gbar();
            storeB();
            gbar();
            if (c < 3) loadB(Bp, HID_, (c+1)*32);
            computeL(aBase + c*16);
        }
#pragma unroll
        for (int mf = 0; mf < 2; mf++)
#pragma unroll
        for (int hf = 0; hf < 2; hf++) {
            const int row  = warpM*32 + mf*16 + g + hf*8;
            const int cx = cx0 + row;
            const float* r1 = p.Tt + (size_t)tg*1024 + poff;
            const float* r2 = p.Cc + (size_t)cx*768  + poff;
#pragma unroll
            for (int nf = 0; nf < 8; nf++) {
                const int col = warpN*64 + nf*8 + t4*2;
                float2 a = __ldg((const float2*)(r1 + col));
                float2 b = __ldg((const float2*)(r2 + col));
                float2 v = __ldg((const float2*)(bias + col));
                __half2 h = __floats2half2_rn(
                    acc[mf][nf][hf*2+0] + a.x + b.x + v.x,
                    acc[mf][nf][hf*2+1] + a.y + b.y + v.y);
                Ot[row*TP + (col >> 1)] = *reinterpret_cast<uint32_t*>(&h);
            }
        }
    }

    __syncthreads();

    // ---- gate phase: K=512. Reordered: H chunks (B cols 256-511) first,
    //      then Ht := |K-V| (one vector pass), |K-V| chunks (B cols 0-255).
    zeroAcc();
    loadB(p.BGh, 512, 256);
#pragma unroll
    for (int c = 0; c < 16; c++) {
        gbar();
        storeB();
        gbar();
        if (c < 15) {
            const int nk = (c + 1 < 8) ? 256 + (c + 1)*32 : (c + 1 - 8)*32;
            loadB(p.BGh, 512, nk);
        }
        if (c == 8) {
            __syncthreads();   // all H-chunk ldmatrix reads of Ht done
            for (int i = tid; i < 128*32; i += 512) {
                const int row = i >> 5, c4 = i & 31;
                uint4 kk = *(uint4*)(Kt + row*TP + c4*4);
                uint4 vv = *(uint4*)(Vt + row*TP + c4*4);
                uint4 o;
                o.x = habsdiff2(kk.x, vv.x); o.y = habsdiff2(kk.y, vv.y);
                o.z = habsdiff2(kk.z, vv.z); o.w = habsdiff2(kk.w, vv.w);
                *(uint4*)(Ht + row*TP + c4*4) = o;
            }
            __syncthreads();
        }
        computeL(((c < 8) ? c : (c - 8)) * 16);
    }
    // epilogue: g=sigmoid(pre); Kg,Vg overwrite Kt,Vt in smem.
#pragma unroll
    for (int mf = 0; mf < 2; mf++)
#pragma unroll
    for (int hf = 0; hf < 2; hf++) {
        const int row  = warpM*32 + mf*16 + g + hf*8;
        const int cx = cx0 + row;
        const float* r1 = p.Tt + (size_t)tg*1024 + 768;
        const float* r2 = p.Cc + (size_t)cx*768  + 512;
#pragma unroll
        for (int nf = 0; nf < 8; nf++) {
            const int col = warpN*64 + nf*8 + t4*2;
            float2 at = __ldg((const float2*)(r1 + col));
            float2 ac = __ldg((const float2*)(r2 + col));
            float2 cb = __ldg((const float2*)(p.cb + col));
            uint32_t ku = Kt[row*TP + (col >> 1)];
            uint32_t vu = Vt[row*TP + (col >> 1)];
            float2 kk = __half22float2(*reinterpret_cast<__half2*>(&ku));
            float2 vv = __half22float2(*reinterpret_cast<__half2*>(&vu));
            float g0 = 1.f / (1.f + __expf(-(acc[mf][nf][hf*2+0] + at.x + ac.x + cb.x)));
            float g1 = 1.f / (1.f + __expf(-(acc[mf][nf][hf*2+1] + at.y + ac.y + cb.y)));
            __half2 hk = __floats2half2_rn(kk.x*g0, kk.y*g1);
            __half2 hv = __floats2half2_rn(vv.x*g0, vv.y*g1);
            Kt[row*TP + (col >> 1)] = *reinterpret_cast<uint32_t*>(&hk);
            Vt[row*TP + (col >> 1)] = *reinterpret_cast<uint32_t*>(&hv);
        }
    }
    __syncthreads();

    // ---- in-CTA partial attention over this CTA's 128 ctx rows ----
    float* fs = (float*)Bs;
    for (int i = tid; i < 256; i += 512)
        fs[1056 + i] = p.Tt[(size_t)tg*1024 + 512 + i];
    __syncthreads();

    const float scale = 0.17677669529663687f;  // 1/sqrt(32)
#pragma unroll
    for (int i = 0; i < 2; i++) {
        const int idx = i*512 + tid;
        const int r = idx >> 3, h = idx & 7;
        const uint4* kr4 = (const uint4*)(Kt + r*TP + h*16);
        const float* qh = fs + 1056 + h*32;
        float s = 0.f;
#pragma unroll
        for (int j4 = 0; j4 < 4; j4++) {
            uint4 u = kr4[j4];
            float2 k0 = __half22float2(*reinterpret_cast<__half2*>(&u.x));
            float2 k1 = __half22float2(*reinterpret_cast<__half2*>(&u.y));
            float2 k2 = __half22float2(*reinterpret_cast<__half2*>(&u.z));
            float2 k3 = __half22float2(*reinterpret_cast<__half2*>(&u.w));
            const float* q8 = qh + j4*8;
            s += q8[0]*k0.x + q8[1]*k0.y + q8[2]*k1.x + q8[3]*k1.y
               + q8[4]*k2.x + q8[5]*k2.y + q8[6]*k3.x + q8[7]*k3.y;
        }
        fs[h*SP + r] = s * scale;
    }
    __syncthreads();
    if (wid < 8) {
        const int h = wid;
        float m = -1e30f;
#pragma unroll
        for (int j = 0; j < 4; j++) m = fmaxf(m, fs[h*SP + lane + j*32]);
#pragma unroll
        for (int o = 16; o; o >>= 1) m = fmaxf(m, __shfl_xor_sync(0xffffffffu, m, o));
        if (lane == 0) fs[1320 + h] = m;
    }
    __syncthreads();
#pragma unroll
    for (int i = 0; i < 2; i++) {
        const int idx = i*512 + tid;
        const int r = idx >> 3, h = idx & 7;
        fs[h*SP + r] = __expf(fs[h*SP + r] - fs[1320 + h]);
    }
    __syncthreads();
    if (wid < 8) {
        const int h = wid;
        float l = 0.f;
#pragma unroll
        for (int j = 0; j < 4; j++) l += fs[h*SP + lane + j*32];
#pragma unroll
        for (int o = 16; o; o >>= 1) l += __shfl_xor_sync(0xffffffffu, l, o);
        if (lane == 0) fs[1328 + h] = l;
    }
    {
        const int h = tid >> 6, rem = tid & 63, dp = rem >> 2, part = rem & 3;
        const uint32_t* vr = Vt + h*16 + dp;
        const float* pr = fs + h*SP;
        float o0 = 0.f, o1 = 0.f;
        for (int r = part*32; r < part*32 + 32; r++) {
            uint32_t u = vr[r*TP];
            float2 vv = __half22float2(*reinterpret_cast<__half2*>(&u));
            o0 = fmaf(pr[r], vv.x, o0);
            o1 = fmaf(pr[r], vv.y, o1);
        }
        fs[1408 + ((h*16+dp)*4 + part)*2 + 0] = o0;
        fs[1408 + ((h*16+dp)*4 + part)*2 + 1] = o1;
    }
    __syncthreads();

    float* pp = p.Part + ((size_t)(tg*4 + chunk) * 8) * 36;
    if (tid < 8) {
        pp[tid*36 + 32] = fs[1320 + tid];
        pp[tid*36 + 33] = fs[1328 + tid];
    }
    if (tid < 256) {
        const int h = tid >> 5, rem = tid & 31, dp = rem >> 1, v = rem & 1;
        float s = 0.f;
#pragma unroll
        for (int part = 0; part < 4; part++)
            s += fs[1408 + ((h*16+dp)*4 + part)*2 + v];
        pp[h*36 + dp*2 + v] = s;
    }
}

// ---------------------- attention partial reduce -----------------------------
__global__ void __launch_bounds__(256) attn_reduce(const float* Part, float* ctxOut) {
    const int tg = blockIdx.x;
    const int h = threadIdx.x >> 5, d = threadIdx.x & 31;
    const float* pp = Part + ((size_t)(tg*4) * 8 + h) * 36;
    float m0 = pp[32], m1 = pp[288+32], m2 = pp[576+32], m3 = pp[864+32];
    float ms = fmaxf(fmaxf(m0, m1), fmaxf(m2, m3));
    float w0 = __expf(m0-ms), w1 = __expf(m1-ms), w2 = __expf(m2-ms), w3 = __expf(m3-ms);
    float l = w0*pp[33] + w1*pp[288+33] + w2*pp[576+33] + w3*pp[864+33];
    float o = w0*pp[d]  + w1*pp[288+d]  + w2*pp[576+d]  + w3*pp[864+d];
    ctxOut[tg*256 + h*32 + d] = o / l;
}

// ------------------- fp32 FFMA2 GEMM (prologue-sized) -----------------------
__device__ __forceinline__ unsigned long long pk2(float lo, float hi) {
    unsigned long long r;
    asm("mov.b64 %0, {%1, %2};" : "=l"(r) : "f"(lo), "f"(hi));
    return r;
}
__device__ __forceinline__ void upk2(unsigned long long v, float& lo, float& hi) {
    asm("mov.b64 {%0, %1}, %2;" : "=f"(lo), "=f"(hi) : "l"(v));
}
__device__ __forceinline__ void ffma2(unsigned long long& d,
                                      unsigned long long a, unsigned long long b) {
    asm("fma.rn.f32x2 %0, %1, %2, %0;" : "+l"(d) : "l"(a), "l"(b));
}

struct GemmP {
    const float* A; int lda; int aoff;
    const float* B; int ldb; int boff;
    int K;
    float* C; int ldc; int coff;
    const float* vec;
    __half* hC; float* O2; float* O3;
};

// 64x64 tile, TM=TN=4, 256 threads, bias epilogue
__device__ __forceinline__ void gemm64_body(const GemmP& p, int mBase, int nBase) {
    constexpr int BM = 64, BN = 64, BK = 16, TM = 4, TN = 4, NTX = 16;
    __shared__ __align__(16) float As[2][BK*BM];
    __shared__ __align__(16) float Bs[2][BK*BN];

    const int tid = threadIdx.x;
    const int tx = tid % NTX;
    const int ty = tid / NTX;
    const int lrow = tid >> 2;
    const int lk   = (tid & 3) << 2;

    const float* Abase = p.A + (size_t)(mBase + lrow) * p.lda + p.aoff + lk;
    const float* Bbase = p.B + (size_t)(nBase + lrow) * p.ldb + p.boff + lk;

    unsigned long long acc2[TM/2][TN];
#pragma unroll
    for (int i = 0; i < TM/2; i++)
#pragma unroll
        for (int j = 0; j < TN; j++) acc2[i][j] = 0ull;

    const int nTiles = p.K / BK;
    float4 ra, rbv;
    ra  = *(const float4*)(Abase);
    rbv = *(const float4*)(Bbase);
    {
        int m = lrow;
        As[0][(lk+0)*BM+m]=ra.x; As[0][(lk+1)*BM+m]=ra.y;
        As[0][(lk+2)*BM+m]=ra.z; As[0][(lk+3)*BM+m]=ra.w;
        Bs[0][(lk+0)*BN+m]=rbv.x; Bs[0][(lk+1)*BN+m]=rbv.y;
        Bs[0][(lk+2)*BN+m]=rbv.z; Bs[0][(lk+3)*BN+m]=rbv.w;
    }
    __syncthreads();

    for (int t = 0; t < nTiles; t++) {
        const int cur = t & 1;
        const bool more = (t + 1) < nTiles;
        if (more) {
            const int k0 = (t + 1) * BK;
            ra  = *(const float4*)(Abase + k0);
            rbv = *(const float4*)(Bbase + k0);
        }
#pragma unroll
        for (int k = 0; k < BK; k++) {
            unsigned long long a2[TM/2], b2[TN];
            ulonglong2 va = *(const ulonglong2*)&As[cur][k*BM + ty*TM];
            a2[0] = va.x; a2[1] = va.y;
            float4 vb = *(const float4*)&Bs[cur][k*BN + tx*TN];
            b2[0] = pk2(vb.x, vb.x); b2[1] = pk2(vb.y, vb.y);
            b2[2] = pk2(vb.z, vb.z); b2[3] = pk2(vb.w, vb.w);
#pragma unroll
            for (int i = 0; i < TM/2; i++)
#pragma unroll
                for (int j = 0; j < TN; j++) ffma2(acc2[i][j], a2[i], b2[j]);
        }
        if (more) {
            const int nxt = cur ^ 1;
            __syncthreads();
            int m = lrow;
            As[nxt][(lk+0)*BM+m]=ra.x; As[nxt][(lk+1)*BM+m]=ra.y;
            As[nxt][(lk+2)*BM+m]=ra.z; As[nxt][(lk+3)*BM+m]=ra.w;
            Bs[nxt][(lk+0)*BN+m]=rbv.x; Bs[nxt][(lk+1)*BN+m]=rbv.y;
            Bs[nxt][(lk+2)*BN+m]=rbv.z; Bs[nxt][(lk+3)*BN+m]=rbv.w;
            __syncthreads();
        }
    }

    float accf[TM][TN];
#pragma unroll
    for (int i = 0; i < TM/2; i++)
#pragma unroll
        for (int j = 0; j < TN; j++) upk2(acc2[i][j], accf[2*i][j], accf[2*i+1][j]);

#pragma unroll
    for (int i = 0; i < TM; i++) {
        const int gm  = mBase + ty*TM + i;
        const int gn0 = nBase + tx*TN;
        float* co = p.C + (size_t)gm * p.ldc + p.coff + gn0;
#pragma unroll
        for (int j = 0; j < TN; j++)
            co[j] = accf[i][j] + p.vec[gn0 + j];
    }
}

__global__ void __launch_bounds__(256, 1) gemm64_dual(GemmP pa, int nba, int gxa,
                                                      GemmP pb, int gxb) {
    const int bid = blockIdx.x;
    if (bid < nba) gemm64_body(pa, (bid / gxa) * 64, (bid % gxa) * 64);
    else {
        const int b2 = bid - nba;
        gemm64_body(pb, (b2 / gxb) * 64, (b2 % gxb) * 64);
    }
}

__global__ void __launch_bounds__(256, 1) gemm64_single(GemmP p) {
    gemm64_body(p, blockIdx.y * 64, blockIdx.x * 64);
}

// --------------------- weight-prep: 32x32 tiles, load-once smem -------------
#define WP_SMEM (2 * 512 * 33 * 4)   // 135168 B
__global__ void __launch_bounds__(256) wprep32(const float* gw, const float* WB,
                                               __half* BGh, float* Wat, float* Wac) {
    extern __shared__ float ws[];
    float* As = ws;
    float* Bs = ws + 512*33;
    const int tid = threadIdx.x;
    const int mBase = blockIdx.y * 32;
    const int nBase = blockIdx.x * 32;
#pragma unroll
    for (int i = 0; i < 16; i++) {
        int idx = i*256 + tid;
        int row = idx >> 7, c4 = (idx & 127) << 2;
        float4 v = *(const float4*)(gw + (size_t)(mBase+row)*768 + c4);
        As[(c4+0)*33 + row] = v.x; As[(c4+1)*33 + row] = v.y;
        As[(c4+2)*33 + row] = v.z; As[(c4+3)*33 + row] = v.w;
        float4 w = *(const float4*)(WB + (size_t)(nBase+row)*512 + c4);
        Bs[(c4+0)*33 + row] = w.x; Bs[(c4+1)*33 + row] = w.y;
        Bs[(c4+2)*33 + row] = w.z; Bs[(c4+3)*33 + row] = w.w;
    }
    __syncthreads();
    const int ty = tid >> 4, tx = tid & 15;
    const int r0 = ty*2, c0 = tx*2;
    float a00 = 0.f, a01 = 0.f, a10 = 0.f, a11 = 0.f;
#pragma unroll 8
    for (int k = 0; k < 512; k++) {
        float x0 = As[k*33 + r0], x1 = As[k*33 + r0 + 1];
        float y0 = Bs[k*33 + c0], y1 = Bs[k*33 + c0 + 1];
        a00 = fmaf(x0, y0, a00); a01 = fmaf(x0, y1, a01);
        a10 = fmaf(x1, y0, a10); a11 = fmaf(x1, y1, a11);
    }
    float accv[2][2] = {{a00, a01}, {a10, a11}};
#pragma unroll
    for (int i = 0; i < 2; i++)
#pragma unroll
        for (int j = 0; j < 2; j++) {
            const int gm = mBase + r0 + i, d = nBase + c0 + j;
            const float v = accv[i][j];
            if (d < 256)      BGh[(size_t)gm*512 + 256 + d] = __float2half(v);
            else if (d < 512) Wat[(size_t)gm*256 + (d-256)] = v;
            else              Wac[(size_t)gm*256 + (d-512)] = v;
        }
}

// --------------------- merged prep kernel (pack + cb + phiproj) -------------
#define PACK_BLKS 3334
__global__ void prep_kernel(const float* kt_w, const float* vt_w,
                            const float* Wq_w, const float* Wq_b,
                            const float* kc_w, const float* vc_w,
                            const float* kp2_w, const float* vp2_w,
                            const float* g_w, const float* g_b,
                            const float* kp2_b, const float* vp2_b,
                            const float* phi_t, const float* phi_c,
                            const float* kp1_w, const float* kp1_b,
                            const float* vp1_w, const float* vp1_b) {
    const int bid = blockIdx.x;
    __shared__ float ph[DPHI_];
    if (bid < PACK_BLKS) {
        int i = bid * 256 + threadIdx.x;
        if (i < 196608) {
            s_Wt[i] = (i < 65536) ? kt_w[i]
                    : (i < 131072) ? vt_w[i - 65536] : Wq_w[i - 131072];
        } else if (i < 327680) {
            int j = i - 196608;
            s_Wc[j] = (j < 65536) ? kc_w[j] : vc_w[j - 65536];
        } else if (i < 720896) {
            int j = i - 327680;
            int d = j >> 9, k = j & 511;
            float v;
            if (d < 128)       v = (k < 256) ? kp2_w[k*128 + d] : 0.f;
            else if (d < 256)  v = (k >= 256) ? vp2_w[(k-256)*128 + (d-128)] : 0.f;
            else if (d < 512)  v = (k < 256) ? kt_w[k*256 + (d-256)] : vt_w[(k-256)*256 + (d-256)];
            else               v = (k < 256) ? kc_w[k*256 + (d-512)] : vc_w[(k-256)*256 + (d-512)];
            s_WB[j] = v;
        } else if (i < 786432) {
            int j = i - 720896;
            int n = j >> 8, c = j & 255;
            s_BGh[n*512 + c] = __float2half(g_w[n*768 + 512 + c]);
        } else if (i < 819200) {
            int j = i - 786432;
            s_kp2h[j] = __float2half(kp2_w[j]);
        } else if (i < 851968) {
            int j = i - 819200;
            s_vp2h[j] = __float2half(vp2_w[j]);
        } else if (i < 852992) {
            int j = i - 851968;
            s_bt[j] = (j >= 512 && j < 768) ? Wq_b[j - 512] : 0.f;
        } else if (i < 853504) {
            int j = i - 852992;
            if (j < 256) s_kpb[j] = kp2_b[j];
            else         s_vpb[j - 256] = vp2_b[j - 256];
        }
    } else if (bid == PACK_BLKS) {
        int n = threadIdx.x;
        float s = g_b[n];
        const float* r = g_w + (size_t)n * 768;
        for (int d = 0; d < 256; d++)
            s += r[d] * kp2_b[d] + r[256 + d] * vp2_b[d];
        s_cb[n] = s;
    } else {
        const int rowId = bid - (PACK_BLKS + 1);
        const int h = threadIdx.x;
        const bool isT = rowId < NTT_;
        const float* src = isT ? (phi_t + rowId*DPHI_)
                               : (phi_c + (size_t)(rowId - NTT_)*DPHI_);
        if (h < DPHI_) ph[h] = src[h];
        __syncthreads();
        const float* W = (h < 128) ? (kp1_w + h*DPHI_) : (vp1_w + (h-128)*DPHI_);
        float s = 0.f;
#pragma unroll
        for (int j = 0; j < DPHI_; j++) s = fmaf(W[j], ph[j], s);
        if (isT) s += (h < 128) ? kp1_b[h] : vp1_b[h-128];
        __half* dst = isT ? (s_apt + (size_t)rowId*256)
                          : (s_Cph + (size_t)(rowId - NTT_)*256);
        dst[h] = __float2half(s);
    }
}

// ------------------------------- launch -------------------------------------
static inline GemmP mk() { GemmP p; p.A=0;p.lda=0;p.aoff=0;p.B=0;p.ldb=0;
    p.boff=0;p.K=0;p.C=0;p.ldc=0;p.coff=0;p.vec=0;p.hC=0;p.O2=0;p.O3=0; return p; }

extern "C" void kernel_launch(void* const* d_in, const int* in_sizes, int n_in,
                              void* d_out, int out_size) {
    const float* R_t   = (const float*)d_in[0];
    const float* R_ctx = (const float*)d_in[1];
    const float* phi_t = (const float*)d_in[2];
    const float* phi_c = (const float*)d_in[3];
    const float* Wq_w  = (const float*)d_in[5];
    const float* Wq_b  = (const float*)d_in[6];
    const float* kc_w  = (const float*)d_in[7];
    const float* kt_w  = (const float*)d_in[8];
    const float* kp1_w = (const float*)d_in[9];
    const float* kp1_b = (const float*)d_in[10];
    const float* kp2_w = (const float*)d_in[11];
    const float* kp2_b = (const float*)d_in[12];
    const float* vc_w  = (const float*)d_in[13];
    const float* vt_w  = (const float*)d_in[14];
    const float* vp1_w = (const float*)d_in[15];
    const float* vp1_b = (const float*)d_in[16];
    const float* vp2_w = (const float*)d_in[17];
    const float* vp2_b = (const float*)d_in[18];
    const float* g_w   = (const float*)d_in[19];
    const float* g_b   = (const float*)d_in[20];
    const float* out_w = (const float*)d_in[21];
    const float* out_b = (const float*)d_in[22];
    float* outp = (float*)d_out;

    __half *papt, *pCph, *pBGh, *pkp2h, *pvp2h;
    float *pTt, *pCc, *pAt, *pPart, *pWt, *pbt, *pWc, *pWB, *pcb, *pkpb, *pvpb, *pzero;
    cudaGetSymbolAddress((void**)&papt, s_apt);
    cudaGetSymbolAddress((void**)&pCph, s_Cph);
    cudaGetSymbolAddress((void**)&pBGh, s_BGh);
    cudaGetSymbolAddress((void**)&pkp2h, s_kp2h);
    cudaGetSymbolAddress((void**)&pvp2h, s_vp2h);
    cudaGetSymbolAddress((void**)&pTt, s_Tt);
    cudaGetSymbolAddress((void**)&pCc, s_Cc);
    cudaGetSymbolAddress((void**)&pAt, s_At);
    cudaGetSymbolAddress((void**)&pPart, s_Part);
    cudaGetSymbolAddress((void**)&pWt, s_Wt);
    cudaGetSymbolAddress((void**)&pbt, s_bt);
    cudaGetSymbolAddress((void**)&pWc, s_Wc);
    cudaGetSymbolAddress((void**)&pWB, s_WB);
    cudaGetSymbolAddress((void**)&pcb, s_cb);
    cudaGetSymbolAddress((void**)&pkpb, s_kpb);
    cudaGetSymbolAddress((void**)&pvpb, s_vpb);
    cudaGetSymbolAddress((void**)&pzero, s_zero);

    cudaFuncSetAttribute(fused_pair,
                         cudaFuncAttributeMaxDynamicSharedMemorySize, FUSED_SMEM);
    cudaFuncSetAttribute(wprep32,
                         cudaFuncAttributeMaxDynamicSharedMemorySize, WP_SMEM);

    prep_kernel<<<PACK_BLKS + 1 + NTT_ + NCC_, 256>>>(
        kt_w, vt_w, Wq_w, Wq_b, kc_w, vc_w, kp2_w, vp2_w,
        g_w, g_b, kp2_b, vp2_b, phi_t, phi_c, kp1_w, kp1_b, vp1_w, vp1_b);

    wprep32<<<dim3(24, 8), 256, WP_SMEM>>>(g_w, pWB, pBGh,
                                           pWt + 768*256, pWc + 512*256);

    {
        GemmP pa = mk(); pa.A=R_t; pa.lda=256; pa.B=pWt; pa.ldb=256; pa.K=256;
        pa.C=pTt; pa.ldc=1024; pa.vec=pbt;
        GemmP pb = mk(); pb.A=R_ctx; pb.lda=256; pb.B=pWc; pb.ldb=256; pb.K=256;
        pb.C=pCc; pb.ldc=768; pb.vec=pzero;
        gemm64_dual<<<64 + 192, 256>>>(pa, 64, 16, pb, 12);
    }

    // --- fused pair kernel (H build + K/V/gate + partial attention) ---
    {
        FusedP fp;
        fp.apt = papt; fp.Cph = pCph;
        fp.kp2h = pkp2h; fp.vp2h = pvp2h; fp.BGh = pBGh;
        fp.Part = pPart;
        fp.Tt = pTt; fp.Cc = pCc; fp.kpb = pkpb; fp.vpb = pvpb; fp.cb = pcb;
        fused_pair<<<NP_/128, 512, FUSED_SMEM>>>(fp);
    }

    attn_reduce<<<NTT_, 256>>>(pPart, pAt);

    {
        GemmP p = mk(); p.A=pAt; p.lda=256; p.B=out_w; p.ldb=256; p.K=256;
        p.C=outp; p.ldc=256; p.vec=out_b;
        gemm64_single<<<dim3(4,4), 256>>>(p);
    }
}